// round 6
// baseline (speedup 1.0000x reference)
#include <cuda_runtime.h>
#include <cuda_bf16.h>
#include <math.h>
#include <stdint.h>

#define N_NODES 100000
#define N_EDGES 3200000
#define N_FEAT  512
#define N_HID   256
#define N_CLASS 40
#define K_HOPS  10

#define SPMM_BLOCKS   296   // 148 SMs x 2 co-resident blocks (guaranteed by launch_bounds)
#define SPMM_THREADS  320   // 32 rows x 10 lanes

// tcgen05 only exists in the arch-accelerated target (sm_103a / sm_100a).
// The harness also runs a plain compute_103 ptxas pass, which rejects it.
#if defined(__CUDA_ARCH_FEAT_SM103_ALL) || defined(__CUDA_ARCH_FEAT_SM100_ALL)
#define USE_TCGEN05 1
#else
#define USE_TCGEN05 0
#endif

// ---------------- scratch (no cudaMalloc allowed) ----------------
__device__ float g_h1[(size_t)N_NODES * N_HID];                   // 102.4 MB
__device__ float g_xs[(size_t)(K_HOPS + 1) * N_NODES * N_CLASS];  // 176 MB
__device__ float g_w1t[(size_t)N_HID * N_FEAT];                   // W1^T, 512 KB
__device__ int   g_rowptr[N_NODES + 1];
__device__ int   g_count[N_NODES];
__device__ int   g_cursor[N_NODES];
__device__ int2  g_edge[N_EDGES];                                 // (col, w bits) interleaved
__device__ int   g_bar[K_HOPS];                                   // grid barrier counters

// ================= PTX helpers =================
__device__ __forceinline__ uint32_t smem_to_u32(const void* p) {
    uint32_t a;
    asm("{ .reg .u64 t; cvta.to.shared.u64 t, %1; cvt.u32.u64 %0, t; }"
        : "=r"(a) : "l"(p));
    return a;
}

#if USE_TCGEN05
__device__ __forceinline__ uint32_t elect_one_pred() {
    uint32_t p;
    asm volatile("{\n\t.reg .pred p;\n\telect.sync _|p, 0xFFFFFFFF;\n\t"
                 "selp.b32 %0, 1, 0, p;\n\t}" : "=r"(p));
    return p;
}

#define TCGEN05_ALLOC(smem_addr, nCols) \
    asm volatile("tcgen05.alloc.cta_group::1.sync.aligned.shared::cta.b32 [%0], %1;" \
                 :: "r"((uint32_t)(smem_addr)), "r"((uint32_t)(nCols)) : "memory")
#define TCGEN05_DEALLOC(tmem, nCols) \
    asm volatile("tcgen05.dealloc.cta_group::1.sync.aligned.b32 %0, %1;" \
                 :: "r"(tmem), "r"((uint32_t)(nCols)))
#define TCGEN05_RELINQUISH() \
    asm volatile("tcgen05.relinquish_alloc_permit.cta_group::1.sync.aligned;")
#define TCGEN05_COMMIT(mbar) \
    asm volatile("tcgen05.commit.cta_group::1.mbarrier::arrive::one.shared::cluster.b64 [%0];" \
                 :: "r"((uint32_t)(mbar)) : "memory")
#define TCGEN05_WAIT_LD() \
    asm volatile("tcgen05.wait::ld.sync.aligned;" ::: "memory")
#define TCGEN05_FENCE_AFTER() \
    asm volatile("tcgen05.fence::after_thread_sync;" ::: "memory")
#define TCGEN05_FENCE_BEFORE() \
    asm volatile("tcgen05.fence::before_thread_sync;" ::: "memory")
#define MBARRIER_INIT(mbar, cnt) \
    asm volatile("mbarrier.init.shared.b64 [%0], %1;" \
                 :: "r"((uint32_t)(mbar)), "r"((uint32_t)(cnt)) : "memory")
#define MBARRIER_INVAL(mbar) \
    asm volatile("mbarrier.inval.shared.b64 [%0];" :: "r"((uint32_t)(mbar)) : "memory")
#define FENCE_PROXY_ASYNC() \
    asm volatile("fence.proxy.async.shared::cta;" ::: "memory")

#define MBARRIER_WAIT_PARITY(mbar, parity) do { \
    uint32_t _m = (uint32_t)(mbar); \
    uint32_t _p = (uint32_t)(parity); \
    uint32_t _done; \
    asm volatile("{\n\t.reg .pred p;\n\t" \
        "mbarrier.try_wait.parity.acquire.cta.shared::cta.b64 p, [%1], %2;\n\t" \
        "selp.b32 %0, 1, 0, p;\n\t}" : "=r"(_done) : "r"(_m), "r"(_p) : "memory"); \
    if (!_done) { \
        asm volatile("{\n\t.reg .pred P1;\n\t" \
            "WL_%=:\n\t" \
            "mbarrier.try_wait.parity.acquire.cta.shared::cta.b64 P1, [%0], %1, 0x989680;\n\t" \
            "@P1 bra.uni WD_%=;\n\t" \
            "bra.uni WL_%=;\n\t" \
            "WD_%=:\n\t}" :: "r"(_m), "r"(_p) : "memory"); \
    } \
} while (0)

#define TCGEN05_LD_32X32B_X32(r, tmem_addr) \
    asm volatile( \
        "tcgen05.ld.sync.aligned.32x32b.x32.b32 " \
        "{%0, %1, %2, %3, %4, %5, %6, %7, " \
        " %8, %9, %10, %11, %12, %13, %14, %15, " \
        " %16, %17, %18, %19, %20, %21, %22, %23, " \
        " %24, %25, %26, %27, %28, %29, %30, %31}, [%32];" \
        : "=r"((r)[0]),  "=r"((r)[1]),  "=r"((r)[2]),  "=r"((r)[3]), \
          "=r"((r)[4]),  "=r"((r)[5]),  "=r"((r)[6]),  "=r"((r)[7]), \
          "=r"((r)[8]),  "=r"((r)[9]),  "=r"((r)[10]), "=r"((r)[11]), \
          "=r"((r)[12]), "=r"((r)[13]), "=r"((r)[14]), "=r"((r)[15]), \
          "=r"((r)[16]), "=r"((r)[17]), "=r"((r)[18]), "=r"((r)[19]), \
          "=r"((r)[20]), "=r"((r)[21]), "=r"((r)[22]), "=r"((r)[23]), \
          "=r"((r)[24]), "=r"((r)[25]), "=r"((r)[26]), "=r"((r)[27]), \
          "=r"((r)[28]), "=r"((r)[29]), "=r"((r)[30]), "=r"((r)[31]) \
        : "r"(tmem_addr))

// SW128 K-major descriptor: layout=2 (SW128), version=1, SBO=64, LBO=1
static constexpr uint64_t SMEM_DESC_BASE_SW128 =
    (uint64_t(2) << 61) | (uint64_t(1) << 46) | (uint64_t(64) << 32) | (uint64_t(1) << 16);
#define MAKE_SMEM_DESC(base_addr) \
    (SMEM_DESC_BASE_SW128 | ((uint64_t)((base_addr) >> 4) & 0x3FFF))

// tf32 SS MMA idesc: c=F32 (1<<4), a=TF32 (2<<7), b=TF32 (2<<10),
// N/8 at bits[17:23), M/16 at bits[24:29)
static constexpr uint32_t IDESC_TF32 =
    (1u << 4) | (2u << 7) | (2u << 10) | ((256u / 8u) << 17) | ((128u / 16u) << 24);

__device__ __forceinline__ void mma_tf32_ss(uint32_t d, uint64_t ad, uint64_t bd,
                                            uint32_t idesc, bool acc) {
    uint32_t en = acc ? 1u : 0u;
    asm volatile(
        "{\n\t.reg .pred p;\n\tsetp.ne.u32 p, %5, 0;\n\t"
        "tcgen05.mma.cta_group::1.kind::tf32 [%0], %1, %2, %3, {%4, %4, %4, %4}, p;\n\t}"
        :: "r"(d), "l"(ad), "l"(bd), "r"(idesc), "r"(0u), "r"(en)
        : "memory");
}

__device__ __forceinline__ float to_tf32(float x) {
    uint32_t r;
    asm("cvt.rna.tf32.f32 %0, %1;" : "=r"(r) : "f"(x));
    return __uint_as_float(r);
}
#endif  // USE_TCGEN05

#define SMEM_SWIZZLE_128B(off) ((off) ^ (((off) >> 3) & 0x70))

// ---------------- W1 transpose: g_w1t[n][k] = W1[k][n] ----------------
__global__ void transpose_w1_kernel(const float* __restrict__ W1) {
    __shared__ float t[32][33];
    int bk = blockIdx.x * 32;
    int bn = blockIdx.y * 32;
    int x = threadIdx.x, y = threadIdx.y;
#pragma unroll
    for (int i = 0; i < 32; i += 8)
        t[y + i][x] = W1[(size_t)(bk + y + i) * N_HID + bn + x];
    __syncthreads();
#pragma unroll
    for (int i = 0; i < 32; i += 8)
        g_w1t[(size_t)(bn + y + i) * N_FEAT + bk + x] = t[x][y + i];
}

// ---------------- GEMM1: relu(feature @ W1 + b1) -> g_h1 ----------------
#define G1_CHUNK_K   32
#define G1_NCHUNKS   (N_FEAT / G1_CHUNK_K)      // 16
#define G1_A_BYTES   (128 * 128)
#define G1_B_BYTES   (256 * 128)
#define G1_OFF_A0    1024
#define G1_OFF_A1    (G1_OFF_A0 + G1_A_BYTES)
#define G1_OFF_B0    (G1_OFF_A1 + G1_A_BYTES)
#define G1_OFF_B1    (G1_OFF_B0 + G1_B_BYTES)
#define G1_SMEM_TOTAL (G1_OFF_B1 + G1_B_BYTES)   // 99328

__global__ void __launch_bounds__(256) gemm1_tc_kernel(const float* __restrict__ A,
                                                       const float* __restrict__ bias) {
    extern __shared__ char smem[];
#if USE_TCGEN05
    const uint32_t sb = smem_to_u32(smem);
    const int tid  = threadIdx.x;
    const int wid  = tid >> 5;
    const int lane = tid & 31;
    const int bm   = blockIdx.x * 128;

    if (wid == 4) TCGEN05_ALLOC(sb + 0, 256);
    if (tid == 0) { MBARRIER_INIT(sb + 8, 1); MBARRIER_INIT(sb + 16, 1); }
    __syncthreads();
    uint32_t tmem;
    asm volatile("ld.shared.b32 %0, [%1];" : "=r"(tmem) : "r"(sb + 0));

    const uint32_t aoff[2] = {G1_OFF_A0, G1_OFF_A1};
    const uint32_t boff[2] = {G1_OFF_B0, G1_OFF_B1};

    for (int c = 0; c < G1_NCHUNKS; c++) {
        const int buf = c & 1;
        if (c >= 2) MBARRIER_WAIT_PARITY(sb + 8 + 8 * buf, ((c - 2) >> 1) & 1);

        // A chunk: 128 rows x 8 float4 (k = c*32 .. c*32+31), SW128-swizzled
#pragma unroll
        for (int r = 0; r < 4; r++) {
            int i   = tid + r * 256;
            int row = i >> 3;
            int f4  = i & 7;
            int gm  = bm + row;
            float4 v = make_float4(0.f, 0.f, 0.f, 0.f);
            if (gm < N_NODES)
                v = *(const float4*)(A + (size_t)gm * N_FEAT + c * G1_CHUNK_K + f4 * 4);
            v.x = to_tf32(v.x); v.y = to_tf32(v.y); v.z = to_tf32(v.z); v.w = to_tf32(v.w);
            uint32_t off = SMEM_SWIZZLE_128B((uint32_t)(row * 128 + f4 * 16));
            *(float4*)(smem + aoff[buf] + off) = v;
        }
        // B chunk: 256 n-rows x 8 float4 from W1^T
#pragma unroll
        for (int r = 0; r < 8; r++) {
            int i  = tid + r * 256;
            int n  = i >> 3;
            int f4 = i & 7;
            float4 v = *(const float4*)(g_w1t + (size_t)n * N_FEAT + c * G1_CHUNK_K + f4 * 4);
            v.x = to_tf32(v.x); v.y = to_tf32(v.y); v.z = to_tf32(v.z); v.w = to_tf32(v.w);
            uint32_t off = SMEM_SWIZZLE_128B((uint32_t)(n * 128 + f4 * 16));
            *(float4*)(smem + boff[buf] + off) = v;
        }
        FENCE_PROXY_ASYNC();
        __syncthreads();

        if (wid == 4) {
            if (elect_one_pred()) {
                uint64_t ad = MAKE_SMEM_DESC(sb + aoff[buf]);
                uint64_t bd = MAKE_SMEM_DESC(sb + boff[buf]);
#pragma unroll
                for (int ks = 0; ks < 4; ks++)
                    mma_tf32_ss(tmem, ad + ks * 2, bd + ks * 2, IDESC_TF32,
                                (c > 0) || (ks > 0));
                TCGEN05_COMMIT(sb + 8 + 8 * buf);
            }
        }
    }

    MBARRIER_WAIT_PARITY(sb + 8, 1);
    MBARRIER_WAIT_PARITY(sb + 16, 1);
    TCGEN05_FENCE_AFTER();

    // Epilogue: warps 0-3 read D (128 lanes x 256 cols fp32), bias+relu, store.
    if (wid < 4) {
        const int m = bm + wid * 32 + lane;
#pragma unroll
        for (int b = 0; b < 4; b++) {
            uint32_t r[64];
            TCGEN05_LD_32X32B_X32(r, tmem + b * 64);
            TCGEN05_LD_32X32B_X32(r + 32, tmem + b * 64 + 32);
            TCGEN05_WAIT_LD();
            if (m < N_NODES) {
                float* outp = g_h1 + (size_t)m * N_HID + b * 64;
#pragma unroll
                for (int j = 0; j < 64; j += 4) {
                    float4 o;
                    o.x = fmaxf(__uint_as_float(r[j + 0]) + bias[b * 64 + j + 0], 0.f);
                    o.y = fmaxf(__uint_as_float(r[j + 1]) + bias[b * 64 + j + 1], 0.f);
                    o.z = fmaxf(__uint_as_float(r[j + 2]) + bias[b * 64 + j + 2], 0.f);
                    o.w = fmaxf(__uint_as_float(r[j + 3]) + bias[b * 64 + j + 3], 0.f);
                    *(float4*)(outp + j) = o;
                }
            }
        }
        TCGEN05_FENCE_BEFORE();
    }
    __syncthreads();
    if (tid == 0) { MBARRIER_INVAL(sb + 8); MBARRIER_INVAL(sb + 16); }
    __syncthreads();
    if (wid == 4) { TCGEN05_RELINQUISH(); TCGEN05_DEALLOC(tmem, 256); }

#else  // ---------- SIMT fallback (plain sm_103 JIT path) ----------
    float (*As)[132] = (float(*)[132])smem;
    float (*Bs)[68]  = (float(*)[68])(smem + 16 * 132 * sizeof(float));

    const int tid  = threadIdx.x;
    const int bm   = blockIdx.x * 128;
    const int mIdx = tid >> 4;
    const int nIdx = tid & 15;

    for (int nb = 0; nb < 4; nb++) {
        const int bn = nb * 64;
        float acc[8][4];
#pragma unroll
        for (int i = 0; i < 8; i++)
#pragma unroll
            for (int j = 0; j < 4; j++) acc[i][j] = 0.f;

        for (int kt = 0; kt < N_FEAT; kt += 16) {
#pragma unroll
            for (int r = 0; r < 2; r++) {
                int i  = tid + r * 256;
                int m  = i >> 2;
                int k4 = (i & 3) * 4;
                int gm = bm + m;
                float4 v = make_float4(0.f, 0.f, 0.f, 0.f);
                if (gm < N_NODES)
                    v = *(const float4*)(A + (size_t)gm * N_FEAT + kt + k4);
                As[k4 + 0][m] = v.x;
                As[k4 + 1][m] = v.y;
                As[k4 + 2][m] = v.z;
                As[k4 + 3][m] = v.w;
            }
            {
                int n  = tid >> 2;
                int k4 = (tid & 3) * 4;
                float4 v = *(const float4*)(g_w1t + (size_t)(bn + n) * N_FEAT + kt + k4);
                Bs[k4 + 0][n] = v.x;
                Bs[k4 + 1][n] = v.y;
                Bs[k4 + 2][n] = v.z;
                Bs[k4 + 3][n] = v.w;
            }
            __syncthreads();

#pragma unroll
            for (int k = 0; k < 16; k++) {
                float ra[8], rb[4];
#pragma unroll
                for (int i = 0; i < 8; i++) ra[i] = As[k][mIdx * 8 + i];
#pragma unroll
                for (int j = 0; j < 4; j++) rb[j] = Bs[k][nIdx * 4 + j];
#pragma unroll
                for (int i = 0; i < 8; i++)
#pragma unroll
                    for (int j = 0; j < 4; j++) acc[i][j] += ra[i] * rb[j];
            }
            __syncthreads();
        }

#pragma unroll
        for (int i = 0; i < 8; i++) {
            int gm = bm + mIdx * 8 + i;
            if (gm < N_NODES) {
#pragma unroll
                for (int j = 0; j < 4; j++) {
                    int gn = bn + nIdx * 4 + j;
                    float v = acc[i][j] + bias[gn];
                    g_h1[(size_t)gm * N_HID + gn] = fmaxf(v, 0.f);
                }
            }
        }
    }
#endif
}

// ---------------- GEMM2: g_h1 @ W2 + b2 -> g_xs plane 0 ----------------
__global__ void gemm2_kernel(const float* __restrict__ W2,
                             const float* __restrict__ b2) {
    __shared__ float As[64][65];
    __shared__ float W2s[64 * N_CLASS];

    const int tid = threadIdx.x;
    const int bm  = blockIdx.x * 64;
    const int row = tid >> 2;
    const int q   = tid & 3;

    float acc[10];
#pragma unroll
    for (int j = 0; j < 10; j++) acc[j] = 0.f;

    for (int kb = 0; kb < N_HID; kb += 64) {
#pragma unroll
        for (int r = 0; r < 4; r++) {
            int i  = tid + r * 256;
            int rr = i >> 4;
            int c4 = (i & 15) * 4;
            int gm = bm + rr;
            float4 v = make_float4(0.f, 0.f, 0.f, 0.f);
            if (gm < N_NODES)
                v = *(const float4*)(g_h1 + (size_t)gm * N_HID + kb + c4);
            As[rr][c4 + 0] = v.x;
            As[rr][c4 + 1] = v.y;
            As[rr][c4 + 2] = v.z;
            As[rr][c4 + 3] = v.w;
        }
#pragma unroll
        for (int r = 0; r < 10; r++) {
            int e = tid + r * 256;
            W2s[e] = W2[(size_t)kb * N_CLASS + e];
        }
        __syncthreads();

#pragma unroll 4
        for (int k = 0; k < 64; k++) {
            float a = As[row][k];
#pragma unroll
            for (int j = 0; j < 10; j++)
                acc[j] += a * W2s[k * N_CLASS + q * 10 + j];
        }
        __syncthreads();
    }

    int gm = bm + row;
    if (gm < N_NODES) {
#pragma unroll
        for (int j = 0; j < 10; j++)
            g_xs[(size_t)gm * N_CLASS + q * 10 + j] = acc[j] + b2[q * 10 + j];
    }
}

// ---------------- CSR build ----------------
__global__ void zero_count_kernel() {
    int i = blockIdx.x * blockDim.x + threadIdx.x;
    if (i < N_NODES) g_count[i] = 0;
    if (i < K_HOPS) g_bar[i] = 0;   // reset persistent-kernel barriers each launch
}

__global__ void hist_kernel(const int* __restrict__ edge_row) {
    int e = blockIdx.x * blockDim.x + threadIdx.x;
    if (e < N_EDGES) atomicAdd(&g_count[edge_row[e]], 1);
}

__global__ void scan_kernel() {
    __shared__ int warp_sums[32];
    __shared__ int carry_s;
    const int tid = threadIdx.x, lane = tid & 31, wid = tid >> 5;
    if (tid == 0) { carry_s = 0; g_rowptr[0] = 0; }
    __syncthreads();

    for (int base = 0; base < N_NODES; base += 1024) {
        int i = base + tid;
        int v = (i < N_NODES) ? g_count[i] : 0;
        int x = v;
#pragma unroll
        for (int off = 1; off < 32; off <<= 1) {
            int y = __shfl_up_sync(0xffffffffu, x, off);
            if (lane >= off) x += y;
        }
        if (lane == 31) warp_sums[wid] = x;
        __syncthreads();
        if (wid == 0) {
            int s = warp_sums[lane];
#pragma unroll
            for (int off = 1; off < 32; off <<= 1) {
                int y = __shfl_up_sync(0xffffffffu, s, off);
                if (lane >= off) s += y;
            }
            warp_sums[lane] = s;
        }
        __syncthreads();
        int incl = x + ((wid > 0) ? warp_sums[wid - 1] : 0) + carry_s;
        if (i < N_NODES) {
            g_rowptr[i + 1] = incl;
            g_cursor[i]     = incl - v;
        }
        __syncthreads();
        if (tid == 1023) carry_s = incl;
        __syncthreads();
    }
}

__global__ void scatter_kernel(const int* __restrict__ edge_row,
                               const int* __restrict__ edge_col,
                               const float* __restrict__ edge_w) {
    int e = blockIdx.x * blockDim.x + threadIdx.x;
    if (e < N_EDGES) {
        int r = edge_row[e];
        int p = atomicAdd(&g_cursor[r], 1);
        g_edge[p] = make_int2(edge_col[e], __float_as_int(edge_w[e]));
    }
}

// ---------------- persistent SpMM: all K_HOPS hops in one kernel ----------------
// Static row partition per block; 10 lanes per row; grid barrier between hops.
// 2 blocks/SM guaranteed co-resident (launch_bounds), so the spin barrier is safe.
__device__ __forceinline__ void spmm_row(const float* __restrict__ xin,
                                         float* __restrict__ xout,
                                         int row, int lane) {
    const int s = g_rowptr[row];
    const int e = g_rowptr[row + 1];
    float4 acc = make_float4(0.f, 0.f, 0.f, 0.f);

    int i = s;
    for (; i + 4 <= e; i += 4) {
        int2 e0 = g_edge[i + 0];
        int2 e1 = g_edge[i + 1];
        int2 e2 = g_edge[i + 2];
        int2 e3 = g_edge[i + 3];
        float4 v0 = *(const float4*)(xin + (size_t)e0.x * N_CLASS + lane * 4);
        float4 v1 = *(const float4*)(xin + (size_t)e1.x * N_CLASS + lane * 4);
        float4 v2 = *(const float4*)(xin + (size_t)e2.x * N_CLASS + lane * 4);
        float4 v3 = *(const float4*)(xin + (size_t)e3.x * N_CLASS + lane * 4);
        float w0 = __int_as_float(e0.y);
        float w1 = __int_as_float(e1.y);
        float w2 = __int_as_float(e2.y);
        float w3 = __int_as_float(e3.y);
        acc.x += w0 * v0.x; acc.y += w0 * v0.y; acc.z += w0 * v0.z; acc.w += w0 * v0.w;
        acc.x += w1 * v1.x; acc.y += w1 * v1.y; acc.z += w1 * v1.z; acc.w += w1 * v1.w;
        acc.x += w2 * v2.x; acc.y += w2 * v2.y; acc.z += w2 * v2.z; acc.w += w2 * v2.w;
        acc.x += w3 * v3.x; acc.y += w3 * v3.y; acc.z += w3 * v3.z; acc.w += w3 * v3.w;
    }
    for (; i < e; i++) {
        int2  ed = g_edge[i];
        float w  = __int_as_float(ed.y);
        float4 v = *(const float4*)(xin + (size_t)ed.x * N_CLASS + lane * 4);
        acc.x += w * v.x; acc.y += w * v.y; acc.z += w * v.z; acc.w += w * v.w;
    }
    *(float4*)(xout + (size_t)row * N_CLASS + lane * 4) = acc;
}

__global__ void __launch_bounds__(SPMM_THREADS, 2) spmm_persistent_kernel() {
    const int tid  = threadIdx.x;
    const int lane = tid % 10;
    const int rloc = tid / 10;           // 0..31
    const int nb   = gridDim.x;

    const int row0 = (int)(((long long)blockIdx.x * N_NODES) / nb);
    const int row1 = (int)(((long long)(blockIdx.x + 1) * N_NODES) / nb);

    for (int hop = 1; hop <= K_HOPS; hop++) {
        const float* xin  = g_xs + (size_t)(hop - 1) * N_NODES * N_CLASS;
        float*       xout = g_xs + (size_t)hop * N_NODES * N_CLASS;

        for (int row = row0 + rloc; row < row1; row += 32)
            spmm_row(xin, xout, row, lane);

        if (hop < K_HOPS) {
            // grid barrier: all blocks' hop writes visible before next hop reads
            __threadfence();
            __syncthreads();
            if (tid == 0) {
                atomicAdd(&g_bar[hop - 1], 1);
                while (atomicAdd(&g_bar[hop - 1], 0) < nb)
                    __nanosleep(64);
            }
            __syncthreads();
            __threadfence();
        }
    }
}

// ---------------- attention + log_softmax ----------------
__global__ void attn_kernel(const float* __restrict__ Wa,
                            const float* __restrict__ ba,
                            float* __restrict__ out) {
    int gwarp = (blockIdx.x * blockDim.x + threadIdx.x) >> 5;
    int lane  = threadIdx.x & 31;
    if (gwarp >= N_NODES) return;
    const int n = gwarp;

    const float wa0 = Wa[lane];
    const float wa1 = (lane < 8) ? Wa[lane + 32] : 0.f;
    const float bav = ba[0];

    float acc0 = 0.f, acc1 = 0.f;
#pragma unroll
    for (int k = 0; k <= K_HOPS; k++) {
        const float* p = g_xs + ((size_t)k * N_NODES + n) * N_CLASS;
        float v0 = p[lane];
        float v1 = (lane < 8) ? p[lane + 32] : 0.f;
        float dot = v0 * wa0 + v1 * wa1;
#pragma unroll
        for (int off = 16; off > 0; off >>= 1)
            dot += __shfl_xor_sync(0xffffffffu, dot, off);
        float s = 1.f / (1.f + expf(-(dot + bav)));
        acc0 += s * v0;
        acc1 += s * v1;
    }

    float m = acc0;
    if (lane < 8) m = fmaxf(m, acc1);
#pragma unroll
    for (int off = 16; off > 0; off >>= 1)
        m = fmaxf(m, __shfl_xor_sync(0xffffffffu, m, off));

    float se = expf(acc0 - m) + ((lane < 8) ? expf(acc1 - m) : 0.f);
#pragma unroll
    for (int off = 16; off > 0; off >>= 1)
        se += __shfl_xor_sync(0xffffffffu, se, off);

    float lse = logf(se);
    out[(size_t)n * N_CLASS + lane] = acc0 - m - lse;
    if (lane < 8)
        out[(size_t)n * N_CLASS + lane + 32] = acc1 - m - lse;
}

// ---------------- launch (fork-join: CSR chain || dense chain) ----------------
static cudaStream_t g_side    = nullptr;
static cudaEvent_t  g_ev_fork = nullptr;
static cudaEvent_t  g_ev_join = nullptr;
static int          g_inited  = 0;

extern "C" void kernel_launch(void* const* d_in, const int* in_sizes, int n_in,
                              void* d_out, int out_size) {
    const float* feature  = (const float*)d_in[0];
    const int*   edge_row = (const int*)  d_in[1];
    const int*   edge_col = (const int*)  d_in[2];
    const float* edge_w   = (const float*)d_in[3];
    const float* W1       = (const float*)d_in[4];
    const float* b1       = (const float*)d_in[5];
    const float* W2       = (const float*)d_in[6];
    const float* b2       = (const float*)d_in[7];
    const float* Wa       = (const float*)d_in[8];
    const float* ba       = (const float*)d_in[9];
    float*       out      = (float*)d_out;

    if (!g_inited) {
        cudaStreamCreateWithFlags(&g_side, cudaStreamNonBlocking);
        cudaEventCreateWithFlags(&g_ev_fork, cudaEventDisableTiming);
        cudaEventCreateWithFlags(&g_ev_join, cudaEventDisableTiming);
        cudaFuncSetAttribute(gemm1_tc_kernel,
                             cudaFuncAttributeMaxDynamicSharedMemorySize, G1_SMEM_TOTAL);
        g_inited = 1;
    }

    const bool fork = (g_side != nullptr) && (g_ev_fork != nullptr) && (g_ev_join != nullptr);
    cudaStream_t cs = fork ? g_side : (cudaStream_t)0;

    if (fork) {
        cudaEventRecord(g_ev_fork, 0);
        cudaStreamWaitEvent(g_side, g_ev_fork, 0);
    }

    // ---- CSR chain (independent of dense path); also resets hop barriers ----
    zero_count_kernel<<<(N_NODES + 255) / 256, 256, 0, cs>>>();
    hist_kernel<<<(N_EDGES + 255) / 256, 256, 0, cs>>>(edge_row);
    scan_kernel<<<1, 1024, 0, cs>>>();
    scatter_kernel<<<(N_EDGES + 255) / 256, 256, 0, cs>>>(edge_row, edge_col, edge_w);

    if (fork) cudaEventRecord(g_ev_join, g_side);

    // ---- dense chain (legacy stream) ----
    transpose_w1_kernel<<<dim3(N_FEAT / 32, N_HID / 32), dim3(32, 8)>>>(W1);
    gemm1_tc_kernel<<<(N_NODES + 127) / 128, 256, G1_SMEM_TOTAL>>>(feature, b1);
    gemm2_kernel<<<(N_NODES + 63) / 64, 256>>>(W2, b2);

    // ---- join: SpMM needs both CSR and xs plane 0 ----
    if (fork) cudaStreamWaitEvent((cudaStream_t)0, g_ev_join, 0);

    spmm_persistent_kernel<<<SPMM_BLOCKS, SPMM_THREADS>>>();

    attn_kernel<<<(N_NODES * 32 + 255) / 256, 256>>>(Wa, ba, out);
}

// round 7
// speedup vs baseline: 1.0447x; 1.0447x over previous
#include <cuda_runtime.h>
#include <cuda_bf16.h>
#include <math.h>
#include <stdint.h>

#define N_NODES 100000
#define N_EDGES 3200000
#define N_FEAT  512
#define N_HID   256
#define N_CLASS 40
#define K_HOPS  10

// tcgen05 only exists in the arch-accelerated target (sm_103a / sm_100a).
// The harness also runs a plain compute_103 ptxas pass, which rejects it.
#if defined(__CUDA_ARCH_FEAT_SM103_ALL) || defined(__CUDA_ARCH_FEAT_SM100_ALL)
#define USE_TCGEN05 1
#else
#define USE_TCGEN05 0
#endif

// ---------------- scratch (no cudaMalloc allowed) ----------------
__device__ float g_h1[(size_t)N_NODES * N_HID];                   // 102.4 MB
__device__ float g_xs[(size_t)(K_HOPS + 1) * N_NODES * N_CLASS];  // 176 MB
__device__ float g_w1t[(size_t)N_HID * N_FEAT];                   // W1^T, 512 KB
__device__ int   g_rowptr[N_NODES + 1];
__device__ int   g_count[N_NODES];
__device__ int   g_cursor[N_NODES];
__device__ int2  g_edge[N_EDGES];                                 // (col, w bits) interleaved
__device__ int   g_rowperm[N_NODES];                              // rows sorted by degree
__device__ int   g_degcount[256];
__device__ int   g_degoff[256];

// ================= PTX helpers =================
__device__ __forceinline__ uint32_t smem_to_u32(const void* p) {
    uint32_t a;
    asm("{ .reg .u64 t; cvta.to.shared.u64 t, %1; cvt.u32.u64 %0, t; }"
        : "=r"(a) : "l"(p));
    return a;
}

#if USE_TCGEN05
__device__ __forceinline__ uint32_t elect_one_pred() {
    uint32_t p;
    asm volatile("{\n\t.reg .pred p;\n\telect.sync _|p, 0xFFFFFFFF;\n\t"
                 "selp.b32 %0, 1, 0, p;\n\t}" : "=r"(p));
    return p;
}

#define TCGEN05_ALLOC(smem_addr, nCols) \
    asm volatile("tcgen05.alloc.cta_group::1.sync.aligned.shared::cta.b32 [%0], %1;" \
                 :: "r"((uint32_t)(smem_addr)), "r"((uint32_t)(nCols)) : "memory")
#define TCGEN05_DEALLOC(tmem, nCols) \
    asm volatile("tcgen05.dealloc.cta_group::1.sync.aligned.b32 %0, %1;" \
                 :: "r"(tmem), "r"((uint32_t)(nCols)))
#define TCGEN05_RELINQUISH() \
    asm volatile("tcgen05.relinquish_alloc_permit.cta_group::1.sync.aligned;")
#define TCGEN05_COMMIT(mbar) \
    asm volatile("tcgen05.commit.cta_group::1.mbarrier::arrive::one.shared::cluster.b64 [%0];" \
                 :: "r"((uint32_t)(mbar)) : "memory")
#define TCGEN05_WAIT_LD() \
    asm volatile("tcgen05.wait::ld.sync.aligned;" ::: "memory")
#define TCGEN05_FENCE_AFTER() \
    asm volatile("tcgen05.fence::after_thread_sync;" ::: "memory")
#define TCGEN05_FENCE_BEFORE() \
    asm volatile("tcgen05.fence::before_thread_sync;" ::: "memory")
#define MBARRIER_INIT(mbar, cnt) \
    asm volatile("mbarrier.init.shared.b64 [%0], %1;" \
                 :: "r"((uint32_t)(mbar)), "r"((uint32_t)(cnt)) : "memory")
#define MBARRIER_INVAL(mbar) \
    asm volatile("mbarrier.inval.shared.b64 [%0];" :: "r"((uint32_t)(mbar)) : "memory")
#define FENCE_PROXY_ASYNC() \
    asm volatile("fence.proxy.async.shared::cta;" ::: "memory")

#define MBARRIER_WAIT_PARITY(mbar, parity) do { \
    uint32_t _m = (uint32_t)(mbar); \
    uint32_t _p = (uint32_t)(parity); \
    uint32_t _done; \
    asm volatile("{\n\t.reg .pred p;\n\t" \
        "mbarrier.try_wait.parity.acquire.cta.shared::cta.b64 p, [%1], %2;\n\t" \
        "selp.b32 %0, 1, 0, p;\n\t}" : "=r"(_done) : "r"(_m), "r"(_p) : "memory"); \
    if (!_done) { \
        asm volatile("{\n\t.reg .pred P1;\n\t" \
            "WL_%=:\n\t" \
            "mbarrier.try_wait.parity.acquire.cta.shared::cta.b64 P1, [%0], %1, 0x989680;\n\t" \
            "@P1 bra.uni WD_%=;\n\t" \
            "bra.uni WL_%=;\n\t" \
            "WD_%=:\n\t}" :: "r"(_m), "r"(_p) : "memory"); \
    } \
} while (0)

#define TCGEN05_LD_32X32B_X32(r, tmem_addr) \
    asm volatile( \
        "tcgen05.ld.sync.aligned.32x32b.x32.b32 " \
        "{%0, %1, %2, %3, %4, %5, %6, %7, " \
        " %8, %9, %10, %11, %12, %13, %14, %15, " \
        " %16, %17, %18, %19, %20, %21, %22, %23, " \
        " %24, %25, %26, %27, %28, %29, %30, %31}, [%32];" \
        : "=r"((r)[0]),  "=r"((r)[1]),  "=r"((r)[2]),  "=r"((r)[3]), \
          "=r"((r)[4]),  "=r"((r)[5]),  "=r"((r)[6]),  "=r"((r)[7]), \
          "=r"((r)[8]),  "=r"((r)[9]),  "=r"((r)[10]), "=r"((r)[11]), \
          "=r"((r)[12]), "=r"((r)[13]), "=r"((r)[14]), "=r"((r)[15]), \
          "=r"((r)[16]), "=r"((r)[17]), "=r"((r)[18]), "=r"((r)[19]), \
          "=r"((r)[20]), "=r"((r)[21]), "=r"((r)[22]), "=r"((r)[23]), \
          "=r"((r)[24]), "=r"((r)[25]), "=r"((r)[26]), "=r"((r)[27]), \
          "=r"((r)[28]), "=r"((r)[29]), "=r"((r)[30]), "=r"((r)[31]) \
        : "r"(tmem_addr))

// SW128 K-major descriptor: layout=2 (SW128), version=1, SBO=64, LBO=1
static constexpr uint64_t SMEM_DESC_BASE_SW128 =
    (uint64_t(2) << 61) | (uint64_t(1) << 46) | (uint64_t(64) << 32) | (uint64_t(1) << 16);
#define MAKE_SMEM_DESC(base_addr) \
    (SMEM_DESC_BASE_SW128 | ((uint64_t)((base_addr) >> 4) & 0x3FFF))

// tf32 SS MMA idesc: c=F32 (1<<4), a=TF32 (2<<7), b=TF32 (2<<10),
// N/8 at bits[17:23), M/16 at bits[24:29)
static constexpr uint32_t IDESC_TF32 =
    (1u << 4) | (2u << 7) | (2u << 10) | ((256u / 8u) << 17) | ((128u / 16u) << 24);

__device__ __forceinline__ void mma_tf32_ss(uint32_t d, uint64_t ad, uint64_t bd,
                                            uint32_t idesc, bool acc) {
    uint32_t en = acc ? 1u : 0u;
    asm volatile(
        "{\n\t.reg .pred p;\n\tsetp.ne.u32 p, %5, 0;\n\t"
        "tcgen05.mma.cta_group::1.kind::tf32 [%0], %1, %2, %3, {%4, %4, %4, %4}, p;\n\t}"
        :: "r"(d), "l"(ad), "l"(bd), "r"(idesc), "r"(0u), "r"(en)
        : "memory");
}

__device__ __forceinline__ float to_tf32(float x) {
    uint32_t r;
    asm("cvt.rna.tf32.f32 %0, %1;" : "=r"(r) : "f"(x));
    return __uint_as_float(r);
}
#endif  // USE_TCGEN05

#define SMEM_SWIZZLE_128B(off) ((off) ^ (((off) >> 3) & 0x70))

// ---------------- W1 transpose: g_w1t[n][k] = W1[k][n] ----------------
__global__ void transpose_w1_kernel(const float* __restrict__ W1) {
    __shared__ float t[32][33];
    int bk = blockIdx.x * 32;
    int bn = blockIdx.y * 32;
    int x = threadIdx.x, y = threadIdx.y;
#pragma unroll
    for (int i = 0; i < 32; i += 8)
        t[y + i][x] = W1[(size_t)(bk + y + i) * N_HID + bn + x];
    __syncthreads();
#pragma unroll
    for (int i = 0; i < 32; i += 8)
        g_w1t[(size_t)(bn + y + i) * N_FEAT + bk + x] = t[x][y + i];
}

// ---------------- GEMM1: relu(feature @ W1 + b1) -> g_h1 ----------------
#define G1_CHUNK_K   32
#define G1_NCHUNKS   (N_FEAT / G1_CHUNK_K)      // 16
#define G1_A_BYTES   (128 * 128)
#define G1_B_BYTES   (256 * 128)
#define G1_OFF_A0    1024
#define G1_OFF_A1    (G1_OFF_A0 + G1_A_BYTES)
#define G1_OFF_B0    (G1_OFF_A1 + G1_A_BYTES)
#define G1_OFF_B1    (G1_OFF_B0 + G1_B_BYTES)
#define G1_SMEM_TOTAL (G1_OFF_B1 + G1_B_BYTES)   // 99328

__global__ void __launch_bounds__(256) gemm1_tc_kernel(const float* __restrict__ A,
                                                       const float* __restrict__ bias) {
    extern __shared__ char smem[];
#if USE_TCGEN05
    const uint32_t sb = smem_to_u32(smem);
    const int tid  = threadIdx.x;
    const int wid  = tid >> 5;
    const int lane = tid & 31;
    const int bm   = blockIdx.x * 128;

    if (wid == 4) TCGEN05_ALLOC(sb + 0, 256);
    if (tid == 0) { MBARRIER_INIT(sb + 8, 1); MBARRIER_INIT(sb + 16, 1); }
    __syncthreads();
    uint32_t tmem;
    asm volatile("ld.shared.b32 %0, [%1];" : "=r"(tmem) : "r"(sb + 0));

    const uint32_t aoff[2] = {G1_OFF_A0, G1_OFF_A1};
    const uint32_t boff[2] = {G1_OFF_B0, G1_OFF_B1};

    for (int c = 0; c < G1_NCHUNKS; c++) {
        const int buf = c & 1;
        if (c >= 2) MBARRIER_WAIT_PARITY(sb + 8 + 8 * buf, ((c - 2) >> 1) & 1);

        // A chunk: 128 rows x 8 float4 (k = c*32 .. c*32+31), SW128-swizzled
#pragma unroll
        for (int r = 0; r < 4; r++) {
            int i   = tid + r * 256;
            int row = i >> 3;
            int f4  = i & 7;
            int gm  = bm + row;
            float4 v = make_float4(0.f, 0.f, 0.f, 0.f);
            if (gm < N_NODES)
                v = *(const float4*)(A + (size_t)gm * N_FEAT + c * G1_CHUNK_K + f4 * 4);
            v.x = to_tf32(v.x); v.y = to_tf32(v.y); v.z = to_tf32(v.z); v.w = to_tf32(v.w);
            uint32_t off = SMEM_SWIZZLE_128B((uint32_t)(row * 128 + f4 * 16));
            *(float4*)(smem + aoff[buf] + off) = v;
        }
        // B chunk: 256 n-rows x 8 float4 from W1^T
#pragma unroll
        for (int r = 0; r < 8; r++) {
            int i  = tid + r * 256;
            int n  = i >> 3;
            int f4 = i & 7;
            float4 v = *(const float4*)(g_w1t + (size_t)n * N_FEAT + c * G1_CHUNK_K + f4 * 4);
            v.x = to_tf32(v.x); v.y = to_tf32(v.y); v.z = to_tf32(v.z); v.w = to_tf32(v.w);
            uint32_t off = SMEM_SWIZZLE_128B((uint32_t)(n * 128 + f4 * 16));
            *(float4*)(smem + boff[buf] + off) = v;
        }
        FENCE_PROXY_ASYNC();
        __syncthreads();

        if (wid == 4) {
            if (elect_one_pred()) {
                uint64_t ad = MAKE_SMEM_DESC(sb + aoff[buf]);
                uint64_t bd = MAKE_SMEM_DESC(sb + boff[buf]);
#pragma unroll
                for (int ks = 0; ks < 4; ks++)
                    mma_tf32_ss(tmem, ad + ks * 2, bd + ks * 2, IDESC_TF32,
                                (c > 0) || (ks > 0));
                TCGEN05_COMMIT(sb + 8 + 8 * buf);
            }
        }
    }

    MBARRIER_WAIT_PARITY(sb + 8, 1);
    MBARRIER_WAIT_PARITY(sb + 16, 1);
    TCGEN05_FENCE_AFTER();

    // Epilogue: warps 0-3 read D (128 lanes x 256 cols fp32), bias+relu, store.
    if (wid < 4) {
        const int m = bm + wid * 32 + lane;
#pragma unroll
        for (int b = 0; b < 4; b++) {
            uint32_t r[64];
            TCGEN05_LD_32X32B_X32(r, tmem + b * 64);
            TCGEN05_LD_32X32B_X32(r + 32, tmem + b * 64 + 32);
            TCGEN05_WAIT_LD();
            if (m < N_NODES) {
                float* outp = g_h1 + (size_t)m * N_HID + b * 64;
#pragma unroll
                for (int j = 0; j < 64; j += 4) {
                    float4 o;
                    o.x = fmaxf(__uint_as_float(r[j + 0]) + bias[b * 64 + j + 0], 0.f);
                    o.y = fmaxf(__uint_as_float(r[j + 1]) + bias[b * 64 + j + 1], 0.f);
                    o.z = fmaxf(__uint_as_float(r[j + 2]) + bias[b * 64 + j + 2], 0.f);
                    o.w = fmaxf(__uint_as_float(r[j + 3]) + bias[b * 64 + j + 3], 0.f);
                    *(float4*)(outp + j) = o;
                }
            }
        }
        TCGEN05_FENCE_BEFORE();
    }
    __syncthreads();
    if (tid == 0) { MBARRIER_INVAL(sb + 8); MBARRIER_INVAL(sb + 16); }
    __syncthreads();
    if (wid == 4) { TCGEN05_RELINQUISH(); TCGEN05_DEALLOC(tmem, 256); }

#else  // ---------- SIMT fallback (plain sm_103 JIT path) ----------
    float (*As)[132] = (float(*)[132])smem;
    float (*Bs)[68]  = (float(*)[68])(smem + 16 * 132 * sizeof(float));

    const int tid  = threadIdx.x;
    const int bm   = blockIdx.x * 128;
    const int mIdx = tid >> 4;
    const int nIdx = tid & 15;

    for (int nb = 0; nb < 4; nb++) {
        const int bn = nb * 64;
        float acc[8][4];
#pragma unroll
        for (int i = 0; i < 8; i++)
#pragma unroll
            for (int j = 0; j < 4; j++) acc[i][j] = 0.f;

        for (int kt = 0; kt < N_FEAT; kt += 16) {
#pragma unroll
            for (int r = 0; r < 2; r++) {
                int i  = tid + r * 256;
                int m  = i >> 2;
                int k4 = (i & 3) * 4;
                int gm = bm + m;
                float4 v = make_float4(0.f, 0.f, 0.f, 0.f);
                if (gm < N_NODES)
                    v = *(const float4*)(A + (size_t)gm * N_FEAT + kt + k4);
                As[k4 + 0][m] = v.x;
                As[k4 + 1][m] = v.y;
                As[k4 + 2][m] = v.z;
                As[k4 + 3][m] = v.w;
            }
            {
                int n  = tid >> 2;
                int k4 = (tid & 3) * 4;
                float4 v = *(const float4*)(g_w1t + (size_t)(bn + n) * N_FEAT + kt + k4);
                Bs[k4 + 0][n] = v.x;
                Bs[k4 + 1][n] = v.y;
                Bs[k4 + 2][n] = v.z;
                Bs[k4 + 3][n] = v.w;
            }
            __syncthreads();

#pragma unroll
            for (int k = 0; k < 16; k++) {
                float ra[8], rb[4];
#pragma unroll
                for (int i = 0; i < 8; i++) ra[i] = As[k][mIdx * 8 + i];
#pragma unroll
                for (int j = 0; j < 4; j++) rb[j] = Bs[k][nIdx * 4 + j];
#pragma unroll
                for (int i = 0; i < 8; i++)
#pragma unroll
                    for (int j = 0; j < 4; j++) acc[i][j] += ra[i] * rb[j];
            }
            __syncthreads();
        }

#pragma unroll
        for (int i = 0; i < 8; i++) {
            int gm = bm + mIdx * 8 + i;
            if (gm < N_NODES) {
#pragma unroll
                for (int j = 0; j < 4; j++) {
                    int gn = bn + nIdx * 4 + j;
                    float v = acc[i][j] + bias[gn];
                    g_h1[(size_t)gm * N_HID + gn] = fmaxf(v, 0.f);
                }
            }
        }
    }
#endif
}

// ---------------- GEMM2: g_h1 @ W2 + b2 -> g_xs plane 0 ----------------
__global__ void gemm2_kernel(const float* __restrict__ W2,
                             const float* __restrict__ b2) {
    __shared__ float As[64][65];
    __shared__ float W2s[64 * N_CLASS];

    const int tid = threadIdx.x;
    const int bm  = blockIdx.x * 64;
    const int row = tid >> 2;
    const int q   = tid & 3;

    float acc[10];
#pragma unroll
    for (int j = 0; j < 10; j++) acc[j] = 0.f;

    for (int kb = 0; kb < N_HID; kb += 64) {
#pragma unroll
        for (int r = 0; r < 4; r++) {
            int i  = tid + r * 256;
            int rr = i >> 4;
            int c4 = (i & 15) * 4;
            int gm = bm + rr;
            float4 v = make_float4(0.f, 0.f, 0.f, 0.f);
            if (gm < N_NODES)
                v = *(const float4*)(g_h1 + (size_t)gm * N_HID + kb + c4);
            As[rr][c4 + 0] = v.x;
            As[rr][c4 + 1] = v.y;
            As[rr][c4 + 2] = v.z;
            As[rr][c4 + 3] = v.w;
        }
#pragma unroll
        for (int r = 0; r < 10; r++) {
            int e = tid + r * 256;
            W2s[e] = W2[(size_t)kb * N_CLASS + e];
        }
        __syncthreads();

#pragma unroll 4
        for (int k = 0; k < 64; k++) {
            float a = As[row][k];
#pragma unroll
            for (int j = 0; j < 10; j++)
                acc[j] += a * W2s[k * N_CLASS + q * 10 + j];
        }
        __syncthreads();
    }

    int gm = bm + row;
    if (gm < N_NODES) {
#pragma unroll
        for (int j = 0; j < 10; j++)
            g_xs[(size_t)gm * N_CLASS + q * 10 + j] = acc[j] + b2[q * 10 + j];
    }
}

// ---------------- CSR build ----------------
__global__ void zero_count_kernel() {
    int i = blockIdx.x * blockDim.x + threadIdx.x;
    if (i < N_NODES) g_count[i] = 0;
    if (i < 256) g_degcount[i] = 0;
}

__global__ void hist_kernel(const int* __restrict__ edge_row) {
    int e = blockIdx.x * blockDim.x + threadIdx.x;
    if (e < N_EDGES) atomicAdd(&g_count[edge_row[e]], 1);
}

__global__ void scan_kernel() {
    __shared__ int warp_sums[32];
    __shared__ int carry_s;
    const int tid = threadIdx.x, lane = tid & 31, wid = tid >> 5;
    if (tid == 0) { carry_s = 0; g_rowptr[0] = 0; }
    __syncthreads();

    for (int base = 0; base < N_NODES; base += 1024) {
        int i = base + tid;
        int v = (i < N_NODES) ? g_count[i] : 0;
        int x = v;
#pragma unroll
        for (int off = 1; off < 32; off <<= 1) {
            int y = __shfl_up_sync(0xffffffffu, x, off);
            if (lane >= off) x += y;
        }
        if (lane == 31) warp_sums[wid] = x;
        __syncthreads();
        if (wid == 0) {
            int s = warp_sums[lane];
#pragma unroll
            for (int off = 1; off < 32; off <<= 1) {
                int y = __shfl_up_sync(0xffffffffu, s, off);
                if (lane >= off) s += y;
            }
            warp_sums[lane] = s;
        }
        __syncthreads();
        int incl = x + ((wid > 0) ? warp_sums[wid - 1] : 0) + carry_s;
        if (i < N_NODES) {
            g_rowptr[i + 1] = incl;
            g_cursor[i]     = incl - v;
        }
        __syncthreads();
        if (tid == 1023) carry_s = incl;
        __syncthreads();
    }
}

__global__ void scatter_kernel(const int* __restrict__ edge_row,
                               const int* __restrict__ edge_col,
                               const float* __restrict__ edge_w) {
    int e = blockIdx.x * blockDim.x + threadIdx.x;
    if (e < N_EDGES) {
        int r = edge_row[e];
        int p = atomicAdd(&g_cursor[r], 1);
        g_edge[p] = make_int2(edge_col[e], __float_as_int(edge_w[e]));
    }
}

// ---- degree-sort rows so each SpMM warp gets equal-degree rows ----
__global__ void deg_hist_kernel() {
    int i = blockIdx.x * blockDim.x + threadIdx.x;
    if (i < N_NODES) {
        int d = g_rowptr[i + 1] - g_rowptr[i];
        if (d > 255) d = 255;
        atomicAdd(&g_degcount[d], 1);
    }
}

__global__ void deg_scan_kernel() {   // 1 block, 256 threads
    __shared__ int ws[8];
    int tid = threadIdx.x, lane = tid & 31, wid = tid >> 5;
    int v = g_degcount[tid];
    int x = v;
#pragma unroll
    for (int off = 1; off < 32; off <<= 1) {
        int y = __shfl_up_sync(0xffffffffu, x, off);
        if (lane >= off) x += y;
    }
    if (lane == 31) ws[wid] = x;
    __syncthreads();
    if (wid == 0 && lane < 8) {
        int s = ws[lane];
#pragma unroll
        for (int off = 1; off < 8; off <<= 1) {
            int y = __shfl_up_sync(0xffu, s, off);
            if (lane >= off) s += y;
        }
        ws[lane] = s;
    }
    __syncthreads();
    int excl = x - v + ((wid > 0) ? ws[wid - 1] : 0);
    g_degoff[tid] = excl;
}

__global__ void perm_kernel() {
    int i = blockIdx.x * blockDim.x + threadIdx.x;
    if (i < N_NODES) {
        int d = g_rowptr[i + 1] - g_rowptr[i];
        if (d > 255) d = 255;
        int p = atomicAdd(&g_degoff[d], 1);
        g_rowperm[p] = i;
    }
}

// ---------------- SpMM hop: xs[hop] = A_sparse @ xs[hop-1] ----------------
// 10 threads per row, rows visited in degree-sorted order (uniform warps).
__global__ void __launch_bounds__(320) spmm_kernel(int hop) {
    const float* __restrict__ xin  = g_xs + (size_t)(hop - 1) * N_NODES * N_CLASS;
    float* __restrict__       xout = g_xs + (size_t)hop * N_NODES * N_CLASS;

    int t    = blockIdx.x * blockDim.x + threadIdx.x;
    int idx  = t / 10;
    int lane = t - idx * 10;
    if (idx >= N_NODES) return;
    const int row = g_rowperm[idx];

    const int s = g_rowptr[row];
    const int e = g_rowptr[row + 1];
    float4 acc = make_float4(0.f, 0.f, 0.f, 0.f);

    int i = s;
    for (; i + 4 <= e; i += 4) {
        int2 e0 = g_edge[i + 0];
        int2 e1 = g_edge[i + 1];
        int2 e2 = g_edge[i + 2];
        int2 e3 = g_edge[i + 3];
        float4 v0 = *(const float4*)(xin + (size_t)e0.x * N_CLASS + lane * 4);
        float4 v1 = *(const float4*)(xin + (size_t)e1.x * N_CLASS + lane * 4);
        float4 v2 = *(const float4*)(xin + (size_t)e2.x * N_CLASS + lane * 4);
        float4 v3 = *(const float4*)(xin + (size_t)e3.x * N_CLASS + lane * 4);
        float w0 = __int_as_float(e0.y);
        float w1 = __int_as_float(e1.y);
        float w2 = __int_as_float(e2.y);
        float w3 = __int_as_float(e3.y);
        acc.x += w0 * v0.x; acc.y += w0 * v0.y; acc.z += w0 * v0.z; acc.w += w0 * v0.w;
        acc.x += w1 * v1.x; acc.y += w1 * v1.y; acc.z += w1 * v1.z; acc.w += w1 * v1.w;
        acc.x += w2 * v2.x; acc.y += w2 * v2.y; acc.z += w2 * v2.z; acc.w += w2 * v2.w;
        acc.x += w3 * v3.x; acc.y += w3 * v3.y; acc.z += w3 * v3.z; acc.w += w3 * v3.w;
    }
    for (; i < e; i++) {
        int2  ed = g_edge[i];
        float w  = __int_as_float(ed.y);
        float4 v = *(const float4*)(xin + (size_t)ed.x * N_CLASS + lane * 4);
        acc.x += w * v.x; acc.y += w * v.y; acc.z += w * v.z; acc.w += w * v.w;
    }
    *(float4*)(xout + (size_t)row * N_CLASS + lane * 4) = acc;
}

// ---------------- attention + log_softmax ----------------
__global__ void attn_kernel(const float* __restrict__ Wa,
                            const float* __restrict__ ba,
                            float* __restrict__ out) {
    int gwarp = (blockIdx.x * blockDim.x + threadIdx.x) >> 5;
    int lane  = threadIdx.x & 31;
    if (gwarp >= N_NODES) return;
    const int n = gwarp;

    const float wa0 = Wa[lane];
    const float wa1 = (lane < 8) ? Wa[lane + 32] : 0.f;
    const float bav = ba[0];

    float acc0 = 0.f, acc1 = 0.f;
#pragma unroll
    for (int k = 0; k <= K_HOPS; k++) {
        const float* p = g_xs + ((size_t)k * N_NODES + n) * N_CLASS;
        float v0 = p[lane];
        float v1 = (lane < 8) ? p[lane + 32] : 0.f;
        float dot = v0 * wa0 + v1 * wa1;
#pragma unroll
        for (int off = 16; off > 0; off >>= 1)
            dot += __shfl_xor_sync(0xffffffffu, dot, off);
        float s = 1.f / (1.f + expf(-(dot + bav)));
        acc0 += s * v0;
        acc1 += s * v1;
    }

    float m = acc0;
    if (lane < 8) m = fmaxf(m, acc1);
#pragma unroll
    for (int off = 16; off > 0; off >>= 1)
        m = fmaxf(m, __shfl_xor_sync(0xffffffffu, m, off));

    float se = expf(acc0 - m) + ((lane < 8) ? expf(acc1 - m) : 0.f);
#pragma unroll
    for (int off = 16; off > 0; off >>= 1)
        se += __shfl_xor_sync(0xffffffffu, se, off);

    float lse = logf(se);
    out[(size_t)n * N_CLASS + lane] = acc0 - m - lse;
    if (lane < 8)
        out[(size_t)n * N_CLASS + lane + 32] = acc1 - m - lse;
}

// ---------------- launch (fork-join: CSR chain || dense chain) ----------------
static cudaStream_t g_side    = nullptr;
static cudaEvent_t  g_ev_fork = nullptr;
static cudaEvent_t  g_ev_join = nullptr;
static int          g_inited  = 0;

extern "C" void kernel_launch(void* const* d_in, const int* in_sizes, int n_in,
                              void* d_out, int out_size) {
    const float* feature  = (const float*)d_in[0];
    const int*   edge_row = (const int*)  d_in[1];
    const int*   edge_col = (const int*)  d_in[2];
    const float* edge_w   = (const float*)d_in[3];
    const float* W1       = (const float*)d_in[4];
    const float* b1       = (const float*)d_in[5];
    const float* W2       = (const float*)d_in[6];
    const float* b2       = (const float*)d_in[7];
    const float* Wa       = (const float*)d_in[8];
    const float* ba       = (const float*)d_in[9];
    float*       out      = (float*)d_out;

    if (!g_inited) {
        cudaStreamCreateWithFlags(&g_side, cudaStreamNonBlocking);
        cudaEventCreateWithFlags(&g_ev_fork, cudaEventDisableTiming);
        cudaEventCreateWithFlags(&g_ev_join, cudaEventDisableTiming);
        cudaFuncSetAttribute(gemm1_tc_kernel,
                             cudaFuncAttributeMaxDynamicSharedMemorySize, G1_SMEM_TOTAL);
        g_inited = 1;
    }

    const bool fork = (g_side != nullptr) && (g_ev_fork != nullptr) && (g_ev_join != nullptr);
    cudaStream_t cs = fork ? g_side : (cudaStream_t)0;

    if (fork) {
        cudaEventRecord(g_ev_fork, 0);
        cudaStreamWaitEvent(g_side, g_ev_fork, 0);
    }

    // ---- CSR chain (independent of dense path) ----
    zero_count_kernel<<<(N_NODES + 255) / 256, 256, 0, cs>>>();
    hist_kernel<<<(N_EDGES + 255) / 256, 256, 0, cs>>>(edge_row);
    scan_kernel<<<1, 1024, 0, cs>>>();
    scatter_kernel<<<(N_EDGES + 255) / 256, 256, 0, cs>>>(edge_row, edge_col, edge_w);
    deg_hist_kernel<<<(N_NODES + 255) / 256, 256, 0, cs>>>();
    deg_scan_kernel<<<1, 256, 0, cs>>>();
    perm_kernel<<<(N_NODES + 255) / 256, 256, 0, cs>>>();

    if (fork) cudaEventRecord(g_ev_join, g_side);

    // ---- dense chain (legacy stream) ----
    transpose_w1_kernel<<<dim3(N_FEAT / 32, N_HID / 32), dim3(32, 8)>>>(W1);
    gemm1_tc_kernel<<<(N_NODES + 127) / 128, 256, G1_SMEM_TOTAL>>>(feature, b1);
    gemm2_kernel<<<(N_NODES + 63) / 64, 256>>>(W2, b2);

    // ---- join: SpMM needs both CSR and xs plane 0 ----
    if (fork) cudaStreamWaitEvent((cudaStream_t)0, g_ev_join, 0);

    for (int k = 1; k <= K_HOPS; k++)
        spmm_kernel<<<(N_NODES * 10 + 319) / 320, 320>>>(k);

    attn_kernel<<<(N_NODES * 32 + 255) / 256, 256>>>(Wa, ba, out);
}

// round 8
// speedup vs baseline: 1.1473x; 1.0982x over previous
#include <cuda_runtime.h>
#include <cuda_bf16.h>
#include <math.h>
#include <stdint.h>

#define N_NODES 100000
#define N_EDGES 3200000
#define N_FEAT  512
#define N_HID   256
#define N_CLASS 40
#define K_HOPS  10

// tcgen05 only exists in the arch-accelerated target (sm_103a / sm_100a).
// The harness also runs a plain compute_103 ptxas pass, which rejects it.
#if defined(__CUDA_ARCH_FEAT_SM103_ALL) || defined(__CUDA_ARCH_FEAT_SM100_ALL)
#define USE_TCGEN05 1
#else
#define USE_TCGEN05 0
#endif

// ---------------- scratch (no cudaMalloc allowed) ----------------
__device__ float g_h1[(size_t)N_NODES * N_HID];                   // 102.4 MB
__device__ float g_xs[(size_t)(K_HOPS + 1) * N_NODES * N_CLASS];  // 176 MB
__device__ float g_w1t[(size_t)N_HID * N_FEAT];                   // W1^T, 512 KB
__device__ float g_w2t[(size_t)N_CLASS * N_HID];                  // W2^T, 40 KB
__device__ int   g_rowptr[N_NODES + 1];
__device__ int   g_count[N_NODES];
__device__ int   g_cursor[N_NODES];
__device__ int2  g_edge[N_EDGES];                                 // (col, w bits) interleaved

// ================= PTX helpers =================
__device__ __forceinline__ uint32_t smem_to_u32(const void* p) {
    uint32_t a;
    asm("{ .reg .u64 t; cvta.to.shared.u64 t, %1; cvt.u32.u64 %0, t; }"
        : "=r"(a) : "l"(p));
    return a;
}

#if USE_TCGEN05
__device__ __forceinline__ uint32_t elect_one_pred() {
    uint32_t p;
    asm volatile("{\n\t.reg .pred p;\n\telect.sync _|p, 0xFFFFFFFF;\n\t"
                 "selp.b32 %0, 1, 0, p;\n\t}" : "=r"(p));
    return p;
}

#define TCGEN05_ALLOC(smem_addr, nCols) \
    asm volatile("tcgen05.alloc.cta_group::1.sync.aligned.shared::cta.b32 [%0], %1;" \
                 :: "r"((uint32_t)(smem_addr)), "r"((uint32_t)(nCols)) : "memory")
#define TCGEN05_DEALLOC(tmem, nCols) \
    asm volatile("tcgen05.dealloc.cta_group::1.sync.aligned.b32 %0, %1;" \
                 :: "r"(tmem), "r"((uint32_t)(nCols)))
#define TCGEN05_RELINQUISH() \
    asm volatile("tcgen05.relinquish_alloc_permit.cta_group::1.sync.aligned;")
#define TCGEN05_COMMIT(mbar) \
    asm volatile("tcgen05.commit.cta_group::1.mbarrier::arrive::one.shared::cluster.b64 [%0];" \
                 :: "r"((uint32_t)(mbar)) : "memory")
#define TCGEN05_WAIT_LD() \
    asm volatile("tcgen05.wait::ld.sync.aligned;" ::: "memory")
#define TCGEN05_FENCE_AFTER() \
    asm volatile("tcgen05.fence::after_thread_sync;" ::: "memory")
#define TCGEN05_FENCE_BEFORE() \
    asm volatile("tcgen05.fence::before_thread_sync;" ::: "memory")
#define MBARRIER_INIT(mbar, cnt) \
    asm volatile("mbarrier.init.shared.b64 [%0], %1;" \
                 :: "r"((uint32_t)(mbar)), "r"((uint32_t)(cnt)) : "memory")
#define MBARRIER_INVAL(mbar) \
    asm volatile("mbarrier.inval.shared.b64 [%0];" :: "r"((uint32_t)(mbar)) : "memory")
#define FENCE_PROXY_ASYNC() \
    asm volatile("fence.proxy.async.shared::cta;" ::: "memory")

#define MBARRIER_WAIT_PARITY(mbar, parity) do { \
    uint32_t _m = (uint32_t)(mbar); \
    uint32_t _p = (uint32_t)(parity); \
    uint32_t _done; \
    asm volatile("{\n\t.reg .pred p;\n\t" \
        "mbarrier.try_wait.parity.acquire.cta.shared::cta.b64 p, [%1], %2;\n\t" \
        "selp.b32 %0, 1, 0, p;\n\t}" : "=r"(_done) : "r"(_m), "r"(_p) : "memory"); \
    if (!_done) { \
        asm volatile("{\n\t.reg .pred P1;\n\t" \
            "WL_%=:\n\t" \
            "mbarrier.try_wait.parity.acquire.cta.shared::cta.b64 P1, [%0], %1, 0x989680;\n\t" \
            "@P1 bra.uni WD_%=;\n\t" \
            "bra.uni WL_%=;\n\t" \
            "WD_%=:\n\t}" :: "r"(_m), "r"(_p) : "memory"); \
    } \
} while (0)

#define TCGEN05_LD_32X32B_X32(r, tmem_addr) \
    asm volatile( \
        "tcgen05.ld.sync.aligned.32x32b.x32.b32 " \
        "{%0, %1, %2, %3, %4, %5, %6, %7, " \
        " %8, %9, %10, %11, %12, %13, %14, %15, " \
        " %16, %17, %18, %19, %20, %21, %22, %23, " \
        " %24, %25, %26, %27, %28, %29, %30, %31}, [%32];" \
        : "=r"((r)[0]),  "=r"((r)[1]),  "=r"((r)[2]),  "=r"((r)[3]), \
          "=r"((r)[4]),  "=r"((r)[5]),  "=r"((r)[6]),  "=r"((r)[7]), \
          "=r"((r)[8]),  "=r"((r)[9]),  "=r"((r)[10]), "=r"((r)[11]), \
          "=r"((r)[12]), "=r"((r)[13]), "=r"((r)[14]), "=r"((r)[15]), \
          "=r"((r)[16]), "=r"((r)[17]), "=r"((r)[18]), "=r"((r)[19]), \
          "=r"((r)[20]), "=r"((r)[21]), "=r"((r)[22]), "=r"((r)[23]), \
          "=r"((r)[24]), "=r"((r)[25]), "=r"((r)[26]), "=r"((r)[27]), \
          "=r"((r)[28]), "=r"((r)[29]), "=r"((r)[30]), "=r"((r)[31]) \
        : "r"(tmem_addr))

#define TCGEN05_LD_32X32B_X8(r, tmem_addr) \
    asm volatile( \
        "tcgen05.ld.sync.aligned.32x32b.x8.b32 " \
        "{%0, %1, %2, %3, %4, %5, %6, %7}, [%8];" \
        : "=r"((r)[0]), "=r"((r)[1]), "=r"((r)[2]), "=r"((r)[3]), \
          "=r"((r)[4]), "=r"((r)[5]), "=r"((r)[6]), "=r"((r)[7]) \
        : "r"(tmem_addr))

// SW128 K-major descriptor: layout=2 (SW128), version=1, SBO=64, LBO=1
static constexpr uint64_t SMEM_DESC_BASE_SW128 =
    (uint64_t(2) << 61) | (uint64_t(1) << 46) | (uint64_t(64) << 32) | (uint64_t(1) << 16);
#define MAKE_SMEM_DESC(base_addr) \
    (SMEM_DESC_BASE_SW128 | ((uint64_t)((base_addr) >> 4) & 0x3FFF))

// tf32 SS MMA idesc: c=F32 (1<<4), a=TF32 (2<<7), b=TF32 (2<<10),
// N/8 at bits[17:23), M/16 at bits[24:29)
static constexpr uint32_t IDESC_TF32_N256 =
    (1u << 4) | (2u << 7) | (2u << 10) | ((256u / 8u) << 17) | ((128u / 16u) << 24);
static constexpr uint32_t IDESC_TF32_N64 =
    (1u << 4) | (2u << 7) | (2u << 10) | ((64u / 8u) << 17) | ((128u / 16u) << 24);

__device__ __forceinline__ void mma_tf32_ss(uint32_t d, uint64_t ad, uint64_t bd,
                                            uint32_t idesc, bool acc) {
    uint32_t en = acc ? 1u : 0u;
    asm volatile(
        "{\n\t.reg .pred p;\n\tsetp.ne.u32 p, %5, 0;\n\t"
        "tcgen05.mma.cta_group::1.kind::tf32 [%0], %1, %2, %3, {%4, %4, %4, %4}, p;\n\t}"
        :: "r"(d), "l"(ad), "l"(bd), "r"(idesc), "r"(0u), "r"(en)
        : "memory");
}

__device__ __forceinline__ float to_tf32(float x) {
    uint32_t r;
    asm("cvt.rna.tf32.f32 %0, %1;" : "=r"(r) : "f"(x));
    return __uint_as_float(r);
}
#endif  // USE_TCGEN05

#define SMEM_SWIZZLE_128B(off) ((off) ^ (((off) >> 3) & 0x70))

// ---------------- W1 transpose: g_w1t[n][k] = W1[k][n] ----------------
__global__ void transpose_w1_kernel(const float* __restrict__ W1) {
    __shared__ float t[32][33];
    int bk = blockIdx.x * 32;
    int bn = blockIdx.y * 32;
    int x = threadIdx.x, y = threadIdx.y;
#pragma unroll
    for (int i = 0; i < 32; i += 8)
        t[y + i][x] = W1[(size_t)(bk + y + i) * N_HID + bn + x];
    __syncthreads();
#pragma unroll
    for (int i = 0; i < 32; i += 8)
        g_w1t[(size_t)(bn + y + i) * N_FEAT + bk + x] = t[x][y + i];
}

// ---------------- W2 transpose: g_w2t[n][k] = W2[k][n] (tiny) ----------------
__global__ void transpose_w2_kernel(const float* __restrict__ W2) {
    int i = blockIdx.x * blockDim.x + threadIdx.x;   // over 256*40
    if (i < N_HID * N_CLASS) {
        int k = i / N_CLASS;
        int n = i - k * N_CLASS;
        g_w2t[(size_t)n * N_HID + k] = W2[i];
    }
}

// ---------------- GEMM1: relu(feature @ W1 + b1) -> g_h1 ----------------
#define G1_CHUNK_K   32
#define G1_NCHUNKS   (N_FEAT / G1_CHUNK_K)      // 16
#define G1_A_BYTES   (128 * 128)
#define G1_B_BYTES   (256 * 128)
#define G1_OFF_A0    1024
#define G1_OFF_A1    (G1_OFF_A0 + G1_A_BYTES)
#define G1_OFF_B0    (G1_OFF_A1 + G1_A_BYTES)
#define G1_OFF_B1    (G1_OFF_B0 + G1_B_BYTES)
#define G1_SMEM_TOTAL (G1_OFF_B1 + G1_B_BYTES)   // 99328

__global__ void __launch_bounds__(256) gemm1_tc_kernel(const float* __restrict__ A,
                                                       const float* __restrict__ bias) {
    extern __shared__ char smem[];
#if USE_TCGEN05
    const uint32_t sb = smem_to_u32(smem);
    const int tid  = threadIdx.x;
    const int wid  = tid >> 5;
    const int lane = tid & 31;
    const int bm   = blockIdx.x * 128;

    if (wid == 4) TCGEN05_ALLOC(sb + 0, 256);
    if (tid == 0) { MBARRIER_INIT(sb + 8, 1); MBARRIER_INIT(sb + 16, 1); }
    __syncthreads();
    uint32_t tmem;
    asm volatile("ld.shared.b32 %0, [%1];" : "=r"(tmem) : "r"(sb + 0));

    const uint32_t aoff[2] = {G1_OFF_A0, G1_OFF_A1};
    const uint32_t boff[2] = {G1_OFF_B0, G1_OFF_B1};

    for (int c = 0; c < G1_NCHUNKS; c++) {
        const int buf = c & 1;
        if (c >= 2) MBARRIER_WAIT_PARITY(sb + 8 + 8 * buf, ((c - 2) >> 1) & 1);

#pragma unroll
        for (int r = 0; r < 4; r++) {
            int i   = tid + r * 256;
            int row = i >> 3;
            int f4  = i & 7;
            int gm  = bm + row;
            float4 v = make_float4(0.f, 0.f, 0.f, 0.f);
            if (gm < N_NODES)
                v = *(const float4*)(A + (size_t)gm * N_FEAT + c * G1_CHUNK_K + f4 * 4);
            v.x = to_tf32(v.x); v.y = to_tf32(v.y); v.z = to_tf32(v.z); v.w = to_tf32(v.w);
            uint32_t off = SMEM_SWIZZLE_128B((uint32_t)(row * 128 + f4 * 16));
            *(float4*)(smem + aoff[buf] + off) = v;
        }
#pragma unroll
        for (int r = 0; r < 8; r++) {
            int i  = tid + r * 256;
            int n  = i >> 3;
            int f4 = i & 7;
            float4 v = *(const float4*)(g_w1t + (size_t)n * N_FEAT + c * G1_CHUNK_K + f4 * 4);
            v.x = to_tf32(v.x); v.y = to_tf32(v.y); v.z = to_tf32(v.z); v.w = to_tf32(v.w);
            uint32_t off = SMEM_SWIZZLE_128B((uint32_t)(n * 128 + f4 * 16));
            *(float4*)(smem + boff[buf] + off) = v;
        }
        FENCE_PROXY_ASYNC();
        __syncthreads();

        if (wid == 4) {
            if (elect_one_pred()) {
                uint64_t ad = MAKE_SMEM_DESC(sb + aoff[buf]);
                uint64_t bd = MAKE_SMEM_DESC(sb + boff[buf]);
#pragma unroll
                for (int ks = 0; ks < 4; ks++)
                    mma_tf32_ss(tmem, ad + ks * 2, bd + ks * 2, IDESC_TF32_N256,
                                (c > 0) || (ks > 0));
                TCGEN05_COMMIT(sb + 8 + 8 * buf);
            }
        }
    }

    MBARRIER_WAIT_PARITY(sb + 8, 1);
    MBARRIER_WAIT_PARITY(sb + 16, 1);
    TCGEN05_FENCE_AFTER();

    if (wid < 4) {
        const int m = bm + wid * 32 + lane;
#pragma unroll
        for (int b = 0; b < 4; b++) {
            uint32_t r[64];
            TCGEN05_LD_32X32B_X32(r, tmem + b * 64);
            TCGEN05_LD_32X32B_X32(r + 32, tmem + b * 64 + 32);
            TCGEN05_WAIT_LD();
            if (m < N_NODES) {
                float* outp = g_h1 + (size_t)m * N_HID + b * 64;
#pragma unroll
                for (int j = 0; j < 64; j += 4) {
                    float4 o;
                    o.x = fmaxf(__uint_as_float(r[j + 0]) + bias[b * 64 + j + 0], 0.f);
                    o.y = fmaxf(__uint_as_float(r[j + 1]) + bias[b * 64 + j + 1], 0.f);
                    o.z = fmaxf(__uint_as_float(r[j + 2]) + bias[b * 64 + j + 2], 0.f);
                    o.w = fmaxf(__uint_as_float(r[j + 3]) + bias[b * 64 + j + 3], 0.f);
                    *(float4*)(outp + j) = o;
                }
            }
        }
        TCGEN05_FENCE_BEFORE();
    }
    __syncthreads();
    if (tid == 0) { MBARRIER_INVAL(sb + 8); MBARRIER_INVAL(sb + 16); }
    __syncthreads();
    if (wid == 4) { TCGEN05_RELINQUISH(); TCGEN05_DEALLOC(tmem, 256); }

#else  // ---------- SIMT fallback (plain sm_103 JIT path) ----------
    float (*As)[132] = (float(*)[132])smem;
    float (*Bs)[68]  = (float(*)[68])(smem + 16 * 132 * sizeof(float));

    const int tid  = threadIdx.x;
    const int bm   = blockIdx.x * 128;
    const int mIdx = tid >> 4;
    const int nIdx = tid & 15;

    for (int nb = 0; nb < 4; nb++) {
        const int bn = nb * 64;
        float acc[8][4];
#pragma unroll
        for (int i = 0; i < 8; i++)
#pragma unroll
            for (int j = 0; j < 4; j++) acc[i][j] = 0.f;

        for (int kt = 0; kt < N_FEAT; kt += 16) {
#pragma unroll
            for (int r = 0; r < 2; r++) {
                int i  = tid + r * 256;
                int m  = i >> 2;
                int k4 = (i & 3) * 4;
                int gm = bm + m;
                float4 v = make_float4(0.f, 0.f, 0.f, 0.f);
                if (gm < N_NODES)
                    v = *(const float4*)(A + (size_t)gm * N_FEAT + kt + k4);
                As[k4 + 0][m] = v.x;
                As[k4 + 1][m] = v.y;
                As[k4 + 2][m] = v.z;
                As[k4 + 3][m] = v.w;
            }
            {
                int n  = tid >> 2;
                int k4 = (tid & 3) * 4;
                float4 v = *(const float4*)(g_w1t + (size_t)(bn + n) * N_FEAT + kt + k4);
                Bs[k4 + 0][n] = v.x;
                Bs[k4 + 1][n] = v.y;
                Bs[k4 + 2][n] = v.z;
                Bs[k4 + 3][n] = v.w;
            }
            __syncthreads();

#pragma unroll
            for (int k = 0; k < 16; k++) {
                float ra[8], rb[4];
#pragma unroll
                for (int i = 0; i < 8; i++) ra[i] = As[k][mIdx * 8 + i];
#pragma unroll
                for (int j = 0; j < 4; j++) rb[j] = Bs[k][nIdx * 4 + j];
#pragma unroll
                for (int i = 0; i < 8; i++)
#pragma unroll
                    for (int j = 0; j < 4; j++) acc[i][j] += ra[i] * rb[j];
            }
            __syncthreads();
        }

#pragma unroll
        for (int i = 0; i < 8; i++) {
            int gm = bm + mIdx * 8 + i;
            if (gm < N_NODES) {
#pragma unroll
                for (int j = 0; j < 4; j++) {
                    int gn = bn + nIdx * 4 + j;
                    float v = acc[i][j] + bias[gn];
                    g_h1[(size_t)gm * N_HID + gn] = fmaxf(v, 0.f);
                }
            }
        }
    }
#endif
}

// ---------------- GEMM2 (tcgen05 tf32): g_h1 @ W2 + b2 -> g_xs plane 0 ------
// M=128/CTA, N=64 (40 real + 24 zero-pad), K=256 in 8 chunks of 32, dbl-buffer.
#define G2_CHUNK_K   32
#define G2_NCHUNKS   (N_HID / G2_CHUNK_K)        // 8
#define G2_A_BYTES   (128 * 128)                  // 16 KB
#define G2_BCH_BYTES (64 * 128)                   // 8 KB per chunk tile
#define G2_OFF_A0    1024
#define G2_OFF_A1    (G2_OFF_A0 + G2_A_BYTES)
#define G2_OFF_B     (G2_OFF_A1 + G2_A_BYTES)     // 33792 (1024-aligned)
#define G2_SMEM_TOTAL (G2_OFF_B + G2_NCHUNKS * G2_BCH_BYTES)  // 99328

__global__ void __launch_bounds__(256) gemm2_tc_kernel(const float* __restrict__ b2) {
    extern __shared__ char smem[];
#if USE_TCGEN05
    const uint32_t sb = smem_to_u32(smem);
    const int tid  = threadIdx.x;
    const int wid  = tid >> 5;
    const int lane = tid & 31;
    const int bm   = blockIdx.x * 128;

    if (wid == 4) TCGEN05_ALLOC(sb + 0, 64);
    if (tid == 0) { MBARRIER_INIT(sb + 8, 1); MBARRIER_INIT(sb + 16, 1); }
    __syncthreads();
    uint32_t tmem;
    asm volatile("ld.shared.b32 %0, [%1];" : "=r"(tmem) : "r"(sb + 0));

    // Zero the 64-row B region, then fill rows 0..39 with W2^T (tf32).
    for (int i = tid; i < (G2_NCHUNKS * G2_BCH_BYTES) / 16; i += 256)
        *(float4*)(smem + G2_OFF_B + i * 16) = make_float4(0.f, 0.f, 0.f, 0.f);
    __syncthreads();
    for (int i = tid; i < G2_NCHUNKS * N_CLASS * 8; i += 256) {
        int ch  = i / (N_CLASS * 8);
        int rem = i - ch * (N_CLASS * 8);
        int n   = rem >> 3;
        int f4  = rem & 7;
        float4 v = *(const float4*)(g_w2t + (size_t)n * N_HID + ch * G2_CHUNK_K + f4 * 4);
        v.x = to_tf32(v.x); v.y = to_tf32(v.y); v.z = to_tf32(v.z); v.w = to_tf32(v.w);
        uint32_t off = SMEM_SWIZZLE_128B((uint32_t)(n * 128 + f4 * 16));
        *(float4*)(smem + G2_OFF_B + ch * G2_BCH_BYTES + off) = v;
    }

    const uint32_t aoff[2] = {G2_OFF_A0, G2_OFF_A1};

    for (int c = 0; c < G2_NCHUNKS; c++) {
        const int buf = c & 1;
        if (c >= 2) MBARRIER_WAIT_PARITY(sb + 8 + 8 * buf, ((c - 2) >> 1) & 1);

        // A chunk: 128 rows x 32 floats from g_h1 (tf32, SW128)
#pragma unroll
        for (int r = 0; r < 4; r++) {
            int i   = tid + r * 256;
            int row = i >> 3;
            int f4  = i & 7;
            int gm  = bm + row;
            float4 v = make_float4(0.f, 0.f, 0.f, 0.f);
            if (gm < N_NODES)
                v = *(const float4*)(g_h1 + (size_t)gm * N_HID + c * G2_CHUNK_K + f4 * 4);
            v.x = to_tf32(v.x); v.y = to_tf32(v.y); v.z = to_tf32(v.z); v.w = to_tf32(v.w);
            uint32_t off = SMEM_SWIZZLE_128B((uint32_t)(row * 128 + f4 * 16));
            *(float4*)(smem + aoff[buf] + off) = v;
        }
        FENCE_PROXY_ASYNC();
        __syncthreads();   // also covers the one-time B fill before c=0's MMA

        if (wid == 4) {
            if (elect_one_pred()) {
                uint64_t ad = MAKE_SMEM_DESC(sb + aoff[buf]);
                uint64_t bd = MAKE_SMEM_DESC(sb + G2_OFF_B + c * G2_BCH_BYTES);
#pragma unroll
                for (int ks = 0; ks < 4; ks++)
                    mma_tf32_ss(tmem, ad + ks * 2, bd + ks * 2, IDESC_TF32_N64,
                                (c > 0) || (ks > 0));
                TCGEN05_COMMIT(sb + 8 + 8 * buf);
            }
        }
    }

    MBARRIER_WAIT_PARITY(sb + 8, 1);
    MBARRIER_WAIT_PARITY(sb + 16, 1);
    TCGEN05_FENCE_AFTER();

    // Epilogue: warps 0-3 read D cols 0..39, add b2, store 160B per row.
    if (wid < 4) {
        const int m = bm + wid * 32 + lane;
        uint32_t r[40];
        TCGEN05_LD_32X32B_X32(r, tmem);
        TCGEN05_LD_32X32B_X8(r + 32, tmem + 32);
        TCGEN05_WAIT_LD();
        if (m < N_NODES) {
            float* outp = g_xs + (size_t)m * N_CLASS;
#pragma unroll
            for (int j = 0; j < 40; j += 4) {
                float4 o;
                o.x = __uint_as_float(r[j + 0]) + b2[j + 0];
                o.y = __uint_as_float(r[j + 1]) + b2[j + 1];
                o.z = __uint_as_float(r[j + 2]) + b2[j + 2];
                o.w = __uint_as_float(r[j + 3]) + b2[j + 3];
                *(float4*)(outp + j) = o;
            }
        }
        TCGEN05_FENCE_BEFORE();
    }
    __syncthreads();
    if (tid == 0) { MBARRIER_INVAL(sb + 8); MBARRIER_INVAL(sb + 16); }
    __syncthreads();
    if (wid == 4) { TCGEN05_RELINQUISH(); TCGEN05_DEALLOC(tmem, 64); }

#else  // ---------- SIMT fallback: two 64-row halves per 128-row block -------
    float (*As)[65] = (float(*)[65])smem;                         // [64][65]
    float* W2s = (float*)(smem + 64 * 65 * sizeof(float));        // [64*40]

    const int tid = threadIdx.x;
    for (int half = 0; half < 2; half++) {
        const int bm  = blockIdx.x * 128 + half * 64;
        const int row = tid >> 2;
        const int q   = tid & 3;

        float acc[10];
#pragma unroll
        for (int j = 0; j < 10; j++) acc[j] = 0.f;

        for (int kb = 0; kb < N_HID; kb += 64) {
#pragma unroll
            for (int r = 0; r < 4; r++) {
                int i  = tid + r * 256;
                int rr = i >> 4;
                int c4 = (i & 15) * 4;
                int gm = bm + rr;
                float4 v = make_float4(0.f, 0.f, 0.f, 0.f);
                if (gm < N_NODES)
                    v = *(const float4*)(g_h1 + (size_t)gm * N_HID + kb + c4);
                As[rr][c4 + 0] = v.x;
                As[rr][c4 + 1] = v.y;
                As[rr][c4 + 2] = v.z;
                As[rr][c4 + 3] = v.w;
            }
#pragma unroll
            for (int r = 0; r < 10; r++) {
                int e = tid + r * 256;
                W2s[e] = g_w2t[0] * 0.f + 0.f;  // placeholder overwritten below
            }
            // load W2 chunk (64 k-rows x 40) from original layout via w2t
#pragma unroll
            for (int r = 0; r < 10; r++) {
                int e = tid + r * 256;          // e over 2560 = 64*40
                int k = e / N_CLASS;
                int n = e - k * N_CLASS;
                W2s[e] = g_w2t[(size_t)n * N_HID + kb + k];
            }
            __syncthreads();

#pragma unroll 4
            for (int k = 0; k < 64; k++) {
                float a = As[row][k];
#pragma unroll
                for (int j = 0; j < 10; j++)
                    acc[j] += a * W2s[k * N_CLASS + q * 10 + j];
            }
            __syncthreads();
        }

        int gm = bm + row;
        if (gm < N_NODES) {
#pragma unroll
            for (int j = 0; j < 10; j++)
                g_xs[(size_t)gm * N_CLASS + q * 10 + j] = acc[j] + b2[q * 10 + j];
        }
        __syncthreads();
    }
#endif
}

// ---------------- CSR build ----------------
__global__ void zero_count_kernel() {
    int i = blockIdx.x * blockDim.x + threadIdx.x;
    if (i < N_NODES) g_count[i] = 0;
}

__global__ void hist_kernel(const int* __restrict__ edge_row) {
    int e = blockIdx.x * blockDim.x + threadIdx.x;
    if (e < N_EDGES) atomicAdd(&g_count[edge_row[e]], 1);
}

__global__ void scan_kernel() {
    __shared__ int warp_sums[32];
    __shared__ int carry_s;
    const int tid = threadIdx.x, lane = tid & 31, wid = tid >> 5;
    if (tid == 0) { carry_s = 0; g_rowptr[0] = 0; }
    __syncthreads();

    for (int base = 0; base < N_NODES; base += 1024) {
        int i = base + tid;
        int v = (i < N_NODES) ? g_count[i] : 0;
        int x = v;
#pragma unroll
        for (int off = 1; off < 32; off <<= 1) {
            int y = __shfl_up_sync(0xffffffffu, x, off);
            if (lane >= off) x += y;
        }
        if (lane == 31) warp_sums[wid] = x;
        __syncthreads();
        if (wid == 0) {
            int s = warp_sums[lane];
#pragma unroll
            for (int off = 1; off < 32; off <<= 1) {
                int y = __shfl_up_sync(0xffffffffu, s, off);
                if (lane >= off) s += y;
            }
            warp_sums[lane] = s;
        }
        __syncthreads();
        int incl = x + ((wid > 0) ? warp_sums[wid - 1] : 0) + carry_s;
        if (i < N_NODES) {
            g_rowptr[i + 1] = incl;
            g_cursor[i]     = incl - v;
        }
        __syncthreads();
        if (tid == 1023) carry_s = incl;
        __syncthreads();
    }
}

__global__ void scatter_kernel(const int* __restrict__ edge_row,
                               const int* __restrict__ edge_col,
                               const float* __restrict__ edge_w) {
    int e = blockIdx.x * blockDim.x + threadIdx.x;
    if (e < N_EDGES) {
        int r = edge_row[e];
        int p = atomicAdd(&g_cursor[r], 1);
        g_edge[p] = make_int2(edge_col[e], __float_as_int(edge_w[e]));
    }
}

// ---------------- SpMM hop: xs[hop] = A_sparse @ xs[hop-1] ----------------
__global__ void __launch_bounds__(320) spmm_kernel(int hop) {
    const float* __restrict__ xin  = g_xs + (size_t)(hop - 1) * N_NODES * N_CLASS;
    float* __restrict__       xout = g_xs + (size_t)hop * N_NODES * N_CLASS;

    int t    = blockIdx.x * blockDim.x + threadIdx.x;
    int row  = t / 10;
    int lane = t - row * 10;
    if (row >= N_NODES) return;

    const int s = g_rowptr[row];
    const int e = g_rowptr[row + 1];
    float4 acc = make_float4(0.f, 0.f, 0.f, 0.f);

    int i = s;
    for (; i + 4 <= e; i += 4) {
        int2 e0 = g_edge[i + 0];
        int2 e1 = g_edge[i + 1];
        int2 e2 = g_edge[i + 2];
        int2 e3 = g_edge[i + 3];
        float4 v0 = *(const float4*)(xin + (size_t)e0.x * N_CLASS + lane * 4);
        float4 v1 = *(const float4*)(xin + (size_t)e1.x * N_CLASS + lane * 4);
        float4 v2 = *(const float4*)(xin + (size_t)e2.x * N_CLASS + lane * 4);
        float4 v3 = *(const float4*)(xin + (size_t)e3.x * N_CLASS + lane * 4);
        float w0 = __int_as_float(e0.y);
        float w1 = __int_as_float(e1.y);
        float w2 = __int_as_float(e2.y);
        float w3 = __int_as_float(e3.y);
        acc.x += w0 * v0.x; acc.y += w0 * v0.y; acc.z += w0 * v0.z; acc.w += w0 * v0.w;
        acc.x += w1 * v1.x; acc.y += w1 * v1.y; acc.z += w1 * v1.z; acc.w += w1 * v1.w;
        acc.x += w2 * v2.x; acc.y += w2 * v2.y; acc.z += w2 * v2.z; acc.w += w2 * v2.w;
        acc.x += w3 * v3.x; acc.y += w3 * v3.y; acc.z += w3 * v3.z; acc.w += w3 * v3.w;
    }
    for (; i < e; i++) {
        int2  ed = g_edge[i];
        float w  = __int_as_float(ed.y);
        float4 v = *(const float4*)(xin + (size_t)ed.x * N_CLASS + lane * 4);
        acc.x += w * v.x; acc.y += w * v.y; acc.z += w * v.z; acc.w += w * v.w;
    }
    *(float4*)(xout + (size_t)row * N_CLASS + lane * 4) = acc;
}

// ---------------- attention + log_softmax ----------------
__global__ void attn_kernel(const float* __restrict__ Wa,
                            const float* __restrict__ ba,
                            float* __restrict__ out) {
    int gwarp = (blockIdx.x * blockDim.x + threadIdx.x) >> 5;
    int lane  = threadIdx.x & 31;
    if (gwarp >= N_NODES) return;
    const int n = gwarp;

    const float wa0 = Wa[lane];
    const float wa1 = (lane < 8) ? Wa[lane + 32] : 0.f;
    const float bav = ba[0];

    float acc0 = 0.f, acc1 = 0.f;
#pragma unroll
    for (int k = 0; k <= K_HOPS; k++) {
        const float* p = g_xs + ((size_t)k * N_NODES + n) * N_CLASS;
        float v0 = p[lane];
        float v1 = (lane < 8) ? p[lane + 32] : 0.f;
        float dot = v0 * wa0 + v1 * wa1;
#pragma unroll
        for (int off = 16; off > 0; off >>= 1)
            dot += __shfl_xor_sync(0xffffffffu, dot, off);
        float s = 1.f / (1.f + expf(-(dot + bav)));
        acc0 += s * v0;
        acc1 += s * v1;
    }

    float m = acc0;
    if (lane < 8) m = fmaxf(m, acc1);
#pragma unroll
    for (int off = 16; off > 0; off >>= 1)
        m = fmaxf(m, __shfl_xor_sync(0xffffffffu, m, off));

    float se = expf(acc0 - m) + ((lane < 8) ? expf(acc1 - m) : 0.f);
#pragma unroll
    for (int off = 16; off > 0; off >>= 1)
        se += __shfl_xor_sync(0xffffffffu, se, off);

    float lse = logf(se);
    out[(size_t)n * N_CLASS + lane] = acc0 - m - lse;
    if (lane < 8)
        out[(size_t)n * N_CLASS + lane + 32] = acc1 - m - lse;
}

// ---------------- launch (fork-join: CSR chain || dense chain) ----------------
static cudaStream_t g_side    = nullptr;
static cudaEvent_t  g_ev_fork = nullptr;
static cudaEvent_t  g_ev_join = nullptr;
static int          g_inited  = 0;

extern "C" void kernel_launch(void* const* d_in, const int* in_sizes, int n_in,
                              void* d_out, int out_size) {
    const float* feature  = (const float*)d_in[0];
    const int*   edge_row = (const int*)  d_in[1];
    const int*   edge_col = (const int*)  d_in[2];
    const float* edge_w   = (const float*)d_in[3];
    const float* W1       = (const float*)d_in[4];
    const float* b1       = (const float*)d_in[5];
    const float* W2       = (const float*)d_in[6];
    const float* b2       = (const float*)d_in[7];
    const float* Wa       = (const float*)d_in[8];
    const float* ba       = (const float*)d_in[9];
    float*       out      = (float*)d_out;

    if (!g_inited) {
        cudaStreamCreateWithFlags(&g_side, cudaStreamNonBlocking);
        cudaEventCreateWithFlags(&g_ev_fork, cudaEventDisableTiming);
        cudaEventCreateWithFlags(&g_ev_join, cudaEventDisableTiming);
        cudaFuncSetAttribute(gemm1_tc_kernel,
                             cudaFuncAttributeMaxDynamicSharedMemorySize, G1_SMEM_TOTAL);
        cudaFuncSetAttribute(gemm2_tc_kernel,
                             cudaFuncAttributeMaxDynamicSharedMemorySize, G2_SMEM_TOTAL);
        g_inited = 1;
    }

    const bool fork = (g_side != nullptr) && (g_ev_fork != nullptr) && (g_ev_join != nullptr);
    cudaStream_t cs = fork ? g_side : (cudaStream_t)0;

    if (fork) {
        cudaEventRecord(g_ev_fork, 0);
        cudaStreamWaitEvent(g_side, g_ev_fork, 0);
    }

    // ---- CSR chain (independent of dense path) ----
    zero_count_kernel<<<(N_NODES + 255) / 256, 256, 0, cs>>>();
    hist_kernel<<<(N_EDGES + 255) / 256, 256, 0, cs>>>(edge_row);
    scan_kernel<<<1, 1024, 0, cs>>>();
    scatter_kernel<<<(N_EDGES + 255) / 256, 256, 0, cs>>>(edge_row, edge_col, edge_w);

    if (fork) cudaEventRecord(g_ev_join, g_side);

    // ---- dense chain (legacy stream) ----
    transpose_w1_kernel<<<dim3(N_FEAT / 32, N_HID / 32), dim3(32, 8)>>>(W1);
    transpose_w2_kernel<<<(N_HID * N_CLASS + 255) / 256, 256>>>(W2);
    gemm1_tc_kernel<<<(N_NODES + 127) / 128, 256, G1_SMEM_TOTAL>>>(feature, b1);
    gemm2_tc_kernel<<<(N_NODES + 127) / 128, 256, G2_SMEM_TOTAL>>>(b2);

    // ---- join: SpMM needs both CSR and xs plane 0 ----
    if (fork) cudaStreamWaitEvent((cudaStream_t)0, g_ev_join, 0);

    for (int k = 1; k <= K_HOPS; k++)
        spmm_kernel<<<(N_NODES * 10 + 319) / 320, 320>>>(k);

    attn_kernel<<<(N_NODES * 32 + 255) / 256, 256>>>(Wa, ba, out);
}

// round 9
// speedup vs baseline: 1.1587x; 1.0099x over previous
#include <cuda_runtime.h>
#include <cuda_bf16.h>
#include <math.h>
#include <stdint.h>

#define N_NODES 100000
#define N_EDGES 3200000
#define N_FEAT  512
#define N_HID   256
#define N_CLASS 40
#define K_HOPS  10
#define SCAN_BLOCKS 98    // 98 * 1024 >= N_NODES

// tcgen05 only exists in the arch-accelerated target (sm_103a / sm_100a).
// The harness also runs a plain compute_103 ptxas pass, which rejects it.
#if defined(__CUDA_ARCH_FEAT_SM103_ALL) || defined(__CUDA_ARCH_FEAT_SM100_ALL)
#define USE_TCGEN05 1
#else
#define USE_TCGEN05 0
#endif

// ---------------- scratch (no cudaMalloc allowed) ----------------
__device__ float g_h1[(size_t)N_NODES * N_HID];                   // 102.4 MB
__device__ float g_xs[(size_t)(K_HOPS + 1) * N_NODES * N_CLASS];  // 176 MB
__device__ float g_w1t[(size_t)N_HID * N_FEAT];                   // W1^T, 512 KB
__device__ float g_w2t[(size_t)N_CLASS * N_HID];                  // W2^T, 40 KB
__device__ int   g_rowptr[N_NODES + 1];
__device__ int   g_count[N_NODES];
__device__ int   g_cursor[N_NODES];
__device__ int2  g_edge[N_EDGES];                                 // (col, w bits) interleaved
__device__ int   g_bsum[SCAN_BLOCKS];
__device__ int   g_boff[SCAN_BLOCKS];

// ================= PTX helpers =================
__device__ __forceinline__ uint32_t smem_to_u32(const void* p) {
    uint32_t a;
    asm("{ .reg .u64 t; cvta.to.shared.u64 t, %1; cvt.u32.u64 %0, t; }"
        : "=r"(a) : "l"(p));
    return a;
}

#if USE_TCGEN05
__device__ __forceinline__ uint32_t elect_one_pred() {
    uint32_t p;
    asm volatile("{\n\t.reg .pred p;\n\telect.sync _|p, 0xFFFFFFFF;\n\t"
                 "selp.b32 %0, 1, 0, p;\n\t}" : "=r"(p));
    return p;
}

#define TCGEN05_ALLOC(smem_addr, nCols) \
    asm volatile("tcgen05.alloc.cta_group::1.sync.aligned.shared::cta.b32 [%0], %1;" \
                 :: "r"((uint32_t)(smem_addr)), "r"((uint32_t)(nCols)) : "memory")
#define TCGEN05_DEALLOC(tmem, nCols) \
    asm volatile("tcgen05.dealloc.cta_group::1.sync.aligned.b32 %0, %1;" \
                 :: "r"(tmem), "r"((uint32_t)(nCols)))
#define TCGEN05_RELINQUISH() \
    asm volatile("tcgen05.relinquish_alloc_permit.cta_group::1.sync.aligned;")
#define TCGEN05_COMMIT(mbar) \
    asm volatile("tcgen05.commit.cta_group::1.mbarrier::arrive::one.shared::cluster.b64 [%0];" \
                 :: "r"((uint32_t)(mbar)) : "memory")
#define TCGEN05_WAIT_LD() \
    asm volatile("tcgen05.wait::ld.sync.aligned;" ::: "memory")
#define TCGEN05_FENCE_AFTER() \
    asm volatile("tcgen05.fence::after_thread_sync;" ::: "memory")
#define TCGEN05_FENCE_BEFORE() \
    asm volatile("tcgen05.fence::before_thread_sync;" ::: "memory")
#define MBARRIER_INIT(mbar, cnt) \
    asm volatile("mbarrier.init.shared.b64 [%0], %1;" \
                 :: "r"((uint32_t)(mbar)), "r"((uint32_t)(cnt)) : "memory")
#define MBARRIER_INVAL(mbar) \
    asm volatile("mbarrier.inval.shared.b64 [%0];" :: "r"((uint32_t)(mbar)) : "memory")
#define FENCE_PROXY_ASYNC() \
    asm volatile("fence.proxy.async.shared::cta;" ::: "memory")

#define MBARRIER_WAIT_PARITY(mbar, parity) do { \
    uint32_t _m = (uint32_t)(mbar); \
    uint32_t _p = (uint32_t)(parity); \
    uint32_t _done; \
    asm volatile("{\n\t.reg .pred p;\n\t" \
        "mbarrier.try_wait.parity.acquire.cta.shared::cta.b64 p, [%1], %2;\n\t" \
        "selp.b32 %0, 1, 0, p;\n\t}" : "=r"(_done) : "r"(_m), "r"(_p) : "memory"); \
    if (!_done) { \
        asm volatile("{\n\t.reg .pred P1;\n\t" \
            "WL_%=:\n\t" \
            "mbarrier.try_wait.parity.acquire.cta.shared::cta.b64 P1, [%0], %1, 0x989680;\n\t" \
            "@P1 bra.uni WD_%=;\n\t" \
            "bra.uni WL_%=;\n\t" \
            "WD_%=:\n\t}" :: "r"(_m), "r"(_p) : "memory"); \
    } \
} while (0)

#define TCGEN05_LD_32X32B_X32(r, tmem_addr) \
    asm volatile( \
        "tcgen05.ld.sync.aligned.32x32b.x32.b32 " \
        "{%0, %1, %2, %3, %4, %5, %6, %7, " \
        " %8, %9, %10, %11, %12, %13, %14, %15, " \
        " %16, %17, %18, %19, %20, %21, %22, %23, " \
        " %24, %25, %26, %27, %28, %29, %30, %31}, [%32];" \
        : "=r"((r)[0]),  "=r"((r)[1]),  "=r"((r)[2]),  "=r"((r)[3]), \
          "=r"((r)[4]),  "=r"((r)[5]),  "=r"((r)[6]),  "=r"((r)[7]), \
          "=r"((r)[8]),  "=r"((r)[9]),  "=r"((r)[10]), "=r"((r)[11]), \
          "=r"((r)[12]), "=r"((r)[13]), "=r"((r)[14]), "=r"((r)[15]), \
          "=r"((r)[16]), "=r"((r)[17]), "=r"((r)[18]), "=r"((r)[19]), \
          "=r"((r)[20]), "=r"((r)[21]), "=r"((r)[22]), "=r"((r)[23]), \
          "=r"((r)[24]), "=r"((r)[25]), "=r"((r)[26]), "=r"((r)[27]), \
          "=r"((r)[28]), "=r"((r)[29]), "=r"((r)[30]), "=r"((r)[31]) \
        : "r"(tmem_addr))

#define TCGEN05_LD_32X32B_X8(r, tmem_addr) \
    asm volatile( \
        "tcgen05.ld.sync.aligned.32x32b.x8.b32 " \
        "{%0, %1, %2, %3, %4, %5, %6, %7}, [%8];" \
        : "=r"((r)[0]), "=r"((r)[1]), "=r"((r)[2]), "=r"((r)[3]), \
          "=r"((r)[4]), "=r"((r)[5]), "=r"((r)[6]), "=r"((r)[7]) \
        : "r"(tmem_addr))

// SW128 K-major descriptor: layout=2 (SW128), version=1, SBO=64, LBO=1
static constexpr uint64_t SMEM_DESC_BASE_SW128 =
    (uint64_t(2) << 61) | (uint64_t(1) << 46) | (uint64_t(64) << 32) | (uint64_t(1) << 16);
#define MAKE_SMEM_DESC(base_addr) \
    (SMEM_DESC_BASE_SW128 | ((uint64_t)((base_addr) >> 4) & 0x3FFF))

// tf32 SS MMA idesc: c=F32 (1<<4), a=TF32 (2<<7), b=TF32 (2<<10),
// N/8 at bits[17:23), M/16 at bits[24:29)
static constexpr uint32_t IDESC_TF32_N256 =
    (1u << 4) | (2u << 7) | (2u << 10) | ((256u / 8u) << 17) | ((128u / 16u) << 24);
static constexpr uint32_t IDESC_TF32_N64 =
    (1u << 4) | (2u << 7) | (2u << 10) | ((64u / 8u) << 17) | ((128u / 16u) << 24);

__device__ __forceinline__ void mma_tf32_ss(uint32_t d, uint64_t ad, uint64_t bd,
                                            uint32_t idesc, bool acc) {
    uint32_t en = acc ? 1u : 0u;
    asm volatile(
        "{\n\t.reg .pred p;\n\tsetp.ne.u32 p, %5, 0;\n\t"
        "tcgen05.mma.cta_group::1.kind::tf32 [%0], %1, %2, %3, {%4, %4, %4, %4}, p;\n\t}"
        :: "r"(d), "l"(ad), "l"(bd), "r"(idesc), "r"(0u), "r"(en)
        : "memory");
}

__device__ __forceinline__ float to_tf32(float x) {
    uint32_t r;
    asm("cvt.rna.tf32.f32 %0, %1;" : "=r"(r) : "f"(x));
    return __uint_as_float(r);
}
#endif  // USE_TCGEN05

#define SMEM_SWIZZLE_128B(off) ((off) ^ (((off) >> 3) & 0x70))

// ---------------- W1 transpose: g_w1t[n][k] = W1[k][n] ----------------
__global__ void transpose_w1_kernel(const float* __restrict__ W1) {
    __shared__ float t[32][33];
    int bk = blockIdx.x * 32;
    int bn = blockIdx.y * 32;
    int x = threadIdx.x, y = threadIdx.y;
#pragma unroll
    for (int i = 0; i < 32; i += 8)
        t[y + i][x] = W1[(size_t)(bk + y + i) * N_HID + bn + x];
    __syncthreads();
#pragma unroll
    for (int i = 0; i < 32; i += 8)
        g_w1t[(size_t)(bn + y + i) * N_FEAT + bk + x] = t[x][y + i];
}

// ---------------- W2 transpose: g_w2t[n][k] = W2[k][n] (tiny) ----------------
__global__ void transpose_w2_kernel(const float* __restrict__ W2) {
    int i = blockIdx.x * blockDim.x + threadIdx.x;
    if (i < N_HID * N_CLASS) {
        int k = i / N_CLASS;
        int n = i - k * N_CLASS;
        g_w2t[(size_t)n * N_HID + k] = W2[i];
    }
}

// ---------------- GEMM1: relu(feature @ W1 + b1) -> g_h1 ----------------
#define G1_CHUNK_K   32
#define G1_NCHUNKS   (N_FEAT / G1_CHUNK_K)      // 16
#define G1_A_BYTES   (128 * 128)
#define G1_B_BYTES   (256 * 128)
#define G1_OFF_A0    1024
#define G1_OFF_A1    (G1_OFF_A0 + G1_A_BYTES)
#define G1_OFF_B0    (G1_OFF_A1 + G1_A_BYTES)
#define G1_OFF_B1    (G1_OFF_B0 + G1_B_BYTES)
#define G1_SMEM_TOTAL (G1_OFF_B1 + G1_B_BYTES)   // 99328

__global__ void __launch_bounds__(256) gemm1_tc_kernel(const float* __restrict__ A,
                                                       const float* __restrict__ bias) {
    extern __shared__ char smem[];
#if USE_TCGEN05
    const uint32_t sb = smem_to_u32(smem);
    const int tid  = threadIdx.x;
    const int wid  = tid >> 5;
    const int lane = tid & 31;
    const int bm   = blockIdx.x * 128;

    if (wid == 4) TCGEN05_ALLOC(sb + 0, 256);
    if (tid == 0) { MBARRIER_INIT(sb + 8, 1); MBARRIER_INIT(sb + 16, 1); }
    __syncthreads();
    uint32_t tmem;
    asm volatile("ld.shared.b32 %0, [%1];" : "=r"(tmem) : "r"(sb + 0));

    const uint32_t aoff[2] = {G1_OFF_A0, G1_OFF_A1};
    const uint32_t boff[2] = {G1_OFF_B0, G1_OFF_B1};

    for (int c = 0; c < G1_NCHUNKS; c++) {
        const int buf = c & 1;
        if (c >= 2) MBARRIER_WAIT_PARITY(sb + 8 + 8 * buf, ((c - 2) >> 1) & 1);

#pragma unroll
        for (int r = 0; r < 4; r++) {
            int i   = tid + r * 256;
            int row = i >> 3;
            int f4  = i & 7;
            int gm  = bm + row;
            float4 v = make_float4(0.f, 0.f, 0.f, 0.f);
            if (gm < N_NODES)
                v = *(const float4*)(A + (size_t)gm * N_FEAT + c * G1_CHUNK_K + f4 * 4);
            v.x = to_tf32(v.x); v.y = to_tf32(v.y); v.z = to_tf32(v.z); v.w = to_tf32(v.w);
            uint32_t off = SMEM_SWIZZLE_128B((uint32_t)(row * 128 + f4 * 16));
            *(float4*)(smem + aoff[buf] + off) = v;
        }
#pragma unroll
        for (int r = 0; r < 8; r++) {
            int i  = tid + r * 256;
            int n  = i >> 3;
            int f4 = i & 7;
            float4 v = *(const float4*)(g_w1t + (size_t)n * N_FEAT + c * G1_CHUNK_K + f4 * 4);
            v.x = to_tf32(v.x); v.y = to_tf32(v.y); v.z = to_tf32(v.z); v.w = to_tf32(v.w);
            uint32_t off = SMEM_SWIZZLE_128B((uint32_t)(n * 128 + f4 * 16));
            *(float4*)(smem + boff[buf] + off) = v;
        }
        FENCE_PROXY_ASYNC();
        __syncthreads();

        if (wid == 4) {
            if (elect_one_pred()) {
                uint64_t ad = MAKE_SMEM_DESC(sb + aoff[buf]);
                uint64_t bd = MAKE_SMEM_DESC(sb + boff[buf]);
#pragma unroll
                for (int ks = 0; ks < 4; ks++)
                    mma_tf32_ss(tmem, ad + ks * 2, bd + ks * 2, IDESC_TF32_N256,
                                (c > 0) || (ks > 0));
                TCGEN05_COMMIT(sb + 8 + 8 * buf);
            }
        }
    }

    MBARRIER_WAIT_PARITY(sb + 8, 1);
    MBARRIER_WAIT_PARITY(sb + 16, 1);
    TCGEN05_FENCE_AFTER();

    if (wid < 4) {
        const int m = bm + wid * 32 + lane;
#pragma unroll
        for (int b = 0; b < 4; b++) {
            uint32_t r[64];
            TCGEN05_LD_32X32B_X32(r, tmem + b * 64);
            TCGEN05_LD_32X32B_X32(r + 32, tmem + b * 64 + 32);
            TCGEN05_WAIT_LD();
            if (m < N_NODES) {
                float* outp = g_h1 + (size_t)m * N_HID + b * 64;
#pragma unroll
                for (int j = 0; j < 64; j += 4) {
                    float4 o;
                    o.x = fmaxf(__uint_as_float(r[j + 0]) + bias[b * 64 + j + 0], 0.f);
                    o.y = fmaxf(__uint_as_float(r[j + 1]) + bias[b * 64 + j + 1], 0.f);
                    o.z = fmaxf(__uint_as_float(r[j + 2]) + bias[b * 64 + j + 2], 0.f);
                    o.w = fmaxf(__uint_as_float(r[j + 3]) + bias[b * 64 + j + 3], 0.f);
                    *(float4*)(outp + j) = o;
                }
            }
        }
        TCGEN05_FENCE_BEFORE();
    }
    __syncthreads();
    if (tid == 0) { MBARRIER_INVAL(sb + 8); MBARRIER_INVAL(sb + 16); }
    __syncthreads();
    if (wid == 4) { TCGEN05_RELINQUISH(); TCGEN05_DEALLOC(tmem, 256); }

#else  // ---------- SIMT fallback (plain sm_103 JIT path) ----------
    float (*As)[132] = (float(*)[132])smem;
    float (*Bs)[68]  = (float(*)[68])(smem + 16 * 132 * sizeof(float));

    const int tid  = threadIdx.x;
    const int bm   = blockIdx.x * 128;
    const int mIdx = tid >> 4;
    const int nIdx = tid & 15;

    for (int nb = 0; nb < 4; nb++) {
        const int bn = nb * 64;
        float acc[8][4];
#pragma unroll
        for (int i = 0; i < 8; i++)
#pragma unroll
            for (int j = 0; j < 4; j++) acc[i][j] = 0.f;

        for (int kt = 0; kt < N_FEAT; kt += 16) {
#pragma unroll
            for (int r = 0; r < 2; r++) {
                int i  = tid + r * 256;
                int m  = i >> 2;
                int k4 = (i & 3) * 4;
                int gm = bm + m;
                float4 v = make_float4(0.f, 0.f, 0.f, 0.f);
                if (gm < N_NODES)
                    v = *(const float4*)(A + (size_t)gm * N_FEAT + kt + k4);
                As[k4 + 0][m] = v.x;
                As[k4 + 1][m] = v.y;
                As[k4 + 2][m] = v.z;
                As[k4 + 3][m] = v.w;
            }
            {
                int n  = tid >> 2;
                int k4 = (tid & 3) * 4;
                float4 v = *(const float4*)(g_w1t + (size_t)(bn + n) * N_FEAT + kt + k4);
                Bs[k4 + 0][n] = v.x;
                Bs[k4 + 1][n] = v.y;
                Bs[k4 + 2][n] = v.z;
                Bs[k4 + 3][n] = v.w;
            }
            __syncthreads();

#pragma unroll
            for (int k = 0; k < 16; k++) {
                float ra[8], rb[4];
#pragma unroll
                for (int i = 0; i < 8; i++) ra[i] = As[k][mIdx * 8 + i];
#pragma unroll
                for (int j = 0; j < 4; j++) rb[j] = Bs[k][nIdx * 4 + j];
#pragma unroll
                for (int i = 0; i < 8; i++)
#pragma unroll
                    for (int j = 0; j < 4; j++) acc[i][j] += ra[i] * rb[j];
            }
            __syncthreads();
        }

#pragma unroll
        for (int i = 0; i < 8; i++) {
            int gm = bm + mIdx * 8 + i;
            if (gm < N_NODES) {
#pragma unroll
                for (int j = 0; j < 4; j++) {
                    int gn = bn + nIdx * 4 + j;
                    float v = acc[i][j] + bias[gn];
                    g_h1[(size_t)gm * N_HID + gn] = fmaxf(v, 0.f);
                }
            }
        }
    }
#endif
}

// ---------------- GEMM2 (tcgen05 tf32): g_h1 @ W2 + b2 -> g_xs plane 0 ------
#define G2_CHUNK_K   32
#define G2_NCHUNKS   (N_HID / G2_CHUNK_K)        // 8
#define G2_A_BYTES   (128 * 128)
#define G2_BCH_BYTES (64 * 128)
#define G2_OFF_A0    1024
#define G2_OFF_A1    (G2_OFF_A0 + G2_A_BYTES)
#define G2_OFF_B     (G2_OFF_A1 + G2_A_BYTES)
#define G2_SMEM_TOTAL (G2_OFF_B + G2_NCHUNKS * G2_BCH_BYTES)  // 99328

__global__ void __launch_bounds__(256) gemm2_tc_kernel(const float* __restrict__ b2) {
    extern __shared__ char smem[];
#if USE_TCGEN05
    const uint32_t sb = smem_to_u32(smem);
    const int tid  = threadIdx.x;
    const int wid  = tid >> 5;
    const int lane = tid & 31;
    const int bm   = blockIdx.x * 128;

    if (wid == 4) TCGEN05_ALLOC(sb + 0, 64);
    if (tid == 0) { MBARRIER_INIT(sb + 8, 1); MBARRIER_INIT(sb + 16, 1); }
    __syncthreads();
    uint32_t tmem;
    asm volatile("ld.shared.b32 %0, [%1];" : "=r"(tmem) : "r"(sb + 0));

    for (int i = tid; i < (G2_NCHUNKS * G2_BCH_BYTES) / 16; i += 256)
        *(float4*)(smem + G2_OFF_B + i * 16) = make_float4(0.f, 0.f, 0.f, 0.f);
    __syncthreads();
    for (int i = tid; i < G2_NCHUNKS * N_CLASS * 8; i += 256) {
        int ch  = i / (N_CLASS * 8);
        int rem = i - ch * (N_CLASS * 8);
        int n   = rem >> 3;
        int f4  = rem & 7;
        float4 v = *(const float4*)(g_w2t + (size_t)n * N_HID + ch * G2_CHUNK_K + f4 * 4);
        v.x = to_tf32(v.x); v.y = to_tf32(v.y); v.z = to_tf32(v.z); v.w = to_tf32(v.w);
        uint32_t off = SMEM_SWIZZLE_128B((uint32_t)(n * 128 + f4 * 16));
        *(float4*)(smem + G2_OFF_B + ch * G2_BCH_BYTES + off) = v;
    }

    const uint32_t aoff[2] = {G2_OFF_A0, G2_OFF_A1};

    for (int c = 0; c < G2_NCHUNKS; c++) {
        const int buf = c & 1;
        if (c >= 2) MBARRIER_WAIT_PARITY(sb + 8 + 8 * buf, ((c - 2) >> 1) & 1);

#pragma unroll
        for (int r = 0; r < 4; r++) {
            int i   = tid + r * 256;
            int row = i >> 3;
            int f4  = i & 7;
            int gm  = bm + row;
            float4 v = make_float4(0.f, 0.f, 0.f, 0.f);
            if (gm < N_NODES)
                v = *(const float4*)(g_h1 + (size_t)gm * N_HID + c * G2_CHUNK_K + f4 * 4);
            v.x = to_tf32(v.x); v.y = to_tf32(v.y); v.z = to_tf32(v.z); v.w = to_tf32(v.w);
            uint32_t off = SMEM_SWIZZLE_128B((uint32_t)(row * 128 + f4 * 16));
            *(float4*)(smem + aoff[buf] + off) = v;
        }
        FENCE_PROXY_ASYNC();
        __syncthreads();

        if (wid == 4) {
            if (elect_one_pred()) {
                uint64_t ad = MAKE_SMEM_DESC(sb + aoff[buf]);
                uint64_t bd = MAKE_SMEM_DESC(sb + G2_OFF_B + c * G2_BCH_BYTES);
#pragma unroll
                for (int ks = 0; ks < 4; ks++)
                    mma_tf32_ss(tmem, ad + ks * 2, bd + ks * 2, IDESC_TF32_N64,
                                (c > 0) || (ks > 0));
                TCGEN05_COMMIT(sb + 8 + 8 * buf);
            }
        }
    }

    MBARRIER_WAIT_PARITY(sb + 8, 1);
    MBARRIER_WAIT_PARITY(sb + 16, 1);
    TCGEN05_FENCE_AFTER();

    if (wid < 4) {
        const int m = bm + wid * 32 + lane;
        uint32_t r[40];
        TCGEN05_LD_32X32B_X32(r, tmem);
        TCGEN05_LD_32X32B_X8(r + 32, tmem + 32);
        TCGEN05_WAIT_LD();
        if (m < N_NODES) {
            float* outp = g_xs + (size_t)m * N_CLASS;
#pragma unroll
            for (int j = 0; j < 40; j += 4) {
                float4 o;
                o.x = __uint_as_float(r[j + 0]) + b2[j + 0];
                o.y = __uint_as_float(r[j + 1]) + b2[j + 1];
                o.z = __uint_as_float(r[j + 2]) + b2[j + 2];
                o.w = __uint_as_float(r[j + 3]) + b2[j + 3];
                *(float4*)(outp + j) = o;
            }
        }
        TCGEN05_FENCE_BEFORE();
    }
    __syncthreads();
    if (tid == 0) { MBARRIER_INVAL(sb + 8); MBARRIER_INVAL(sb + 16); }
    __syncthreads();
    if (wid == 4) { TCGEN05_RELINQUISH(); TCGEN05_DEALLOC(tmem, 64); }

#else  // ---------- SIMT fallback ----------
    float (*As)[65] = (float(*)[65])smem;
    float* W2s = (float*)(smem + 64 * 65 * sizeof(float));

    const int tid = threadIdx.x;
    for (int half = 0; half < 2; half++) {
        const int bm  = blockIdx.x * 128 + half * 64;
        const int row = tid >> 2;
        const int q   = tid & 3;

        float acc[10];
#pragma unroll
        for (int j = 0; j < 10; j++) acc[j] = 0.f;

        for (int kb = 0; kb < N_HID; kb += 64) {
#pragma unroll
            for (int r = 0; r < 4; r++) {
                int i  = tid + r * 256;
                int rr = i >> 4;
                int c4 = (i & 15) * 4;
                int gm = bm + rr;
                float4 v = make_float4(0.f, 0.f, 0.f, 0.f);
                if (gm < N_NODES)
                    v = *(const float4*)(g_h1 + (size_t)gm * N_HID + kb + c4);
                As[rr][c4 + 0] = v.x;
                As[rr][c4 + 1] = v.y;
                As[rr][c4 + 2] = v.z;
                As[rr][c4 + 3] = v.w;
            }
#pragma unroll
            for (int r = 0; r < 10; r++) {
                int e = tid + r * 256;
                int k = e / N_CLASS;
                int n = e - k * N_CLASS;
                W2s[e] = g_w2t[(size_t)n * N_HID + kb + k];
            }
            __syncthreads();

#pragma unroll 4
            for (int k = 0; k < 64; k++) {
                float a = As[row][k];
#pragma unroll
                for (int j = 0; j < 10; j++)
                    acc[j] += a * W2s[k * N_CLASS + q * 10 + j];
            }
            __syncthreads();
        }

        int gm = bm + row;
        if (gm < N_NODES) {
#pragma unroll
            for (int j = 0; j < 10; j++)
                g_xs[(size_t)gm * N_CLASS + q * 10 + j] = acc[j] + b2[q * 10 + j];
        }
        __syncthreads();
    }
#endif
}

// ---------------- CSR build ----------------
__global__ void zero_count_kernel() {
    int i = blockIdx.x * blockDim.x + threadIdx.x;
    if (i < N_NODES) g_count[i] = 0;
}

__global__ void hist_kernel(const int* __restrict__ edge_row) {
    int e = blockIdx.x * blockDim.x + threadIdx.x;
    if (e < N_EDGES) atomicAdd(&g_count[edge_row[e]], 1);
}

// multi-block scan, phase 1: per-block exclusive scan + block totals
__global__ void __launch_bounds__(1024) scan1_kernel() {
    __shared__ int warp_sums[32];
    const int tid = threadIdx.x, lane = tid & 31, wid = tid >> 5;
    const int i = blockIdx.x * 1024 + tid;

    int v = (i < N_NODES) ? g_count[i] : 0;
    int x = v;
#pragma unroll
    for (int off = 1; off < 32; off <<= 1) {
        int y = __shfl_up_sync(0xffffffffu, x, off);
        if (lane >= off) x += y;
    }
    if (lane == 31) warp_sums[wid] = x;
    __syncthreads();
    if (wid == 0) {
        int s = warp_sums[lane];
#pragma unroll
        for (int off = 1; off < 32; off <<= 1) {
            int y = __shfl_up_sync(0xffffffffu, s, off);
            if (lane >= off) s += y;
        }
        warp_sums[lane] = s;
    }
    __syncthreads();
    int incl = x + ((wid > 0) ? warp_sums[wid - 1] : 0);
    if (i < N_NODES) g_cursor[i] = incl - v;      // within-block exclusive
    if (tid == 1023) g_bsum[blockIdx.x] = incl;   // block total
}

// phase 2: scan 98 block sums (1 block, 128 threads)
__global__ void scan2_kernel() {
    __shared__ int ws[4];
    const int tid = threadIdx.x, lane = tid & 31, wid = tid >> 5;
    int v = (tid < SCAN_BLOCKS) ? g_bsum[tid] : 0;
    int x = v;
#pragma unroll
    for (int off = 1; off < 32; off <<= 1) {
        int y = __shfl_up_sync(0xffffffffu, x, off);
        if (lane >= off) x += y;
    }
    if (lane == 31) ws[wid] = x;
    __syncthreads();
    if (wid == 0 && lane < 4) {
        int s = ws[lane];
#pragma unroll
        for (int off = 1; off < 4; off <<= 1) {
            int y = __shfl_up_sync(0xfu, s, off);
            if (lane >= off) s += y;
        }
        ws[lane] = s;
    }
    __syncthreads();
    int excl = x - v + ((wid > 0) ? ws[wid - 1] : 0);
    if (tid < SCAN_BLOCKS) g_boff[tid] = excl;
}

// phase 3: apply block offsets, finalize rowptr + cursor
__global__ void scan3_kernel() {
    int i = blockIdx.x * blockDim.x + threadIdx.x;
    if (i < N_NODES) {
        int excl = g_cursor[i] + g_boff[i >> 10];
        g_cursor[i]     = excl;
        g_rowptr[i + 1] = excl + g_count[i];
        if (i == 0) g_rowptr[0] = 0;
    }
}

__global__ void scatter_kernel(const int* __restrict__ edge_row,
                               const int* __restrict__ edge_col,
                               const float* __restrict__ edge_w) {
    int e = blockIdx.x * blockDim.x + threadIdx.x;
    if (e < N_EDGES) {
        int r = edge_row[e];
        int p = atomicAdd(&g_cursor[r], 1);
        g_edge[p] = make_int2(edge_col[e], __float_as_int(edge_w[e]));
    }
}

// ---------------- SpMM hop: xs[hop] = A_sparse @ xs[hop-1] ----------------
__global__ void __launch_bounds__(320) spmm_kernel(int hop) {
    const float* __restrict__ xin  = g_xs + (size_t)(hop - 1) * N_NODES * N_CLASS;
    float* __restrict__       xout = g_xs + (size_t)hop * N_NODES * N_CLASS;

    int t    = blockIdx.x * blockDim.x + threadIdx.x;
    int row  = t / 10;
    int lane = t - row * 10;
    if (row >= N_NODES) return;

    const int s = g_rowptr[row];
    const int e = g_rowptr[row + 1];
    float4 acc = make_float4(0.f, 0.f, 0.f, 0.f);

    int i = s;
    for (; i + 4 <= e; i += 4) {
        int2 e0 = g_edge[i + 0];
        int2 e1 = g_edge[i + 1];
        int2 e2 = g_edge[i + 2];
        int2 e3 = g_edge[i + 3];
        float4 v0 = *(const float4*)(xin + (size_t)e0.x * N_CLASS + lane * 4);
        float4 v1 = *(const float4*)(xin + (size_t)e1.x * N_CLASS + lane * 4);
        float4 v2 = *(const float4*)(xin + (size_t)e2.x * N_CLASS + lane * 4);
        float4 v3 = *(const float4*)(xin + (size_t)e3.x * N_CLASS + lane * 4);
        float w0 = __int_as_float(e0.y);
        float w1 = __int_as_float(e1.y);
        float w2 = __int_as_float(e2.y);
        float w3 = __int_as_float(e3.y);
        acc.x += w0 * v0.x; acc.y += w0 * v0.y; acc.z += w0 * v0.z; acc.w += w0 * v0.w;
        acc.x += w1 * v1.x; acc.y += w1 * v1.y; acc.z += w1 * v1.z; acc.w += w1 * v1.w;
        acc.x += w2 * v2.x; acc.y += w2 * v2.y; acc.z += w2 * v2.z; acc.w += w2 * v2.w;
        acc.x += w3 * v3.x; acc.y += w3 * v3.y; acc.z += w3 * v3.z; acc.w += w3 * v3.w;
    }
    for (; i < e; i++) {
        int2  ed = g_edge[i];
        float w  = __int_as_float(ed.y);
        float4 v = *(const float4*)(xin + (size_t)ed.x * N_CLASS + lane * 4);
        acc.x += w * v.x; acc.y += w * v.y; acc.z += w * v.z; acc.w += w * v.w;
    }
    *(float4*)(xout + (size_t)row * N_CLASS + lane * 4) = acc;
}

// ---------------- attention + log_softmax ----------------
__global__ void attn_kernel(const float* __restrict__ Wa,
                            const float* __restrict__ ba,
                            float* __restrict__ out) {
    int gwarp = (blockIdx.x * blockDim.x + threadIdx.x) >> 5;
    int lane  = threadIdx.x & 31;
    if (gwarp >= N_NODES) return;
    const int n = gwarp;

    const float wa0 = Wa[lane];
    const float wa1 = (lane < 8) ? Wa[lane + 32] : 0.f;
    const float bav = ba[0];

    // batch all 11 plane loads so the gathers overlap (MLP=22)
    float v0[K_HOPS + 1], v1[K_HOPS + 1];
#pragma unroll
    for (int k = 0; k <= K_HOPS; k++) {
        const float* p = g_xs + ((size_t)k * N_NODES + n) * N_CLASS;
        v0[k] = p[lane];
        v1[k] = (lane < 8) ? p[lane + 32] : 0.f;
    }

    float acc0 = 0.f, acc1 = 0.f;
#pragma unroll
    for (int k = 0; k <= K_HOPS; k++) {
        float dot = v0[k] * wa0 + v1[k] * wa1;
#pragma unroll
        for (int off = 16; off > 0; off >>= 1)
            dot += __shfl_xor_sync(0xffffffffu, dot, off);
        float s = 1.f / (1.f + expf(-(dot + bav)));
        acc0 += s * v0[k];
        acc1 += s * v1[k];
    }

    float m = acc0;
    if (lane < 8) m = fmaxf(m, acc1);
#pragma unroll
    for (int off = 16; off > 0; off >>= 1)
        m = fmaxf(m, __shfl_xor_sync(0xffffffffu, m, off));

    float se = expf(acc0 - m) + ((lane < 8) ? expf(acc1 - m) : 0.f);
#pragma unroll
    for (int off = 16; off > 0; off >>= 1)
        se += __shfl_xor_sync(0xffffffffu, se, off);

    float lse = logf(se);
    out[(size_t)n * N_CLASS + lane] = acc0 - m - lse;
    if (lane < 8)
        out[(size_t)n * N_CLASS + lane + 32] = acc1 - m - lse;
}

// ---------------- launch (fork-join: CSR chain || dense chain) ----------------
static cudaStream_t g_side    = nullptr;
static cudaEvent_t  g_ev_fork = nullptr;
static cudaEvent_t  g_ev_join = nullptr;
static int          g_inited  = 0;

extern "C" void kernel_launch(void* const* d_in, const int* in_sizes, int n_in,
                              void* d_out, int out_size) {
    const float* feature  = (const float*)d_in[0];
    const int*   edge_row = (const int*)  d_in[1];
    const int*   edge_col = (const int*)  d_in[2];
    const float* edge_w   = (const float*)d_in[3];
    const float* W1       = (const float*)d_in[4];
    const float* b1       = (const float*)d_in[5];
    const float* W2       = (const float*)d_in[6];
    const float* b2       = (const float*)d_in[7];
    const float* Wa       = (const float*)d_in[8];
    const float* ba       = (const float*)d_in[9];
    float*       out      = (float*)d_out;

    if (!g_inited) {
        cudaStreamCreateWithFlags(&g_side, cudaStreamNonBlocking);
        cudaEventCreateWithFlags(&g_ev_fork, cudaEventDisableTiming);
        cudaEventCreateWithFlags(&g_ev_join, cudaEventDisableTiming);
        cudaFuncSetAttribute(gemm1_tc_kernel,
                             cudaFuncAttributeMaxDynamicSharedMemorySize, G1_SMEM_TOTAL);
        cudaFuncSetAttribute(gemm2_tc_kernel,
                             cudaFuncAttributeMaxDynamicSharedMemorySize, G2_SMEM_TOTAL);
        g_inited = 1;
    }

    const bool fork = (g_side != nullptr) && (g_ev_fork != nullptr) && (g_ev_join != nullptr);
    cudaStream_t cs = fork ? g_side : (cudaStream_t)0;

    if (fork) {
        cudaEventRecord(g_ev_fork, 0);
        cudaStreamWaitEvent(g_side, g_ev_fork, 0);
    }

    // ---- CSR chain (independent of dense path) ----
    zero_count_kernel<<<(N_NODES + 255) / 256, 256, 0, cs>>>();
    hist_kernel<<<(N_EDGES + 255) / 256, 256, 0, cs>>>(edge_row);
    scan1_kernel<<<SCAN_BLOCKS, 1024, 0, cs>>>();
    scan2_kernel<<<1, 128, 0, cs>>>();
    scan3_kernel<<<(N_NODES + 255) / 256, 256, 0, cs>>>();
    scatter_kernel<<<(N_EDGES + 255) / 256, 256, 0, cs>>>(edge_row, edge_col, edge_w);

    if (fork) cudaEventRecord(g_ev_join, g_side);

    // ---- dense chain (legacy stream) ----
    transpose_w1_kernel<<<dim3(N_FEAT / 32, N_HID / 32), dim3(32, 8)>>>(W1);
    transpose_w2_kernel<<<(N_HID * N_CLASS + 255) / 256, 256>>>(W2);
    gemm1_tc_kernel<<<(N_NODES + 127) / 128, 256, G1_SMEM_TOTAL>>>(feature, b1);
    gemm2_tc_kernel<<<(N_NODES + 127) / 128, 256, G2_SMEM_TOTAL>>>(b2);

    // ---- join: SpMM needs both CSR and xs plane 0 ----
    if (fork) cudaStreamWaitEvent((cudaStream_t)0, g_ev_join, 0);

    for (int k = 1; k <= K_HOPS; k++)
        spmm_kernel<<<(N_NODES * 10 + 319) / 320, 320>>>(k);

    attn_kernel<<<(N_NODES * 32 + 255) / 256, 256>>>(Wa, ba, out);
}

// round 10
// speedup vs baseline: 1.2530x; 1.0814x over previous
#include <cuda_runtime.h>
#include <cuda_bf16.h>
#include <math.h>
#include <stdint.h>

#define N_NODES 100000
#define N_EDGES 3200000
#define N_FEAT  512
#define N_HID   256
#define N_CLASS 40
#define K_HOPS  10
#define SCAN_BLOCKS 98    // 98 * 1024 >= N_NODES
#define SPMM_CAP 48       // staged edges per row (deg>48 spills to gmem)
#define SPMM_PAD 49       // +1 int2 to stagger smem banks

// tcgen05 only exists in the arch-accelerated target (sm_103a / sm_100a).
// The harness also runs a plain compute_103 ptxas pass, which rejects it.
#if defined(__CUDA_ARCH_FEAT_SM103_ALL) || defined(__CUDA_ARCH_FEAT_SM100_ALL)
#define USE_TCGEN05 1
#else
#define USE_TCGEN05 0
#endif

// ---------------- scratch (no cudaMalloc allowed) ----------------
__device__ float g_h1[(size_t)N_NODES * N_HID];                   // 102.4 MB
__device__ float g_xs[(size_t)(K_HOPS + 1) * N_NODES * N_CLASS];  // 176 MB
__device__ float g_w1t[(size_t)N_HID * N_FEAT];                   // W1^T, 512 KB
__device__ float g_w2t[(size_t)N_CLASS * N_HID];                  // W2^T, 40 KB
__device__ int   g_rowptr[N_NODES + 1];
__device__ int   g_count[N_NODES];
__device__ int   g_cursor[N_NODES];
__device__ int2  g_edge[N_EDGES];                                 // (col, w bits) interleaved
__device__ int   g_bsum[SCAN_BLOCKS];
__device__ int   g_boff[SCAN_BLOCKS];

// ================= PTX helpers =================
__device__ __forceinline__ uint32_t smem_to_u32(const void* p) {
    uint32_t a;
    asm("{ .reg .u64 t; cvta.to.shared.u64 t, %1; cvt.u32.u64 %0, t; }"
        : "=r"(a) : "l"(p));
    return a;
}

#define GRIDDEP_WAIT() asm volatile("griddepcontrol.wait;" ::: "memory")
#define GRIDDEP_LAUNCH() asm volatile("griddepcontrol.launch_dependents;")

#if USE_TCGEN05
__device__ __forceinline__ uint32_t elect_one_pred() {
    uint32_t p;
    asm volatile("{\n\t.reg .pred p;\n\telect.sync _|p, 0xFFFFFFFF;\n\t"
                 "selp.b32 %0, 1, 0, p;\n\t}" : "=r"(p));
    return p;
}

#define TCGEN05_ALLOC(smem_addr, nCols) \
    asm volatile("tcgen05.alloc.cta_group::1.sync.aligned.shared::cta.b32 [%0], %1;" \
                 :: "r"((uint32_t)(smem_addr)), "r"((uint32_t)(nCols)) : "memory")
#define TCGEN05_DEALLOC(tmem, nCols) \
    asm volatile("tcgen05.dealloc.cta_group::1.sync.aligned.b32 %0, %1;" \
                 :: "r"(tmem), "r"((uint32_t)(nCols)))
#define TCGEN05_RELINQUISH() \
    asm volatile("tcgen05.relinquish_alloc_permit.cta_group::1.sync.aligned;")
#define TCGEN05_COMMIT(mbar) \
    asm volatile("tcgen05.commit.cta_group::1.mbarrier::arrive::one.shared::cluster.b64 [%0];" \
                 :: "r"((uint32_t)(mbar)) : "memory")
#define TCGEN05_WAIT_LD() \
    asm volatile("tcgen05.wait::ld.sync.aligned;" ::: "memory")
#define TCGEN05_FENCE_AFTER() \
    asm volatile("tcgen05.fence::after_thread_sync;" ::: "memory")
#define TCGEN05_FENCE_BEFORE() \
    asm volatile("tcgen05.fence::before_thread_sync;" ::: "memory")
#define MBARRIER_INIT(mbar, cnt) \
    asm volatile("mbarrier.init.shared.b64 [%0], %1;" \
                 :: "r"((uint32_t)(mbar)), "r"((uint32_t)(cnt)) : "memory")
#define MBARRIER_INVAL(mbar) \
    asm volatile("mbarrier.inval.shared.b64 [%0];" :: "r"((uint32_t)(mbar)) : "memory")
#define FENCE_PROXY_ASYNC() \
    asm volatile("fence.proxy.async.shared::cta;" ::: "memory")

#define MBARRIER_WAIT_PARITY(mbar, parity) do { \
    uint32_t _m = (uint32_t)(mbar); \
    uint32_t _p = (uint32_t)(parity); \
    uint32_t _done; \
    asm volatile("{\n\t.reg .pred p;\n\t" \
        "mbarrier.try_wait.parity.acquire.cta.shared::cta.b64 p, [%1], %2;\n\t" \
        "selp.b32 %0, 1, 0, p;\n\t}" : "=r"(_done) : "r"(_m), "r"(_p) : "memory"); \
    if (!_done) { \
        asm volatile("{\n\t.reg .pred P1;\n\t" \
            "WL_%=:\n\t" \
            "mbarrier.try_wait.parity.acquire.cta.shared::cta.b64 P1, [%0], %1, 0x989680;\n\t" \
            "@P1 bra.uni WD_%=;\n\t" \
            "bra.uni WL_%=;\n\t" \
            "WD_%=:\n\t}" :: "r"(_m), "r"(_p) : "memory"); \
    } \
} while (0)

#define TCGEN05_LD_32X32B_X32(r, tmem_addr) \
    asm volatile( \
        "tcgen05.ld.sync.aligned.32x32b.x32.b32 " \
        "{%0, %1, %2, %3, %4, %5, %6, %7, " \
        " %8, %9, %10, %11, %12, %13, %14, %15, " \
        " %16, %17, %18, %19, %20, %21, %22, %23, " \
        " %24, %25, %26, %27, %28, %29, %30, %31}, [%32];" \
        : "=r"((r)[0]),  "=r"((r)[1]),  "=r"((r)[2]),  "=r"((r)[3]), \
          "=r"((r)[4]),  "=r"((r)[5]),  "=r"((r)[6]),  "=r"((r)[7]), \
          "=r"((r)[8]),  "=r"((r)[9]),  "=r"((r)[10]), "=r"((r)[11]), \
          "=r"((r)[12]), "=r"((r)[13]), "=r"((r)[14]), "=r"((r)[15]), \
          "=r"((r)[16]), "=r"((r)[17]), "=r"((r)[18]), "=r"((r)[19]), \
          "=r"((r)[20]), "=r"((r)[21]), "=r"((r)[22]), "=r"((r)[23]), \
          "=r"((r)[24]), "=r"((r)[25]), "=r"((r)[26]), "=r"((r)[27]), \
          "=r"((r)[28]), "=r"((r)[29]), "=r"((r)[30]), "=r"((r)[31]) \
        : "r"(tmem_addr))

#define TCGEN05_LD_32X32B_X8(r, tmem_addr) \
    asm volatile( \
        "tcgen05.ld.sync.aligned.32x32b.x8.b32 " \
        "{%0, %1, %2, %3, %4, %5, %6, %7}, [%8];" \
        : "=r"((r)[0]), "=r"((r)[1]), "=r"((r)[2]), "=r"((r)[3]), \
          "=r"((r)[4]), "=r"((r)[5]), "=r"((r)[6]), "=r"((r)[7]) \
        : "r"(tmem_addr))

static constexpr uint64_t SMEM_DESC_BASE_SW128 =
    (uint64_t(2) << 61) | (uint64_t(1) << 46) | (uint64_t(64) << 32) | (uint64_t(1) << 16);
#define MAKE_SMEM_DESC(base_addr) \
    (SMEM_DESC_BASE_SW128 | ((uint64_t)((base_addr) >> 4) & 0x3FFF))

static constexpr uint32_t IDESC_TF32_N256 =
    (1u << 4) | (2u << 7) | (2u << 10) | ((256u / 8u) << 17) | ((128u / 16u) << 24);
static constexpr uint32_t IDESC_TF32_N64 =
    (1u << 4) | (2u << 7) | (2u << 10) | ((64u / 8u) << 17) | ((128u / 16u) << 24);

__device__ __forceinline__ void mma_tf32_ss(uint32_t d, uint64_t ad, uint64_t bd,
                                            uint32_t idesc, bool acc) {
    uint32_t en = acc ? 1u : 0u;
    asm volatile(
        "{\n\t.reg .pred p;\n\tsetp.ne.u32 p, %5, 0;\n\t"
        "tcgen05.mma.cta_group::1.kind::tf32 [%0], %1, %2, %3, {%4, %4, %4, %4}, p;\n\t}"
        :: "r"(d), "l"(ad), "l"(bd), "r"(idesc), "r"(0u), "r"(en)
        : "memory");
}

__device__ __forceinline__ float to_tf32(float x) {
    uint32_t r;
    asm("cvt.rna.tf32.f32 %0, %1;" : "=r"(r) : "f"(x));
    return __uint_as_float(r);
}
#endif  // USE_TCGEN05

#define SMEM_SWIZZLE_128B(off) ((off) ^ (((off) >> 3) & 0x70))

// ---------------- W1 transpose ----------------
__global__ void transpose_w1_kernel(const float* __restrict__ W1) {
    __shared__ float t[32][33];
    int bk = blockIdx.x * 32;
    int bn = blockIdx.y * 32;
    int x = threadIdx.x, y = threadIdx.y;
#pragma unroll
    for (int i = 0; i < 32; i += 8)
        t[y + i][x] = W1[(size_t)(bk + y + i) * N_HID + bn + x];
    __syncthreads();
#pragma unroll
    for (int i = 0; i < 32; i += 8)
        g_w1t[(size_t)(bn + y + i) * N_FEAT + bk + x] = t[x][y + i];
}

// ---------------- W2 transpose ----------------
__global__ void transpose_w2_kernel(const float* __restrict__ W2) {
    int i = blockIdx.x * blockDim.x + threadIdx.x;
    if (i < N_HID * N_CLASS) {
        int k = i / N_CLASS;
        int n = i - k * N_CLASS;
        g_w2t[(size_t)n * N_HID + k] = W2[i];
    }
}

// ---------------- GEMM1 ----------------
#define G1_CHUNK_K   32
#define G1_NCHUNKS   (N_FEAT / G1_CHUNK_K)
#define G1_A_BYTES   (128 * 128)
#define G1_B_BYTES   (256 * 128)
#define G1_OFF_A0    1024
#define G1_OFF_A1    (G1_OFF_A0 + G1_A_BYTES)
#define G1_OFF_B0    (G1_OFF_A1 + G1_A_BYTES)
#define G1_OFF_B1    (G1_OFF_B0 + G1_B_BYTES)
#define G1_SMEM_TOTAL (G1_OFF_B1 + G1_B_BYTES)

__global__ void __launch_bounds__(256) gemm1_tc_kernel(const float* __restrict__ A,
                                                       const float* __restrict__ bias) {
    extern __shared__ char smem[];
#if USE_TCGEN05
    const uint32_t sb = smem_to_u32(smem);
    const int tid  = threadIdx.x;
    const int wid  = tid >> 5;
    const int lane = tid & 31;
    const int bm   = blockIdx.x * 128;

    if (wid == 4) TCGEN05_ALLOC(sb + 0, 256);
    if (tid == 0) { MBARRIER_INIT(sb + 8, 1); MBARRIER_INIT(sb + 16, 1); }
    __syncthreads();
    uint32_t tmem;
    asm volatile("ld.shared.b32 %0, [%1];" : "=r"(tmem) : "r"(sb + 0));

    const uint32_t aoff[2] = {G1_OFF_A0, G1_OFF_A1};
    const uint32_t boff[2] = {G1_OFF_B0, G1_OFF_B1};

    for (int c = 0; c < G1_NCHUNKS; c++) {
        const int buf = c & 1;
        if (c >= 2) MBARRIER_WAIT_PARITY(sb + 8 + 8 * buf, ((c - 2) >> 1) & 1);

#pragma unroll
        for (int r = 0; r < 4; r++) {
            int i   = tid + r * 256;
            int row = i >> 3;
            int f4  = i & 7;
            int gm  = bm + row;
            float4 v = make_float4(0.f, 0.f, 0.f, 0.f);
            if (gm < N_NODES)
                v = *(const float4*)(A + (size_t)gm * N_FEAT + c * G1_CHUNK_K + f4 * 4);
            v.x = to_tf32(v.x); v.y = to_tf32(v.y); v.z = to_tf32(v.z); v.w = to_tf32(v.w);
            uint32_t off = SMEM_SWIZZLE_128B((uint32_t)(row * 128 + f4 * 16));
            *(float4*)(smem + aoff[buf] + off) = v;
        }
#pragma unroll
        for (int r = 0; r < 8; r++) {
            int i  = tid + r * 256;
            int n  = i >> 3;
            int f4 = i & 7;
            float4 v = *(const float4*)(g_w1t + (size_t)n * N_FEAT + c * G1_CHUNK_K + f4 * 4);
            v.x = to_tf32(v.x); v.y = to_tf32(v.y); v.z = to_tf32(v.z); v.w = to_tf32(v.w);
            uint32_t off = SMEM_SWIZZLE_128B((uint32_t)(n * 128 + f4 * 16));
            *(float4*)(smem + boff[buf] + off) = v;
        }
        FENCE_PROXY_ASYNC();
        __syncthreads();

        if (wid == 4) {
            if (elect_one_pred()) {
                uint64_t ad = MAKE_SMEM_DESC(sb + aoff[buf]);
                uint64_t bd = MAKE_SMEM_DESC(sb + boff[buf]);
#pragma unroll
                for (int ks = 0; ks < 4; ks++)
                    mma_tf32_ss(tmem, ad + ks * 2, bd + ks * 2, IDESC_TF32_N256,
                                (c > 0) || (ks > 0));
                TCGEN05_COMMIT(sb + 8 + 8 * buf);
            }
        }
    }

    MBARRIER_WAIT_PARITY(sb + 8, 1);
    MBARRIER_WAIT_PARITY(sb + 16, 1);
    TCGEN05_FENCE_AFTER();

    if (wid < 4) {
        const int m = bm + wid * 32 + lane;
#pragma unroll
        for (int b = 0; b < 4; b++) {
            uint32_t r[64];
            TCGEN05_LD_32X32B_X32(r, tmem + b * 64);
            TCGEN05_LD_32X32B_X32(r + 32, tmem + b * 64 + 32);
            TCGEN05_WAIT_LD();
            if (m < N_NODES) {
                float* outp = g_h1 + (size_t)m * N_HID + b * 64;
#pragma unroll
                for (int j = 0; j < 64; j += 4) {
                    float4 o;
                    o.x = fmaxf(__uint_as_float(r[j + 0]) + bias[b * 64 + j + 0], 0.f);
                    o.y = fmaxf(__uint_as_float(r[j + 1]) + bias[b * 64 + j + 1], 0.f);
                    o.z = fmaxf(__uint_as_float(r[j + 2]) + bias[b * 64 + j + 2], 0.f);
                    o.w = fmaxf(__uint_as_float(r[j + 3]) + bias[b * 64 + j + 3], 0.f);
                    *(float4*)(outp + j) = o;
                }
            }
        }
        TCGEN05_FENCE_BEFORE();
    }
    __syncthreads();
    if (tid == 0) { MBARRIER_INVAL(sb + 8); MBARRIER_INVAL(sb + 16); }
    __syncthreads();
    if (wid == 4) { TCGEN05_RELINQUISH(); TCGEN05_DEALLOC(tmem, 256); }

#else
    float (*As)[132] = (float(*)[132])smem;
    float (*Bs)[68]  = (float(*)[68])(smem + 16 * 132 * sizeof(float));

    const int tid  = threadIdx.x;
    const int bm   = blockIdx.x * 128;
    const int mIdx = tid >> 4;
    const int nIdx = tid & 15;

    for (int nb = 0; nb < 4; nb++) {
        const int bn = nb * 64;
        float acc[8][4];
#pragma unroll
        for (int i = 0; i < 8; i++)
#pragma unroll
            for (int j = 0; j < 4; j++) acc[i][j] = 0.f;

        for (int kt = 0; kt < N_FEAT; kt += 16) {
#pragma unroll
            for (int r = 0; r < 2; r++) {
                int i  = tid + r * 256;
                int m  = i >> 2;
                int k4 = (i & 3) * 4;
                int gm = bm + m;
                float4 v = make_float4(0.f, 0.f, 0.f, 0.f);
                if (gm < N_NODES)
                    v = *(const float4*)(A + (size_t)gm * N_FEAT + kt + k4);
                As[k4 + 0][m] = v.x;
                As[k4 + 1][m] = v.y;
                As[k4 + 2][m] = v.z;
                As[k4 + 3][m] = v.w;
            }
            {
                int n  = tid >> 2;
                int k4 = (tid & 3) * 4;
                float4 v = *(const float4*)(g_w1t + (size_t)(bn + n) * N_FEAT + kt + k4);
                Bs[k4 + 0][n] = v.x;
                Bs[k4 + 1][n] = v.y;
                Bs[k4 + 2][n] = v.z;
                Bs[k4 + 3][n] = v.w;
            }
            __syncthreads();

#pragma unroll
            for (int k = 0; k < 16; k++) {
                float ra[8], rb[4];
#pragma unroll
                for (int i = 0; i < 8; i++) ra[i] = As[k][mIdx * 8 + i];
#pragma unroll
                for (int j = 0; j < 4; j++) rb[j] = Bs[k][nIdx * 4 + j];
#pragma unroll
                for (int i = 0; i < 8; i++)
#pragma unroll
                    for (int j = 0; j < 4; j++) acc[i][j] += ra[i] * rb[j];
            }
            __syncthreads();
        }

#pragma unroll
        for (int i = 0; i < 8; i++) {
            int gm = bm + mIdx * 8 + i;
            if (gm < N_NODES) {
#pragma unroll
                for (int j = 0; j < 4; j++) {
                    int gn = bn + nIdx * 4 + j;
                    float v = acc[i][j] + bias[gn];
                    g_h1[(size_t)gm * N_HID + gn] = fmaxf(v, 0.f);
                }
            }
        }
    }
#endif
}

// ---------------- GEMM2 ----------------
#define G2_CHUNK_K   32
#define G2_NCHUNKS   (N_HID / G2_CHUNK_K)
#define G2_A_BYTES   (128 * 128)
#define G2_BCH_BYTES (64 * 128)
#define G2_OFF_A0    1024
#define G2_OFF_A1    (G2_OFF_A0 + G2_A_BYTES)
#define G2_OFF_B     (G2_OFF_A1 + G2_A_BYTES)
#define G2_SMEM_TOTAL (G2_OFF_B + G2_NCHUNKS * G2_BCH_BYTES)

__global__ void __launch_bounds__(256) gemm2_tc_kernel(const float* __restrict__ b2) {
    extern __shared__ char smem[];
#if USE_TCGEN05
    const uint32_t sb = smem_to_u32(smem);
    const int tid  = threadIdx.x;
    const int wid  = tid >> 5;
    const int lane = tid & 31;
    const int bm   = blockIdx.x * 128;

    if (wid == 4) TCGEN05_ALLOC(sb + 0, 64);
    if (tid == 0) { MBARRIER_INIT(sb + 8, 1); MBARRIER_INIT(sb + 16, 1); }
    __syncthreads();
    uint32_t tmem;
    asm volatile("ld.shared.b32 %0, [%1];" : "=r"(tmem) : "r"(sb + 0));

    for (int i = tid; i < (G2_NCHUNKS * G2_BCH_BYTES) / 16; i += 256)
        *(float4*)(smem + G2_OFF_B + i * 16) = make_float4(0.f, 0.f, 0.f, 0.f);
    __syncthreads();
    for (int i = tid; i < G2_NCHUNKS * N_CLASS * 8; i += 256) {
        int ch  = i / (N_CLASS * 8);
        int rem = i - ch * (N_CLASS * 8);
        int n   = rem >> 3;
        int f4  = rem & 7;
        float4 v = *(const float4*)(g_w2t + (size_t)n * N_HID + ch * G2_CHUNK_K + f4 * 4);
        v.x = to_tf32(v.x); v.y = to_tf32(v.y); v.z = to_tf32(v.z); v.w = to_tf32(v.w);
        uint32_t off = SMEM_SWIZZLE_128B((uint32_t)(n * 128 + f4 * 16));
        *(float4*)(smem + G2_OFF_B + ch * G2_BCH_BYTES + off) = v;
    }

    const uint32_t aoff[2] = {G2_OFF_A0, G2_OFF_A1};

    for (int c = 0; c < G2_NCHUNKS; c++) {
        const int buf = c & 1;
        if (c >= 2) MBARRIER_WAIT_PARITY(sb + 8 + 8 * buf, ((c - 2) >> 1) & 1);

#pragma unroll
        for (int r = 0; r < 4; r++) {
            int i   = tid + r * 256;
            int row = i >> 3;
            int f4  = i & 7;
            int gm  = bm + row;
            float4 v = make_float4(0.f, 0.f, 0.f, 0.f);
            if (gm < N_NODES)
                v = *(const float4*)(g_h1 + (size_t)gm * N_HID + c * G2_CHUNK_K + f4 * 4);
            v.x = to_tf32(v.x); v.y = to_tf32(v.y); v.z = to_tf32(v.z); v.w = to_tf32(v.w);
            uint32_t off = SMEM_SWIZZLE_128B((uint32_t)(row * 128 + f4 * 16));
            *(float4*)(smem + aoff[buf] + off) = v;
        }
        FENCE_PROXY_ASYNC();
        __syncthreads();

        if (wid == 4) {
            if (elect_one_pred()) {
                uint64_t ad = MAKE_SMEM_DESC(sb + aoff[buf]);
                uint64_t bd = MAKE_SMEM_DESC(sb + G2_OFF_B + c * G2_BCH_BYTES);
#pragma unroll
                for (int ks = 0; ks < 4; ks++)
                    mma_tf32_ss(tmem, ad + ks * 2, bd + ks * 2, IDESC_TF32_N64,
                                (c > 0) || (ks > 0));
                TCGEN05_COMMIT(sb + 8 + 8 * buf);
            }
        }
    }

    MBARRIER_WAIT_PARITY(sb + 8, 1);
    MBARRIER_WAIT_PARITY(sb + 16, 1);
    TCGEN05_FENCE_AFTER();

    if (wid < 4) {
        const int m = bm + wid * 32 + lane;
        uint32_t r[40];
        TCGEN05_LD_32X32B_X32(r, tmem);
        TCGEN05_LD_32X32B_X8(r + 32, tmem + 32);
        TCGEN05_WAIT_LD();
        if (m < N_NODES) {
            float* outp = g_xs + (size_t)m * N_CLASS;
#pragma unroll
            for (int j = 0; j < 40; j += 4) {
                float4 o;
                o.x = __uint_as_float(r[j + 0]) + b2[j + 0];
                o.y = __uint_as_float(r[j + 1]) + b2[j + 1];
                o.z = __uint_as_float(r[j + 2]) + b2[j + 2];
                o.w = __uint_as_float(r[j + 3]) + b2[j + 3];
                *(float4*)(outp + j) = o;
            }
        }
        TCGEN05_FENCE_BEFORE();
    }
    __syncthreads();
    if (tid == 0) { MBARRIER_INVAL(sb + 8); MBARRIER_INVAL(sb + 16); }
    __syncthreads();
    if (wid == 4) { TCGEN05_RELINQUISH(); TCGEN05_DEALLOC(tmem, 64); }

#else
    float (*As)[65] = (float(*)[65])smem;
    float* W2s = (float*)(smem + 64 * 65 * sizeof(float));

    const int tid = threadIdx.x;
    for (int half = 0; half < 2; half++) {
        const int bm  = blockIdx.x * 128 + half * 64;
        const int row = tid >> 2;
        const int q   = tid & 3;

        float acc[10];
#pragma unroll
        for (int j = 0; j < 10; j++) acc[j] = 0.f;

        for (int kb = 0; kb < N_HID; kb += 64) {
#pragma unroll
            for (int r = 0; r < 4; r++) {
                int i  = tid + r * 256;
                int rr = i >> 4;
                int c4 = (i & 15) * 4;
                int gm = bm + rr;
                float4 v = make_float4(0.f, 0.f, 0.f, 0.f);
                if (gm < N_NODES)
                    v = *(const float4*)(g_h1 + (size_t)gm * N_HID + kb + c4);
                As[rr][c4 + 0] = v.x;
                As[rr][c4 + 1] = v.y;
                As[rr][c4 + 2] = v.z;
                As[rr][c4 + 3] = v.w;
            }
#pragma unroll
            for (int r = 0; r < 10; r++) {
                int e = tid + r * 256;
                int k = e / N_CLASS;
                int n = e - k * N_CLASS;
                W2s[e] = g_w2t[(size_t)n * N_HID + kb + k];
            }
            __syncthreads();

#pragma unroll 4
            for (int k = 0; k < 64; k++) {
                float a = As[row][k];
#pragma unroll
                for (int j = 0; j < 10; j++)
                    acc[j] += a * W2s[k * N_CLASS + q * 10 + j];
            }
            __syncthreads();
        }

        int gm = bm + row;
        if (gm < N_NODES) {
#pragma unroll
            for (int j = 0; j < 10; j++)
                g_xs[(size_t)gm * N_CLASS + q * 10 + j] = acc[j] + b2[q * 10 + j];
        }
        __syncthreads();
    }
#endif
}

// ---------------- CSR build ----------------
__global__ void zero_count_kernel() {
    int i = blockIdx.x * blockDim.x + threadIdx.x;
    if (i < N_NODES) g_count[i] = 0;
}

__global__ void hist_kernel(const int* __restrict__ edge_row) {
    int e = blockIdx.x * blockDim.x + threadIdx.x;
    if (e < N_EDGES) atomicAdd(&g_count[edge_row[e]], 1);
}

__global__ void __launch_bounds__(1024) scan1_kernel() {
    __shared__ int warp_sums[32];
    const int tid = threadIdx.x, lane = tid & 31, wid = tid >> 5;
    const int i = blockIdx.x * 1024 + tid;

    int v = (i < N_NODES) ? g_count[i] : 0;
    int x = v;
#pragma unroll
    for (int off = 1; off < 32; off <<= 1) {
        int y = __shfl_up_sync(0xffffffffu, x, off);
        if (lane >= off) x += y;
    }
    if (lane == 31) warp_sums[wid] = x;
    __syncthreads();
    if (wid == 0) {
        int s = warp_sums[lane];
#pragma unroll
        for (int off = 1; off < 32; off <<= 1) {
            int y = __shfl_up_sync(0xffffffffu, s, off);
            if (lane >= off) s += y;
        }
        warp_sums[lane] = s;
    }
    __syncthreads();
    int incl = x + ((wid > 0) ? warp_sums[wid - 1] : 0);
    if (i < N_NODES) g_cursor[i] = incl - v;
    if (tid == 1023) g_bsum[blockIdx.x] = incl;
}

__global__ void scan2_kernel() {
    __shared__ int ws[4];
    const int tid = threadIdx.x, lane = tid & 31, wid = tid >> 5;
    int v = (tid < SCAN_BLOCKS) ? g_bsum[tid] : 0;
    int x = v;
#pragma unroll
    for (int off = 1; off < 32; off <<= 1) {
        int y = __shfl_up_sync(0xffffffffu, x, off);
        if (lane >= off) x += y;
    }
    if (lane == 31) ws[wid] = x;
    __syncthreads();
    if (wid == 0 && lane < 4) {
        int s = ws[lane];
#pragma unroll
        for (int off = 1; off < 4; off <<= 1) {
            int y = __shfl_up_sync(0xfu, s, off);
            if (lane >= off) s += y;
        }
        ws[lane] = s;
    }
    __syncthreads();
    int excl = x - v + ((wid > 0) ? ws[wid - 1] : 0);
    if (tid < SCAN_BLOCKS) g_boff[tid] = excl;
}

__global__ void scan3_kernel() {
    int i = blockIdx.x * blockDim.x + threadIdx.x;
    if (i < N_NODES) {
        int excl = g_cursor[i] + g_boff[i >> 10];
        g_cursor[i]     = excl;
        g_rowptr[i + 1] = excl + g_count[i];
        if (i == 0) g_rowptr[0] = 0;
    }
}

__global__ void scatter_kernel(const int* __restrict__ edge_row,
                               const int* __restrict__ edge_col,
                               const float* __restrict__ edge_w) {
    int e = blockIdx.x * blockDim.x + threadIdx.x;
    if (e < N_EDGES) {
        int r = edge_row[e];
        int p = atomicAdd(&g_cursor[r], 1);
        g_edge[p] = make_int2(edge_col[e], __float_as_int(edge_w[e]));
    }
}

// ---------------- SpMM hop with PDL edge prefetch ----------------
// Prologue (before griddepcontrol.wait) stages this block's edges in SMEM;
// g_rowptr/g_edge do not depend on the previous hop, so under programmatic
// stream serialization this overlaps the prior kernel's execution.
__global__ void __launch_bounds__(320) spmm_kernel(int hop) {
    __shared__ int2 es[32][SPMM_PAD];   // 12.5 KB

    const float* __restrict__ xin  = g_xs + (size_t)(hop - 1) * N_NODES * N_CLASS;
    float* __restrict__       xout = g_xs + (size_t)hop * N_NODES * N_CLASS;

    const int t    = blockIdx.x * blockDim.x + threadIdx.x;   // grid exact: 1M threads
    const int row  = t / 10;
    const int lane = t - row * 10;
    const int rloc = threadIdx.x / 10;

    const int s   = g_rowptr[row];
    const int e   = g_rowptr[row + 1];
    const int deg = e - s;
    const int stage = (deg < SPMM_CAP) ? deg : SPMM_CAP;

    for (int i = lane; i < stage; i += 10)
        es[rloc][i] = g_edge[s + i];
    __syncthreads();                    // row groups straddle warp boundaries

    GRIDDEP_WAIT();                     // previous grid complete + flushed
    GRIDDEP_LAUNCH();                   // release next kernel's prologues

    float4 acc = make_float4(0.f, 0.f, 0.f, 0.f);

    int i = 0;
    for (; i + 4 <= stage; i += 4) {
        int2 e0 = es[rloc][i + 0];
        int2 e1 = es[rloc][i + 1];
        int2 e2 = es[rloc][i + 2];
        int2 e3 = es[rloc][i + 3];
        float4 v0 = *(const float4*)(xin + (size_t)e0.x * N_CLASS + lane * 4);
        float4 v1 = *(const float4*)(xin + (size_t)e1.x * N_CLASS + lane * 4);
        float4 v2 = *(const float4*)(xin + (size_t)e2.x * N_CLASS + lane * 4);
        float4 v3 = *(const float4*)(xin + (size_t)e3.x * N_CLASS + lane * 4);
        float w0 = __int_as_float(e0.y);
        float w1 = __int_as_float(e1.y);
        float w2 = __int_as_float(e2.y);
        float w3 = __int_as_float(e3.y);
        acc.x += w0 * v0.x; acc.y += w0 * v0.y; acc.z += w0 * v0.z; acc.w += w0 * v0.w;
        acc.x += w1 * v1.x; acc.y += w1 * v1.y; acc.z += w1 * v1.z; acc.w += w1 * v1.w;
        acc.x += w2 * v2.x; acc.y += w2 * v2.y; acc.z += w2 * v2.z; acc.w += w2 * v2.w;
        acc.x += w3 * v3.x; acc.y += w3 * v3.y; acc.z += w3 * v3.z; acc.w += w3 * v3.w;
    }
    for (; i < stage; i++) {
        int2  ed = es[rloc][i];
        float w  = __int_as_float(ed.y);
        float4 v = *(const float4*)(xin + (size_t)ed.x * N_CLASS + lane * 4);
        acc.x += w * v.x; acc.y += w * v.y; acc.z += w * v.z; acc.w += w * v.w;
    }
    for (int j = s + stage; j < e; j++) {   // rare spill (deg > 48), same order
        int2  ed = g_edge[j];
        float w  = __int_as_float(ed.y);
        float4 v = *(const float4*)(xin + (size_t)ed.x * N_CLASS + lane * 4);
        acc.x += w * v.x; acc.y += w * v.y; acc.z += w * v.z; acc.w += w * v.w;
    }
    *(float4*)(xout + (size_t)row * N_CLASS + lane * 4) = acc;
}

// ---------------- attention + log_softmax ----------------
__global__ void attn_kernel(const float* __restrict__ Wa,
                            const float* __restrict__ ba,
                            float* __restrict__ out) {
    int gwarp = (blockIdx.x * blockDim.x + threadIdx.x) >> 5;
    int lane  = threadIdx.x & 31;

    const float wa0 = Wa[lane];
    const float wa1 = (lane < 8) ? Wa[lane + 32] : 0.f;
    const float bav = ba[0];

    GRIDDEP_WAIT();
    if (gwarp >= N_NODES) return;
    const int n = gwarp;

    float v0[K_HOPS + 1], v1[K_HOPS + 1];
#pragma unroll
    for (int k = 0; k <= K_HOPS; k++) {
        const float* p = g_xs + ((size_t)k * N_NODES + n) * N_CLASS;
        v0[k] = p[lane];
        v1[k] = (lane < 8) ? p[lane + 32] : 0.f;
    }

    float acc0 = 0.f, acc1 = 0.f;
#pragma unroll
    for (int k = 0; k <= K_HOPS; k++) {
        float dot = v0[k] * wa0 + v1[k] * wa1;
#pragma unroll
        for (int off = 16; off > 0; off >>= 1)
            dot += __shfl_xor_sync(0xffffffffu, dot, off);
        float s = 1.f / (1.f + expf(-(dot + bav)));
        acc0 += s * v0[k];
        acc1 += s * v1[k];
    }

    float m = acc0;
    if (lane < 8) m = fmaxf(m, acc1);
#pragma unroll
    for (int off = 16; off > 0; off >>= 1)
        m = fmaxf(m, __shfl_xor_sync(0xffffffffu, m, off));

    float se = expf(acc0 - m) + ((lane < 8) ? expf(acc1 - m) : 0.f);
#pragma unroll
    for (int off = 16; off > 0; off >>= 1)
        se += __shfl_xor_sync(0xffffffffu, se, off);

    float lse = logf(se);
    out[(size_t)n * N_CLASS + lane] = acc0 - m - lse;
    if (lane < 8)
        out[(size_t)n * N_CLASS + lane + 32] = acc1 - m - lse;
}

// ---------------- launch ----------------
static cudaStream_t g_side    = nullptr;
static cudaEvent_t  g_ev_fork = nullptr;
static cudaEvent_t  g_ev_join = nullptr;
static int          g_inited  = 0;
static int          g_pdl     = -1;   // -1 unknown, decided on first call

static cudaError_t launch_spmm(int hop, bool pdl) {
    cudaLaunchConfig_t cfg = {};
    cfg.gridDim  = dim3((N_NODES * 10 + 319) / 320, 1, 1);
    cfg.blockDim = dim3(320, 1, 1);
    cfg.stream   = (cudaStream_t)0;
    cudaLaunchAttribute attrs[1];
    if (pdl) {
        attrs[0].id = cudaLaunchAttributeProgrammaticStreamSerialization;
        attrs[0].val.programmaticStreamSerializationAllowed = 1;
        cfg.attrs = attrs;
        cfg.numAttrs = 1;
    }
    return cudaLaunchKernelEx(&cfg, spmm_kernel, hop);
}

static cudaError_t launch_attn(const float* Wa, const float* ba, float* out, bool pdl) {
    cudaLaunchConfig_t cfg = {};
    cfg.gridDim  = dim3((N_NODES * 32 + 255) / 256, 1, 1);
    cfg.blockDim = dim3(256, 1, 1);
    cfg.stream   = (cudaStream_t)0;
    cudaLaunchAttribute attrs[1];
    if (pdl) {
        attrs[0].id = cudaLaunchAttributeProgrammaticStreamSerialization;
        attrs[0].val.programmaticStreamSerializationAllowed = 1;
        cfg.attrs = attrs;
        cfg.numAttrs = 1;
    }
    return cudaLaunchKernelEx(&cfg, attn_kernel, Wa, ba, out);
}

extern "C" void kernel_launch(void* const* d_in, const int* in_sizes, int n_in,
                              void* d_out, int out_size) {
    const float* feature  = (const float*)d_in[0];
    const int*   edge_row = (const int*)  d_in[1];
    const int*   edge_col = (const int*)  d_in[2];
    const float* edge_w   = (const float*)d_in[3];
    const float* W1       = (const float*)d_in[4];
    const float* b1       = (const float*)d_in[5];
    const float* W2       = (const float*)d_in[6];
    const float* b2       = (const float*)d_in[7];
    const float* Wa       = (const float*)d_in[8];
    const float* ba       = (const float*)d_in[9];
    float*       out      = (float*)d_out;

    if (!g_inited) {
        cudaStreamCreateWithFlags(&g_side, cudaStreamNonBlocking);
        cudaEventCreateWithFlags(&g_ev_fork, cudaEventDisableTiming);
        cudaEventCreateWithFlags(&g_ev_join, cudaEventDisableTiming);
        cudaFuncSetAttribute(gemm1_tc_kernel,
                             cudaFuncAttributeMaxDynamicSharedMemorySize, G1_SMEM_TOTAL);
        cudaFuncSetAttribute(gemm2_tc_kernel,
                             cudaFuncAttributeMaxDynamicSharedMemorySize, G2_SMEM_TOTAL);
        g_inited = 1;
    }

    const bool fork = (g_side != nullptr) && (g_ev_fork != nullptr) && (g_ev_join != nullptr);
    cudaStream_t cs = fork ? g_side : (cudaStream_t)0;

    if (fork) {
        cudaEventRecord(g_ev_fork, 0);
        cudaStreamWaitEvent(g_side, g_ev_fork, 0);
    }

    // ---- CSR chain ----
    zero_count_kernel<<<(N_NODES + 255) / 256, 256, 0, cs>>>();
    hist_kernel<<<(N_EDGES + 255) / 256, 256, 0, cs>>>(edge_row);
    scan1_kernel<<<SCAN_BLOCKS, 1024, 0, cs>>>();
    scan2_kernel<<<1, 128, 0, cs>>>();
    scan3_kernel<<<(N_NODES + 255) / 256, 256, 0, cs>>>();
    scatter_kernel<<<(N_EDGES + 255) / 256, 256, 0, cs>>>(edge_row, edge_col, edge_w);

    if (fork) cudaEventRecord(g_ev_join, g_side);

    // ---- dense chain ----
    transpose_w1_kernel<<<dim3(N_FEAT / 32, N_HID / 32), dim3(32, 8)>>>(W1);
    transpose_w2_kernel<<<(N_HID * N_CLASS + 255) / 256, 256>>>(W2);
    gemm1_tc_kernel<<<(N_NODES + 127) / 128, 256, G1_SMEM_TOTAL>>>(feature, b1);
    gemm2_tc_kernel<<<(N_NODES + 127) / 128, 256, G2_SMEM_TOTAL>>>(b2);

    // ---- join ----
    if (fork) cudaStreamWaitEvent((cudaStream_t)0, g_ev_join, 0);

    // hop 1 plain (depends on gemm2 + scatter); hops 2..10 + attn with PDL.
    // PDL support decided once on the first (uncaptured) call, then fixed.
    if (launch_spmm(1, false) != cudaSuccess)
        spmm_kernel<<<(N_NODES * 10 + 319) / 320, 320>>>(1);
    for (int k = 2; k <= K_HOPS; k++) {
        bool used_pdl = false;
        if (g_pdl != 0) {
            if (launch_spmm(k, true) == cudaSuccess) { used_pdl = true; if (g_pdl < 0) g_pdl = 1; }
            else if (g_pdl < 0) g_pdl = 0;
        }
        if (!used_pdl)
            if (launch_spmm(k, false) != cudaSuccess)
                spmm_kernel<<<(N_NODES * 10 + 319) / 320, 320>>>(k);
    }
    {
        bool used_pdl = false;
        if (g_pdl == 1 && launch_attn(Wa, ba, out, true) == cudaSuccess) used_pdl = true;
        if (!used_pdl)
            if (launch_attn(Wa, ba, out, false) != cudaSuccess)
                attn_kernel<<<(N_NODES * 32 + 255) / 256, 256>>>(Wa, ba, out);
    }
}

// round 11
// speedup vs baseline: 1.2626x; 1.0077x over previous
#include <cuda_runtime.h>
#include <cuda_bf16.h>
#include <math.h>
#include <stdint.h>

#define N_NODES 100000
#define N_EDGES 3200000
#define N_FEAT  512
#define N_HID   256
#define N_CLASS 40
#define K_HOPS  10
#define SCAN_BLOCKS 98    // 98 * 1024 >= N_NODES
#define SPMM_CAP 48       // staged edges per row (deg>48 spills to gmem)
#define SPMM_PAD 49       // +1 int2 to stagger smem banks

// tcgen05 only exists in the arch-accelerated target (sm_103a / sm_100a).
// The harness also runs a plain compute_103 ptxas pass, which rejects it.
#if defined(__CUDA_ARCH_FEAT_SM103_ALL) || defined(__CUDA_ARCH_FEAT_SM100_ALL)
#define USE_TCGEN05 1
#else
#define USE_TCGEN05 0
#endif

// ---------------- scratch (no cudaMalloc allowed) ----------------
__device__ float g_h1[(size_t)N_NODES * N_HID];                   // 102.4 MB
__device__ float g_xs[(size_t)(K_HOPS + 1) * N_NODES * N_CLASS];  // 176 MB
__device__ float g_w1t[(size_t)N_HID * N_FEAT];                   // W1^T, 512 KB
__device__ float g_w2t[(size_t)N_CLASS * N_HID];                  // W2^T, 40 KB
__device__ int   g_rowptr[N_NODES + 1];
__device__ int   g_count[N_NODES];
__device__ int   g_cursor[N_NODES];
__device__ int2  g_edge[N_EDGES];                                 // (col, w bits) interleaved
__device__ int   g_bsum[SCAN_BLOCKS];
__device__ int   g_boff[SCAN_BLOCKS];

// ================= PTX helpers =================
__device__ __forceinline__ uint32_t smem_to_u32(const void* p) {
    uint32_t a;
    asm("{ .reg .u64 t; cvta.to.shared.u64 t, %1; cvt.u32.u64 %0, t; }"
        : "=r"(a) : "l"(p));
    return a;
}

#define GRIDDEP_WAIT() asm volatile("griddepcontrol.wait;" ::: "memory")
#define GRIDDEP_LAUNCH() asm volatile("griddepcontrol.launch_dependents;")

#if USE_TCGEN05
__device__ __forceinline__ uint32_t elect_one_pred() {
    uint32_t p;
    asm volatile("{\n\t.reg .pred p;\n\telect.sync _|p, 0xFFFFFFFF;\n\t"
                 "selp.b32 %0, 1, 0, p;\n\t}" : "=r"(p));
    return p;
}

#define TCGEN05_ALLOC(smem_addr, nCols) \
    asm volatile("tcgen05.alloc.cta_group::1.sync.aligned.shared::cta.b32 [%0], %1;" \
                 :: "r"((uint32_t)(smem_addr)), "r"((uint32_t)(nCols)) : "memory")
#define TCGEN05_DEALLOC(tmem, nCols) \
    asm volatile("tcgen05.dealloc.cta_group::1.sync.aligned.b32 %0, %1;" \
                 :: "r"(tmem), "r"((uint32_t)(nCols)))
#define TCGEN05_RELINQUISH() \
    asm volatile("tcgen05.relinquish_alloc_permit.cta_group::1.sync.aligned;")
#define TCGEN05_COMMIT(mbar) \
    asm volatile("tcgen05.commit.cta_group::1.mbarrier::arrive::one.shared::cluster.b64 [%0];" \
                 :: "r"((uint32_t)(mbar)) : "memory")
#define TCGEN05_WAIT_LD() \
    asm volatile("tcgen05.wait::ld.sync.aligned;" ::: "memory")
#define TCGEN05_FENCE_AFTER() \
    asm volatile("tcgen05.fence::after_thread_sync;" ::: "memory")
#define TCGEN05_FENCE_BEFORE() \
    asm volatile("tcgen05.fence::before_thread_sync;" ::: "memory")
#define MBARRIER_INIT(mbar, cnt) \
    asm volatile("mbarrier.init.shared.b64 [%0], %1;" \
                 :: "r"((uint32_t)(mbar)), "r"((uint32_t)(cnt)) : "memory")
#define MBARRIER_INVAL(mbar) \
    asm volatile("mbarrier.inval.shared.b64 [%0];" :: "r"((uint32_t)(mbar)) : "memory")
#define FENCE_PROXY_ASYNC() \
    asm volatile("fence.proxy.async.shared::cta;" ::: "memory")

#define MBARRIER_WAIT_PARITY(mbar, parity) do { \
    uint32_t _m = (uint32_t)(mbar); \
    uint32_t _p = (uint32_t)(parity); \
    uint32_t _done; \
    asm volatile("{\n\t.reg .pred p;\n\t" \
        "mbarrier.try_wait.parity.acquire.cta.shared::cta.b64 p, [%1], %2;\n\t" \
        "selp.b32 %0, 1, 0, p;\n\t}" : "=r"(_done) : "r"(_m), "r"(_p) : "memory"); \
    if (!_done) { \
        asm volatile("{\n\t.reg .pred P1;\n\t" \
            "WL_%=:\n\t" \
            "mbarrier.try_wait.parity.acquire.cta.shared::cta.b64 P1, [%0], %1, 0x989680;\n\t" \
            "@P1 bra.uni WD_%=;\n\t" \
            "bra.uni WL_%=;\n\t" \
            "WD_%=:\n\t}" :: "r"(_m), "r"(_p) : "memory"); \
    } \
} while (0)

#define TCGEN05_LD_32X32B_X32(r, tmem_addr) \
    asm volatile( \
        "tcgen05.ld.sync.aligned.32x32b.x32.b32 " \
        "{%0, %1, %2, %3, %4, %5, %6, %7, " \
        " %8, %9, %10, %11, %12, %13, %14, %15, " \
        " %16, %17, %18, %19, %20, %21, %22, %23, " \
        " %24, %25, %26, %27, %28, %29, %30, %31}, [%32];" \
        : "=r"((r)[0]),  "=r"((r)[1]),  "=r"((r)[2]),  "=r"((r)[3]), \
          "=r"((r)[4]),  "=r"((r)[5]),  "=r"((r)[6]),  "=r"((r)[7]), \
          "=r"((r)[8]),  "=r"((r)[9]),  "=r"((r)[10]), "=r"((r)[11]), \
          "=r"((r)[12]), "=r"((r)[13]), "=r"((r)[14]), "=r"((r)[15]), \
          "=r"((r)[16]), "=r"((r)[17]), "=r"((r)[18]), "=r"((r)[19]), \
          "=r"((r)[20]), "=r"((r)[21]), "=r"((r)[22]), "=r"((r)[23]), \
          "=r"((r)[24]), "=r"((r)[25]), "=r"((r)[26]), "=r"((r)[27]), \
          "=r"((r)[28]), "=r"((r)[29]), "=r"((r)[30]), "=r"((r)[31]) \
        : "r"(tmem_addr))

#define TCGEN05_LD_32X32B_X8(r, tmem_addr) \
    asm volatile( \
        "tcgen05.ld.sync.aligned.32x32b.x8.b32 " \
        "{%0, %1, %2, %3, %4, %5, %6, %7}, [%8];" \
        : "=r"((r)[0]), "=r"((r)[1]), "=r"((r)[2]), "=r"((r)[3]), \
          "=r"((r)[4]), "=r"((r)[5]), "=r"((r)[6]), "=r"((r)[7]) \
        : "r"(tmem_addr))

static constexpr uint64_t SMEM_DESC_BASE_SW128 =
    (uint64_t(2) << 61) | (uint64_t(1) << 46) | (uint64_t(64) << 32) | (uint64_t(1) << 16);
#define MAKE_SMEM_DESC(base_addr) \
    (SMEM_DESC_BASE_SW128 | ((uint64_t)((base_addr) >> 4) & 0x3FFF))

static constexpr uint32_t IDESC_TF32_N256 =
    (1u << 4) | (2u << 7) | (2u << 10) | ((256u / 8u) << 17) | ((128u / 16u) << 24);
static constexpr uint32_t IDESC_TF32_N64 =
    (1u << 4) | (2u << 7) | (2u << 10) | ((64u / 8u) << 17) | ((128u / 16u) << 24);

__device__ __forceinline__ void mma_tf32_ss(uint32_t d, uint64_t ad, uint64_t bd,
                                            uint32_t idesc, bool acc) {
    uint32_t en = acc ? 1u : 0u;
    asm volatile(
        "{\n\t.reg .pred p;\n\tsetp.ne.u32 p, %5, 0;\n\t"
        "tcgen05.mma.cta_group::1.kind::tf32 [%0], %1, %2, %3, {%4, %4, %4, %4}, p;\n\t}"
        :: "r"(d), "l"(ad), "l"(bd), "r"(idesc), "r"(0u), "r"(en)
        : "memory");
}

__device__ __forceinline__ float to_tf32(float x) {
    uint32_t r;
    asm("cvt.rna.tf32.f32 %0, %1;" : "=r"(r) : "f"(x));
    return __uint_as_float(r);
}
#endif  // USE_TCGEN05

#define SMEM_SWIZZLE_128B(off) ((off) ^ (((off) >> 3) & 0x70))

// ---------------- W1 transpose ----------------
__global__ void transpose_w1_kernel(const float* __restrict__ W1) {
    __shared__ float t[32][33];
    int bk = blockIdx.x * 32;
    int bn = blockIdx.y * 32;
    int x = threadIdx.x, y = threadIdx.y;
#pragma unroll
    for (int i = 0; i < 32; i += 8)
        t[y + i][x] = W1[(size_t)(bk + y + i) * N_HID + bn + x];
    __syncthreads();
#pragma unroll
    for (int i = 0; i < 32; i += 8)
        g_w1t[(size_t)(bn + y + i) * N_FEAT + bk + x] = t[x][y + i];
}

// ---------------- W2 transpose ----------------
__global__ void transpose_w2_kernel(const float* __restrict__ W2) {
    int i = blockIdx.x * blockDim.x + threadIdx.x;
    if (i < N_HID * N_CLASS) {
        int k = i / N_CLASS;
        int n = i - k * N_CLASS;
        g_w2t[(size_t)n * N_HID + k] = W2[i];
    }
}

// ---------------- GEMM1 ----------------
#define G1_CHUNK_K   32
#define G1_NCHUNKS   (N_FEAT / G1_CHUNK_K)
#define G1_A_BYTES   (128 * 128)
#define G1_B_BYTES   (256 * 128)
#define G1_OFF_A0    1024
#define G1_OFF_A1    (G1_OFF_A0 + G1_A_BYTES)
#define G1_OFF_B0    (G1_OFF_A1 + G1_A_BYTES)
#define G1_OFF_B1    (G1_OFF_B0 + G1_B_BYTES)
#define G1_SMEM_TOTAL (G1_OFF_B1 + G1_B_BYTES)

__global__ void __launch_bounds__(256) gemm1_tc_kernel(const float* __restrict__ A,
                                                       const float* __restrict__ bias) {
    extern __shared__ char smem[];
#if USE_TCGEN05
    const uint32_t sb = smem_to_u32(smem);
    const int tid  = threadIdx.x;
    const int wid  = tid >> 5;
    const int lane = tid & 31;
    const int bm   = blockIdx.x * 128;

    if (wid == 4) TCGEN05_ALLOC(sb + 0, 256);
    if (tid == 0) { MBARRIER_INIT(sb + 8, 1); MBARRIER_INIT(sb + 16, 1); }
    __syncthreads();
    GRIDDEP_LAUNCH();   // let gemm2's prologue (B fill) overlap our mainloop
    uint32_t tmem;
    asm volatile("ld.shared.b32 %0, [%1];" : "=r"(tmem) : "r"(sb + 0));

    const uint32_t aoff[2] = {G1_OFF_A0, G1_OFF_A1};
    const uint32_t boff[2] = {G1_OFF_B0, G1_OFF_B1};

    for (int c = 0; c < G1_NCHUNKS; c++) {
        const int buf = c & 1;
        if (c >= 2) MBARRIER_WAIT_PARITY(sb + 8 + 8 * buf, ((c - 2) >> 1) & 1);

#pragma unroll
        for (int r = 0; r < 4; r++) {
            int i   = tid + r * 256;
            int row = i >> 3;
            int f4  = i & 7;
            int gm  = bm + row;
            float4 v = make_float4(0.f, 0.f, 0.f, 0.f);
            if (gm < N_NODES)
                v = *(const float4*)(A + (size_t)gm * N_FEAT + c * G1_CHUNK_K + f4 * 4);
            v.x = to_tf32(v.x); v.y = to_tf32(v.y); v.z = to_tf32(v.z); v.w = to_tf32(v.w);
            uint32_t off = SMEM_SWIZZLE_128B((uint32_t)(row * 128 + f4 * 16));
            *(float4*)(smem + aoff[buf] + off) = v;
        }
#pragma unroll
        for (int r = 0; r < 8; r++) {
            int i  = tid + r * 256;
            int n  = i >> 3;
            int f4 = i & 7;
            float4 v = *(const float4*)(g_w1t + (size_t)n * N_FEAT + c * G1_CHUNK_K + f4 * 4);
            v.x = to_tf32(v.x); v.y = to_tf32(v.y); v.z = to_tf32(v.z); v.w = to_tf32(v.w);
            uint32_t off = SMEM_SWIZZLE_128B((uint32_t)(n * 128 + f4 * 16));
            *(float4*)(smem + boff[buf] + off) = v;
        }
        FENCE_PROXY_ASYNC();
        __syncthreads();

        if (wid == 4) {
            if (elect_one_pred()) {
                uint64_t ad = MAKE_SMEM_DESC(sb + aoff[buf]);
                uint64_t bd = MAKE_SMEM_DESC(sb + boff[buf]);
#pragma unroll
                for (int ks = 0; ks < 4; ks++)
                    mma_tf32_ss(tmem, ad + ks * 2, bd + ks * 2, IDESC_TF32_N256,
                                (c > 0) || (ks > 0));
                TCGEN05_COMMIT(sb + 8 + 8 * buf);
            }
        }
    }

    MBARRIER_WAIT_PARITY(sb + 8, 1);
    MBARRIER_WAIT_PARITY(sb + 16, 1);
    TCGEN05_FENCE_AFTER();

    if (wid < 4) {
        const int m = bm + wid * 32 + lane;
#pragma unroll
        for (int b = 0; b < 4; b++) {
            uint32_t r[64];
            TCGEN05_LD_32X32B_X32(r, tmem + b * 64);
            TCGEN05_LD_32X32B_X32(r + 32, tmem + b * 64 + 32);
            TCGEN05_WAIT_LD();
            if (m < N_NODES) {
                float* outp = g_h1 + (size_t)m * N_HID + b * 64;
#pragma unroll
                for (int j = 0; j < 64; j += 4) {
                    float4 o;
                    o.x = fmaxf(__uint_as_float(r[j + 0]) + bias[b * 64 + j + 0], 0.f);
                    o.y = fmaxf(__uint_as_float(r[j + 1]) + bias[b * 64 + j + 1], 0.f);
                    o.z = fmaxf(__uint_as_float(r[j + 2]) + bias[b * 64 + j + 2], 0.f);
                    o.w = fmaxf(__uint_as_float(r[j + 3]) + bias[b * 64 + j + 3], 0.f);
                    *(float4*)(outp + j) = o;
                }
            }
        }
        TCGEN05_FENCE_BEFORE();
    }
    __syncthreads();
    if (tid == 0) { MBARRIER_INVAL(sb + 8); MBARRIER_INVAL(sb + 16); }
    __syncthreads();
    if (wid == 4) { TCGEN05_RELINQUISH(); TCGEN05_DEALLOC(tmem, 256); }

#else
    float (*As)[132] = (float(*)[132])smem;
    float (*Bs)[68]  = (float(*)[68])(smem + 16 * 132 * sizeof(float));

    const int tid  = threadIdx.x;
    const int bm   = blockIdx.x * 128;
    const int mIdx = tid >> 4;
    const int nIdx = tid & 15;
    GRIDDEP_LAUNCH();

    for (int nb = 0; nb < 4; nb++) {
        const int bn = nb * 64;
        float acc[8][4];
#pragma unroll
        for (int i = 0; i < 8; i++)
#pragma unroll
            for (int j = 0; j < 4; j++) acc[i][j] = 0.f;

        for (int kt = 0; kt < N_FEAT; kt += 16) {
#pragma unroll
            for (int r = 0; r < 2; r++) {
                int i  = tid + r * 256;
                int m  = i >> 2;
                int k4 = (i & 3) * 4;
                int gm = bm + m;
                float4 v = make_float4(0.f, 0.f, 0.f, 0.f);
                if (gm < N_NODES)
                    v = *(const float4*)(A + (size_t)gm * N_FEAT + kt + k4);
                As[k4 + 0][m] = v.x;
                As[k4 + 1][m] = v.y;
                As[k4 + 2][m] = v.z;
                As[k4 + 3][m] = v.w;
            }
            {
                int n  = tid >> 2;
                int k4 = (tid & 3) * 4;
                float4 v = *(const float4*)(g_w1t + (size_t)(bn + n) * N_FEAT + kt + k4);
                Bs[k4 + 0][n] = v.x;
                Bs[k4 + 1][n] = v.y;
                Bs[k4 + 2][n] = v.z;
                Bs[k4 + 3][n] = v.w;
            }
            __syncthreads();

#pragma unroll
            for (int k = 0; k < 16; k++) {
                float ra[8], rb[4];
#pragma unroll
                for (int i = 0; i < 8; i++) ra[i] = As[k][mIdx * 8 + i];
#pragma unroll
                for (int j = 0; j < 4; j++) rb[j] = Bs[k][nIdx * 4 + j];
#pragma unroll
                for (int i = 0; i < 8; i++)
#pragma unroll
                    for (int j = 0; j < 4; j++) acc[i][j] += ra[i] * rb[j];
            }
            __syncthreads();
        }

#pragma unroll
        for (int i = 0; i < 8; i++) {
            int gm = bm + mIdx * 8 + i;
            if (gm < N_NODES) {
#pragma unroll
                for (int j = 0; j < 4; j++) {
                    int gn = bn + nIdx * 4 + j;
                    float v = acc[i][j] + bias[gn];
                    g_h1[(size_t)gm * N_HID + gn] = fmaxf(v, 0.f);
                }
            }
        }
    }
#endif
}

// ---------------- GEMM2 (PDL dependent: B fill before wait) ----------------
#define G2_CHUNK_K   32
#define G2_NCHUNKS   (N_HID / G2_CHUNK_K)
#define G2_A_BYTES   (128 * 128)
#define G2_BCH_BYTES (64 * 128)
#define G2_OFF_A0    1024
#define G2_OFF_A1    (G2_OFF_A0 + G2_A_BYTES)
#define G2_OFF_B     (G2_OFF_A1 + G2_A_BYTES)
#define G2_SMEM_TOTAL (G2_OFF_B + G2_NCHUNKS * G2_BCH_BYTES)

__global__ void __launch_bounds__(256) gemm2_tc_kernel(const float* __restrict__ b2) {
    extern __shared__ char smem[];
#if USE_TCGEN05
    const uint32_t sb = smem_to_u32(smem);
    const int tid  = threadIdx.x;
    const int wid  = tid >> 5;
    const int lane = tid & 31;
    const int bm   = blockIdx.x * 128;

    // -------- prologue: independent of gemm1 output --------
    if (wid == 4) TCGEN05_ALLOC(sb + 0, 64);
    if (tid == 0) { MBARRIER_INIT(sb + 8, 1); MBARRIER_INIT(sb + 16, 1); }
    __syncthreads();
    uint32_t tmem;
    asm volatile("ld.shared.b32 %0, [%1];" : "=r"(tmem) : "r"(sb + 0));

    for (int i = tid; i < (G2_NCHUNKS * G2_BCH_BYTES) / 16; i += 256)
        *(float4*)(smem + G2_OFF_B + i * 16) = make_float4(0.f, 0.f, 0.f, 0.f);
    __syncthreads();
    for (int i = tid; i < G2_NCHUNKS * N_CLASS * 8; i += 256) {
        int ch  = i / (N_CLASS * 8);
        int rem = i - ch * (N_CLASS * 8);
        int n   = rem >> 3;
        int f4  = rem & 7;
        float4 v = *(const float4*)(g_w2t + (size_t)n * N_HID + ch * G2_CHUNK_K + f4 * 4);
        v.x = to_tf32(v.x); v.y = to_tf32(v.y); v.z = to_tf32(v.z); v.w = to_tf32(v.w);
        uint32_t off = SMEM_SWIZZLE_128B((uint32_t)(n * 128 + f4 * 16));
        *(float4*)(smem + G2_OFF_B + ch * G2_BCH_BYTES + off) = v;
    }

    GRIDDEP_WAIT();     // gemm1's g_h1 writes now visible
    GRIDDEP_LAUNCH();   // let hop1's edge staging overlap our mainloop

    const uint32_t aoff[2] = {G2_OFF_A0, G2_OFF_A1};

    for (int c = 0; c < G2_NCHUNKS; c++) {
        const int buf = c & 1;
        if (c >= 2) MBARRIER_WAIT_PARITY(sb + 8 + 8 * buf, ((c - 2) >> 1) & 1);

#pragma unroll
        for (int r = 0; r < 4; r++) {
            int i   = tid + r * 256;
            int row = i >> 3;
            int f4  = i & 7;
            int gm  = bm + row;
            float4 v = make_float4(0.f, 0.f, 0.f, 0.f);
            if (gm < N_NODES)
                v = *(const float4*)(g_h1 + (size_t)gm * N_HID + c * G2_CHUNK_K + f4 * 4);
            v.x = to_tf32(v.x); v.y = to_tf32(v.y); v.z = to_tf32(v.z); v.w = to_tf32(v.w);
            uint32_t off = SMEM_SWIZZLE_128B((uint32_t)(row * 128 + f4 * 16));
            *(float4*)(smem + aoff[buf] + off) = v;
        }
        FENCE_PROXY_ASYNC();
        __syncthreads();

        if (wid == 4) {
            if (elect_one_pred()) {
                uint64_t ad = MAKE_SMEM_DESC(sb + aoff[buf]);
                uint64_t bd = MAKE_SMEM_DESC(sb + G2_OFF_B + c * G2_BCH_BYTES);
#pragma unroll
                for (int ks = 0; ks < 4; ks++)
                    mma_tf32_ss(tmem, ad + ks * 2, bd + ks * 2, IDESC_TF32_N64,
                                (c > 0) || (ks > 0));
                TCGEN05_COMMIT(sb + 8 + 8 * buf);
            }
        }
    }

    MBARRIER_WAIT_PARITY(sb + 8, 1);
    MBARRIER_WAIT_PARITY(sb + 16, 1);
    TCGEN05_FENCE_AFTER();

    if (wid < 4) {
        const int m = bm + wid * 32 + lane;
        uint32_t r[40];
        TCGEN05_LD_32X32B_X32(r, tmem);
        TCGEN05_LD_32X32B_X8(r + 32, tmem + 32);
        TCGEN05_WAIT_LD();
        if (m < N_NODES) {
            float* outp = g_xs + (size_t)m * N_CLASS;
#pragma unroll
            for (int j = 0; j < 40; j += 4) {
                float4 o;
                o.x = __uint_as_float(r[j + 0]) + b2[j + 0];
                o.y = __uint_as_float(r[j + 1]) + b2[j + 1];
                o.z = __uint_as_float(r[j + 2]) + b2[j + 2];
                o.w = __uint_as_float(r[j + 3]) + b2[j + 3];
                *(float4*)(outp + j) = o;
            }
        }
        TCGEN05_FENCE_BEFORE();
    }
    __syncthreads();
    if (tid == 0) { MBARRIER_INVAL(sb + 8); MBARRIER_INVAL(sb + 16); }
    __syncthreads();
    if (wid == 4) { TCGEN05_RELINQUISH(); TCGEN05_DEALLOC(tmem, 64); }

#else
    float (*As)[65] = (float(*)[65])smem;
    float* W2s = (float*)(smem + 64 * 65 * sizeof(float));

    const int tid = threadIdx.x;
    GRIDDEP_WAIT();
    GRIDDEP_LAUNCH();
    for (int half = 0; half < 2; half++) {
        const int bm  = blockIdx.x * 128 + half * 64;
        const int row = tid >> 2;
        const int q   = tid & 3;

        float acc[10];
#pragma unroll
        for (int j = 0; j < 10; j++) acc[j] = 0.f;

        for (int kb = 0; kb < N_HID; kb += 64) {
#pragma unroll
            for (int r = 0; r < 4; r++) {
                int i  = tid + r * 256;
                int rr = i >> 4;
                int c4 = (i & 15) * 4;
                int gm = bm + rr;
                float4 v = make_float4(0.f, 0.f, 0.f, 0.f);
                if (gm < N_NODES)
                    v = *(const float4*)(g_h1 + (size_t)gm * N_HID + kb + c4);
                As[rr][c4 + 0] = v.x;
                As[rr][c4 + 1] = v.y;
                As[rr][c4 + 2] = v.z;
                As[rr][c4 + 3] = v.w;
            }
#pragma unroll
            for (int r = 0; r < 10; r++) {
                int e = tid + r * 256;
                int k = e / N_CLASS;
                int n = e - k * N_CLASS;
                W2s[e] = g_w2t[(size_t)n * N_HID + kb + k];
            }
            __syncthreads();

#pragma unroll 4
            for (int k = 0; k < 64; k++) {
                float a = As[row][k];
#pragma unroll
                for (int j = 0; j < 10; j++)
                    acc[j] += a * W2s[k * N_CLASS + q * 10 + j];
            }
            __syncthreads();
        }

        int gm = bm + row;
        if (gm < N_NODES) {
#pragma unroll
            for (int j = 0; j < 10; j++)
                g_xs[(size_t)gm * N_CLASS + q * 10 + j] = acc[j] + b2[q * 10 + j];
        }
        __syncthreads();
    }
#endif
}

// ---------------- CSR build ----------------
__global__ void zero_count_kernel() {
    int i = blockIdx.x * blockDim.x + threadIdx.x;
    if (i < N_NODES) g_count[i] = 0;
}

// hist: 4 edges per thread (int4 load -> 4 independent atomics, MLP=4)
__global__ void hist_kernel(const int* __restrict__ edge_row) {
    int t = blockIdx.x * blockDim.x + threadIdx.x;
    int e = t * 4;
    if (e + 4 <= N_EDGES) {
        int4 r = *(const int4*)(edge_row + e);
        atomicAdd(&g_count[r.x], 1);
        atomicAdd(&g_count[r.y], 1);
        atomicAdd(&g_count[r.z], 1);
        atomicAdd(&g_count[r.w], 1);
    } else {
        for (int i = e; i < N_EDGES; i++)
            atomicAdd(&g_count[edge_row[i]], 1);
    }
}

__global__ void __launch_bounds__(1024) scan1_kernel() {
    __shared__ int warp_sums[32];
    const int tid = threadIdx.x, lane = tid & 31, wid = tid >> 5;
    const int i = blockIdx.x * 1024 + tid;

    int v = (i < N_NODES) ? g_count[i] : 0;
    int x = v;
#pragma unroll
    for (int off = 1; off < 32; off <<= 1) {
        int y = __shfl_up_sync(0xffffffffu, x, off);
        if (lane >= off) x += y;
    }
    if (lane == 31) warp_sums[wid] = x;
    __syncthreads();
    if (wid == 0) {
        int s = warp_sums[lane];
#pragma unroll
        for (int off = 1; off < 32; off <<= 1) {
            int y = __shfl_up_sync(0xffffffffu, s, off);
            if (lane >= off) s += y;
        }
        warp_sums[lane] = s;
    }
    __syncthreads();
    int incl = x + ((wid > 0) ? warp_sums[wid - 1] : 0);
    if (i < N_NODES) g_cursor[i] = incl - v;
    if (tid == 1023) g_bsum[blockIdx.x] = incl;
}

__global__ void scan2_kernel() {
    __shared__ int ws[4];
    const int tid = threadIdx.x, lane = tid & 31, wid = tid >> 5;
    int v = (tid < SCAN_BLOCKS) ? g_bsum[tid] : 0;
    int x = v;
#pragma unroll
    for (int off = 1; off < 32; off <<= 1) {
        int y = __shfl_up_sync(0xffffffffu, x, off);
        if (lane >= off) x += y;
    }
    if (lane == 31) ws[wid] = x;
    __syncthreads();
    if (wid == 0 && lane < 4) {
        int s = ws[lane];
#pragma unroll
        for (int off = 1; off < 4; off <<= 1) {
            int y = __shfl_up_sync(0xfu, s, off);
            if (lane >= off) s += y;
        }
        ws[lane] = s;
    }
    __syncthreads();
    int excl = x - v + ((wid > 0) ? ws[wid - 1] : 0);
    if (tid < SCAN_BLOCKS) g_boff[tid] = excl;
}

__global__ void scan3_kernel() {
    int i = blockIdx.x * blockDim.x + threadIdx.x;
    if (i < N_NODES) {
        int excl = g_cursor[i] + g_boff[i >> 10];
        g_cursor[i]     = excl;
        g_rowptr[i + 1] = excl + g_count[i];
        if (i == 0) g_rowptr[0] = 0;
    }
}

// scatter: 4 edges per thread (vector loads, 4 independent atomic+store)
__global__ void scatter_kernel(const int* __restrict__ edge_row,
                               const int* __restrict__ edge_col,
                               const float* __restrict__ edge_w) {
    int t = blockIdx.x * blockDim.x + threadIdx.x;
    int e = t * 4;
    if (e + 4 <= N_EDGES) {
        int4   r = *(const int4*)(edge_row + e);
        int4   c = *(const int4*)(edge_col + e);
        float4 w = *(const float4*)(edge_w + e);
        int p0 = atomicAdd(&g_cursor[r.x], 1);
        int p1 = atomicAdd(&g_cursor[r.y], 1);
        int p2 = atomicAdd(&g_cursor[r.z], 1);
        int p3 = atomicAdd(&g_cursor[r.w], 1);
        g_edge[p0] = make_int2(c.x, __float_as_int(w.x));
        g_edge[p1] = make_int2(c.y, __float_as_int(w.y));
        g_edge[p2] = make_int2(c.z, __float_as_int(w.z));
        g_edge[p3] = make_int2(c.w, __float_as_int(w.w));
    } else {
        for (int i = e; i < N_EDGES; i++) {
            int p = atomicAdd(&g_cursor[edge_row[i]], 1);
            g_edge[p] = make_int2(edge_col[i], __float_as_int(edge_w[i]));
        }
    }
}

// ---------------- SpMM hop with PDL edge prefetch ----------------
__global__ void __launch_bounds__(320) spmm_kernel(int hop) {
    __shared__ int2 es[32][SPMM_PAD];   // 12.5 KB

    const float* __restrict__ xin  = g_xs + (size_t)(hop - 1) * N_NODES * N_CLASS;
    float* __restrict__       xout = g_xs + (size_t)hop * N_NODES * N_CLASS;

    const int t    = blockIdx.x * blockDim.x + threadIdx.x;
    const int row  = t / 10;
    const int lane = t - row * 10;
    const int rloc = threadIdx.x / 10;

    const int s   = g_rowptr[row];
    const int e   = g_rowptr[row + 1];
    const int deg = e - s;
    const int stage = (deg < SPMM_CAP) ? deg : SPMM_CAP;

    for (int i = lane; i < stage; i += 10)
        es[rloc][i] = g_edge[s + i];
    __syncthreads();

    GRIDDEP_WAIT();
    GRIDDEP_LAUNCH();

    float4 acc = make_float4(0.f, 0.f, 0.f, 0.f);

    int i = 0;
    for (; i + 4 <= stage; i += 4) {
        int2 e0 = es[rloc][i + 0];
        int2 e1 = es[rloc][i + 1];
        int2 e2 = es[rloc][i + 2];
        int2 e3 = es[rloc][i + 3];
        float4 v0 = *(const float4*)(xin + (size_t)e0.x * N_CLASS + lane * 4);
        float4 v1 = *(const float4*)(xin + (size_t)e1.x * N_CLASS + lane * 4);
        float4 v2 = *(const float4*)(xin + (size_t)e2.x * N_CLASS + lane * 4);
        float4 v3 = *(const float4*)(xin + (size_t)e3.x * N_CLASS + lane * 4);
        float w0 = __int_as_float(e0.y);
        float w1 = __int_as_float(e1.y);
        float w2 = __int_as_float(e2.y);
        float w3 = __int_as_float(e3.y);
        acc.x += w0 * v0.x; acc.y += w0 * v0.y; acc.z += w0 * v0.z; acc.w += w0 * v0.w;
        acc.x += w1 * v1.x; acc.y += w1 * v1.y; acc.z += w1 * v1.z; acc.w += w1 * v1.w;
        acc.x += w2 * v2.x; acc.y += w2 * v2.y; acc.z += w2 * v2.z; acc.w += w2 * v2.w;
        acc.x += w3 * v3.x; acc.y += w3 * v3.y; acc.z += w3 * v3.z; acc.w += w3 * v3.w;
    }
    for (; i < stage; i++) {
        int2  ed = es[rloc][i];
        float w  = __int_as_float(ed.y);
        float4 v = *(const float4*)(xin + (size_t)ed.x * N_CLASS + lane * 4);
        acc.x += w * v.x; acc.y += w * v.y; acc.z += w * v.z; acc.w += w * v.w;
    }
    for (int j = s + stage; j < e; j++) {
        int2  ed = g_edge[j];
        float w  = __int_as_float(ed.y);
        float4 v = *(const float4*)(xin + (size_t)ed.x * N_CLASS + lane * 4);
        acc.x += w * v.x; acc.y += w * v.y; acc.z += w * v.z; acc.w += w * v.w;
    }
    *(float4*)(xout + (size_t)row * N_CLASS + lane * 4) = acc;
}

// ---------------- attention + log_softmax ----------------
__global__ void attn_kernel(const float* __restrict__ Wa,
                            const float* __restrict__ ba,
                            float* __restrict__ out) {
    int gwarp = (blockIdx.x * blockDim.x + threadIdx.x) >> 5;
    int lane  = threadIdx.x & 31;

    const float wa0 = Wa[lane];
    const float wa1 = (lane < 8) ? Wa[lane + 32] : 0.f;
    const float bav = ba[0];

    GRIDDEP_WAIT();
    if (gwarp >= N_NODES) return;
    const int n = gwarp;

    float v0[K_HOPS + 1], v1[K_HOPS + 1];
#pragma unroll
    for (int k = 0; k <= K_HOPS; k++) {
        const float* p = g_xs + ((size_t)k * N_NODES + n) * N_CLASS;
        v0[k] = p[lane];
        v1[k] = (lane < 8) ? p[lane + 32] : 0.f;
    }

    float acc0 = 0.f, acc1 = 0.f;
#pragma unroll
    for (int k = 0; k <= K_HOPS; k++) {
        float dot = v0[k] * wa0 + v1[k] * wa1;
#pragma unroll
        for (int off = 16; off > 0; off >>= 1)
            dot += __shfl_xor_sync(0xffffffffu, dot, off);
        float s = 1.f / (1.f + expf(-(dot + bav)));
        acc0 += s * v0[k];
        acc1 += s * v1[k];
    }

    float m = acc0;
    if (lane < 8) m = fmaxf(m, acc1);
#pragma unroll
    for (int off = 16; off > 0; off >>= 1)
        m = fmaxf(m, __shfl_xor_sync(0xffffffffu, m, off));

    float se = expf(acc0 - m) + ((lane < 8) ? expf(acc1 - m) : 0.f);
#pragma unroll
    for (int off = 16; off > 0; off >>= 1)
        se += __shfl_xor_sync(0xffffffffu, se, off);

    float lse = logf(se);
    out[(size_t)n * N_CLASS + lane] = acc0 - m - lse;
    if (lane < 8)
        out[(size_t)n * N_CLASS + lane + 32] = acc1 - m - lse;
}

// ---------------- launch ----------------
static cudaStream_t g_side    = nullptr;
static cudaEvent_t  g_ev_fork = nullptr;
static cudaEvent_t  g_ev_join = nullptr;
static int          g_inited  = 0;
static int          g_pdl     = -1;

static cudaError_t launch_gemm2(const float* b2, bool pdl) {
    cudaLaunchConfig_t cfg = {};
    cfg.gridDim  = dim3((N_NODES + 127) / 128, 1, 1);
    cfg.blockDim = dim3(256, 1, 1);
    cfg.dynamicSmemBytes = G2_SMEM_TOTAL;
    cfg.stream   = (cudaStream_t)0;
    cudaLaunchAttribute attrs[1];
    if (pdl) {
        attrs[0].id = cudaLaunchAttributeProgrammaticStreamSerialization;
        attrs[0].val.programmaticStreamSerializationAllowed = 1;
        cfg.attrs = attrs;
        cfg.numAttrs = 1;
    }
    return cudaLaunchKernelEx(&cfg, gemm2_tc_kernel, b2);
}

static cudaError_t launch_spmm(int hop, bool pdl) {
    cudaLaunchConfig_t cfg = {};
    cfg.gridDim  = dim3((N_NODES * 10 + 319) / 320, 1, 1);
    cfg.blockDim = dim3(320, 1, 1);
    cfg.stream   = (cudaStream_t)0;
    cudaLaunchAttribute attrs[1];
    if (pdl) {
        attrs[0].id = cudaLaunchAttributeProgrammaticStreamSerialization;
        attrs[0].val.programmaticStreamSerializationAllowed = 1;
        cfg.attrs = attrs;
        cfg.numAttrs = 1;
    }
    return cudaLaunchKernelEx(&cfg, spmm_kernel, hop);
}

static cudaError_t launch_attn(const float* Wa, const float* ba, float* out, bool pdl) {
    cudaLaunchConfig_t cfg = {};
    cfg.gridDim  = dim3((N_NODES * 32 + 255) / 256, 1, 1);
    cfg.blockDim = dim3(256, 1, 1);
    cfg.stream   = (cudaStream_t)0;
    cudaLaunchAttribute attrs[1];
    if (pdl) {
        attrs[0].id = cudaLaunchAttributeProgrammaticStreamSerialization;
        attrs[0].val.programmaticStreamSerializationAllowed = 1;
        cfg.attrs = attrs;
        cfg.numAttrs = 1;
    }
    return cudaLaunchKernelEx(&cfg, attn_kernel, Wa, ba, out);
}

extern "C" void kernel_launch(void* const* d_in, const int* in_sizes, int n_in,
                              void* d_out, int out_size) {
    const float* feature  = (const float*)d_in[0];
    const int*   edge_row = (const int*)  d_in[1];
    const int*   edge_col = (const int*)  d_in[2];
    const float* edge_w   = (const float*)d_in[3];
    const float* W1       = (const float*)d_in[4];
    const float* b1       = (const float*)d_in[5];
    const float* W2       = (const float*)d_in[6];
    const float* b2       = (const float*)d_in[7];
    const float* Wa       = (const float*)d_in[8];
    const float* ba       = (const float*)d_in[9];
    float*       out      = (float*)d_out;

    if (!g_inited) {
        cudaStreamCreateWithFlags(&g_side, cudaStreamNonBlocking);
        cudaEventCreateWithFlags(&g_ev_fork, cudaEventDisableTiming);
        cudaEventCreateWithFlags(&g_ev_join, cudaEventDisableTiming);
        cudaFuncSetAttribute(gemm1_tc_kernel,
                             cudaFuncAttributeMaxDynamicSharedMemorySize, G1_SMEM_TOTAL);
        cudaFuncSetAttribute(gemm2_tc_kernel,
                             cudaFuncAttributeMaxDynamicSharedMemorySize, G2_SMEM_TOTAL);
        g_inited = 1;
    }

    const bool fork = (g_side != nullptr) && (g_ev_fork != nullptr) && (g_ev_join != nullptr);
    cudaStream_t cs = fork ? g_side : (cudaStream_t)0;

    if (fork) {
        cudaEventRecord(g_ev_fork, 0);
        cudaStreamWaitEvent(g_side, g_ev_fork, 0);
    }

    // ---- CSR chain ----
    zero_count_kernel<<<(N_NODES + 255) / 256, 256, 0, cs>>>();
    hist_kernel<<<(N_EDGES / 4 + 255) / 256, 256, 0, cs>>>(edge_row);
    scan1_kernel<<<SCAN_BLOCKS, 1024, 0, cs>>>();
    scan2_kernel<<<1, 128, 0, cs>>>();
    scan3_kernel<<<(N_NODES + 255) / 256, 256, 0, cs>>>();
    scatter_kernel<<<(N_EDGES / 4 + 255) / 256, 256, 0, cs>>>(edge_row, edge_col, edge_w);

    if (fork) cudaEventRecord(g_ev_join, g_side);

    // ---- dense chain (gemm2 is a PDL dependent of gemm1) ----
    transpose_w1_kernel<<<dim3(N_FEAT / 32, N_HID / 32), dim3(32, 8)>>>(W1);
    transpose_w2_kernel<<<(N_HID * N_CLASS + 255) / 256, 256>>>(W2);
    gemm1_tc_kernel<<<(N_NODES + 127) / 128, 256, G1_SMEM_TOTAL>>>(feature, b1);
    {
        bool used = false;
        if (g_pdl != 0) {
            if (launch_gemm2(b2, true) == cudaSuccess) { used = true; if (g_pdl < 0) g_pdl = 1; }
            else if (g_pdl < 0) g_pdl = 0;
        }
        if (!used)
            if (launch_gemm2(b2, false) != cudaSuccess)
                gemm2_tc_kernel<<<(N_NODES + 127) / 128, 256, G2_SMEM_TOTAL>>>(b2);
    }

    // ---- join: SpMM needs both CSR and xs plane 0 ----
    if (fork) cudaStreamWaitEvent((cudaStream_t)0, g_ev_join, 0);

    // all hops + attn as PDL dependents (hop1's prologue overlaps gemm2)
    for (int k = 1; k <= K_HOPS; k++) {
        bool used = false;
        if (g_pdl == 1) {
            if (launch_spmm(k, true) == cudaSuccess) used = true;
        }
        if (!used)
            if (launch_spmm(k, false) != cudaSuccess)
                spmm_kernel<<<(N_NODES * 10 + 319) / 320, 320>>>(k);
    }
    {
        bool used = false;
        if (g_pdl == 1 && launch_attn(Wa, ba, out, true) == cudaSuccess) used = true;
        if (!used)
            if (launch_attn(Wa, ba, out, false) != cudaSuccess)
                attn_kernel<<<(N_NODES * 32 + 255) / 256, 256>>>(Wa, ba, out);
    }
}